// round 1
// baseline (speedup 1.0000x reference)
#include <cuda_runtime.h>
#include <math.h>

#define N_ 10000
#define E_ 160000
#define D_ 256

// ---------------- scratch (device globals: no allocations allowed) ----------
__device__ float g_Q[N_*D_];
__device__ float g_K[N_*D_];
__device__ float g_V[N_*D_];
__device__ float g_score[E_*8];
__device__ float g_aggr[N_*D_];
__device__ float g_x1[N_*D_];
__device__ float g_ffn[N_*4*D_];
__device__ int   g_cnt[N_];
__device__ int   g_rowptr[N_+1];
__device__ int   g_cur[N_];
__device__ int   g_perm[E_];

// ---------------- helpers ---------------------------------------------------
__device__ __forceinline__ float wsum(float v){
  #pragma unroll
  for (int o=16;o>0;o>>=1) v += __shfl_xor_sync(0xffffffffu, v, o);
  return v;
}

// A tile: 64 rows x 32 k, fp32, zero-padded past M
__device__ __forceinline__ void load_a(float* As, const float* __restrict__ A,
                                       int lda, int M, int r0, int kt, int t){
  #pragma unroll
  for (int s=0;s<2;s++){
    int slot=t+s*256;
    int row=slot>>3, k4=(slot&7)<<2;
    float4 v = make_float4(0.f,0.f,0.f,0.f);
    if (r0+row < M) v = *(const float4*)(A + (size_t)(r0+row)*lda + kt + k4);
    *(float4*)(As + row*32 + k4) = v;
  }
}

// B tile: 32 k x 256 cols
__device__ __forceinline__ void load_b(float* Bs, const float* __restrict__ W,
                                       int kt, int ldw, int colOff, int t){
  #pragma unroll
  for (int s=0;s<8;s++){
    int slot=t+s*256;
    int k=slot>>6, c4=(slot&63)<<2;
    *(float4*)(Bs + k*256 + c4) = *(const float4*)(W + (size_t)(kt+k)*ldw + colOff + c4);
  }
}

// 8x8 register microtile per thread. Thread (tx,ty): rows ty*8..+8,
// cols {tx*4..+4} U {128+tx*4..+4}  (split halves -> conflict-free LDS.128)
__device__ __forceinline__ void mm_inner(const float* As, const float* Bs,
                                         float (&acc)[8][8], int tx, int ty){
  #pragma unroll 8
  for (int k=0;k<32;k++){
    float a[8];
    #pragma unroll
    for (int r=0;r<8;r++) a[r] = As[(ty*8+r)*32+k];
    float4 b0 = *(const float4*)(Bs + k*256 + tx*4);
    float4 b1 = *(const float4*)(Bs + k*256 + 128 + tx*4);
    float b[8] = {b0.x,b0.y,b0.z,b0.w,b1.x,b1.y,b1.z,b1.w};
    #pragma unroll
    for (int r=0;r<8;r++){
      #pragma unroll
      for (int c=0;c<8;c++) acc[r][c] = fmaf(a[r], b[c], acc[r][c]);
    }
  }
}

template<bool RELU>
__device__ __forceinline__ void epi_bias(float (&acc)[8][8], const float* __restrict__ bias,
    float* __restrict__ C, int ldc, int colOff, int M, int r0, int tx, int ty){
  float bb[8];
  #pragma unroll
  for (int c=0;c<4;c++){ bb[c]=bias[colOff+tx*4+c]; bb[4+c]=bias[colOff+128+tx*4+c]; }
  #pragma unroll
  for (int r=0;r<8;r++){
    int row = r0+ty*8+r;
    if (row >= M) continue;
    float v[8];
    #pragma unroll
    for (int c=0;c<8;c++){
      float u = acc[r][c]+bb[c];
      v[c] = RELU ? fmaxf(u,0.f) : u;
    }
    float4 o0 = make_float4(v[0],v[1],v[2],v[3]);
    float4 o1 = make_float4(v[4],v[5],v[6],v[7]);
    *(float4*)(C + (size_t)row*ldc + colOff + tx*4) = o0;
    *(float4*)(C + (size_t)row*ldc + colOff + 128 + tx*4) = o1;
  }
}

// fused: y = acc + bias + res; C = LN(y)*g + b   (row of 256 lives in one warp)
__device__ __forceinline__ void epi_ln(float (&acc)[8][8], const float* __restrict__ bias,
    const float* __restrict__ res, const float* __restrict__ gam, const float* __restrict__ bet,
    float* __restrict__ C, int M, int r0, int tx, int ty){
  float bb[8], gg[8], be[8];
  #pragma unroll
  for (int c=0;c<4;c++){
    int lo=tx*4+c, hi=128+tx*4+c;
    bb[c]=bias[lo]; bb[4+c]=bias[hi];
    gg[c]=gam[lo];  gg[4+c]=gam[hi];
    be[c]=bet[lo];  be[4+c]=bet[hi];
  }
  #pragma unroll
  for (int r=0;r<8;r++){
    int row=r0+ty*8+r;
    bool ok = row<M;
    float y[8];
    if (ok){
      float4 v0 = *(const float4*)(res + (size_t)row*256 + tx*4);
      float4 v1 = *(const float4*)(res + (size_t)row*256 + 128 + tx*4);
      y[0]=v0.x; y[1]=v0.y; y[2]=v0.z; y[3]=v0.w;
      y[4]=v1.x; y[5]=v1.y; y[6]=v1.z; y[7]=v1.w;
    } else {
      #pragma unroll
      for (int c=0;c<8;c++) y[c]=0.f;
    }
    float s1=0.f, s2=0.f;
    #pragma unroll
    for (int c=0;c<8;c++){ y[c] += acc[r][c]+bb[c]; s1+=y[c]; s2=fmaf(y[c],y[c],s2); }
    s1=wsum(s1); s2=wsum(s2);
    float m=s1*(1.f/256.f);
    float rstd = rsqrtf(fmaxf(s2*(1.f/256.f)-m*m, 0.f)+1e-5f);
    if (ok){
      float4 o0, o1;
      o0.x=(y[0]-m)*rstd*gg[0]+be[0];
      o0.y=(y[1]-m)*rstd*gg[1]+be[1];
      o0.z=(y[2]-m)*rstd*gg[2]+be[2];
      o0.w=(y[3]-m)*rstd*gg[3]+be[3];
      o1.x=(y[4]-m)*rstd*gg[4]+be[4];
      o1.y=(y[5]-m)*rstd*gg[5]+be[5];
      o1.z=(y[6]-m)*rstd*gg[6]+be[6];
      o1.w=(y[7]-m)*rstd*gg[7]+be[7];
      *(float4*)(C + (size_t)row*256 + tx*4) = o0;
      *(float4*)(C + (size_t)row*256 + 128 + tx*4) = o1;
    }
  }
}

// ---------------- CSR build --------------------------------------------------
__global__ void k_zero(){
  int i = blockIdx.x*256+threadIdx.x;
  if (i<N_) g_cnt[i]=0;
}
__global__ void k_count(const int* __restrict__ ei){
  int e = blockIdx.x*256+threadIdx.x;
  if (e<E_) atomicAdd(&g_cnt[ei[E_+e]], 1);
}
__global__ void k_scan(){
  __shared__ int sh[1024];
  int t = threadIdx.x;
  int base = t*10;
  int loc[10]; int run=0;
  #pragma unroll
  for (int i=0;i<10;i++){ int idx=base+i; int v=(idx<N_)? g_cnt[idx]:0; loc[i]=run; run+=v; }
  sh[t]=run; __syncthreads();
  for (int off=1; off<1024; off<<=1){
    int v = (t>=off)? sh[t-off] : 0;
    __syncthreads();
    sh[t] += v;
    __syncthreads();
  }
  int pre = (t>0)? sh[t-1] : 0;
  #pragma unroll
  for (int i=0;i<10;i++){ int idx=base+i; if (idx<N_){ int p=pre+loc[i]; g_rowptr[idx]=p; g_cur[idx]=p; } }
  if (t==1023) g_rowptr[N_] = sh[1023];
}
__global__ void k_scatter(const int* __restrict__ ei){
  int e = blockIdx.x*256+threadIdx.x;
  if (e<E_){
    int d = ei[E_+e];
    int p = atomicAdd(&g_cur[d], 1);
    g_perm[p] = e;
  }
}

// ---------------- node QKV GEMMs (blockIdx.y picks set) ----------------------
__global__ void __launch_bounds__(256) k_gemm_qkv(
    const float* __restrict__ x,
    const float* __restrict__ Wq, const float* __restrict__ bq,
    const float* __restrict__ Wk, const float* __restrict__ bk,
    const float* __restrict__ Wv, const float* __restrict__ bv){
  __shared__ float As[64*32];
  __shared__ float Bs[32*256];
  int t=threadIdx.x, tx=t&31, ty=t>>5;
  int r0 = blockIdx.x*64;
  const float* W; const float* bias; float* C;
  if (blockIdx.y==0){ W=Wq; bias=bq; C=g_Q; }
  else if (blockIdx.y==1){ W=Wk; bias=bk; C=g_K; }
  else { W=Wv; bias=bv; C=g_V; }
  float acc[8][8];
  #pragma unroll
  for (int r=0;r<8;r++)
    #pragma unroll
    for (int c=0;c<8;c++) acc[r][c]=0.f;
  for (int kt=0; kt<256; kt+=32){
    load_a(As, x, 256, N_, r0, kt, t);
    load_b(Bs, W, kt, 256, 0, t);
    __syncthreads();
    mm_inner(As, Bs, acc, tx, ty);
    __syncthreads();
  }
  epi_bias<false>(acc, bias, C, 256, 0, N_, r0, tx, ty);
}

// ---------------- fused edge kernel: pe-MLP GEMM + LN + attention score ------
__global__ void __launch_bounds__(256) k_edge_score(
    const float* __restrict__ pos, const int* __restrict__ ei,
    const float* __restrict__ Wp1, const float* __restrict__ bp1,
    const float* __restrict__ Wp2, const float* __restrict__ bp2,
    const float* __restrict__ gp, const float* __restrict__ bpn){
  __shared__ float As[64*32];
  __shared__ float Bs[32*256];
  __shared__ float s_w1[3*256];
  __shared__ float s_b1[256];
  __shared__ float s_dp[64*4];
  __shared__ int   s_src[64], s_dst[64];
  int t=threadIdx.x, tx=t&31, ty=t>>5;
  int e0 = blockIdx.x*64;
  if (t < 64){
    int e = e0+t;
    int sn = ei[e], dn = ei[E_+e];
    s_src[t]=sn; s_dst[t]=dn;
    s_dp[t*4+0] = pos[dn*3+0]-pos[sn*3+0];
    s_dp[t*4+1] = pos[dn*3+1]-pos[sn*3+1];
    s_dp[t*4+2] = pos[dn*3+2]-pos[sn*3+2];
  }
  s_w1[t]=Wp1[t]; s_w1[256+t]=Wp1[256+t]; s_w1[512+t]=Wp1[512+t]; s_b1[t]=bp1[t];
  __syncthreads();

  float acc[8][8];
  #pragma unroll
  for (int r=0;r<8;r++)
    #pragma unroll
    for (int c=0;c<8;c++) acc[r][c]=0.f;

  for (int kt=0; kt<256; kt+=32){
    // A tile generated on the fly: h = relu(dp @ Wp1 + bp1)
    #pragma unroll
    for (int s=0;s<8;s++){
      int slot=t+s*256;
      int i=slot>>5, k=slot&31, kk=kt+k;
      float hv = fmaf(s_dp[i*4+2], s_w1[512+kk],
                 fmaf(s_dp[i*4+1], s_w1[256+kk],
                 fmaf(s_dp[i*4+0], s_w1[kk], s_b1[kk])));
      As[i*32+k] = fmaxf(hv, 0.f);
    }
    load_b(Bs, Wp2, kt, 256, 0, t);
    __syncthreads();
    mm_inner(As, Bs, acc, tx, ty);
    __syncthreads();
  }

  // epilogue: LN(pe) then per-head score = sum Q[dst]*(K[src]+pe) / sqrt(32)
  float gg[8], be[8], b2[8];
  #pragma unroll
  for (int c=0;c<4;c++){
    int lo=tx*4+c, hi=128+tx*4+c;
    gg[c]=gp[lo]; gg[4+c]=gp[hi];
    be[c]=bpn[lo]; be[4+c]=bpn[hi];
    b2[c]=bp2[lo]; b2[4+c]=bp2[hi];
  }
  const float SC = 0.17677669529663688f; // 1/sqrt(32)
  #pragma unroll
  for (int r=0;r<8;r++){
    int row = ty*8+r;
    int e = e0+row;
    float s1=0.f, s2=0.f;
    #pragma unroll
    for (int c=0;c<8;c++){ float yv=acc[r][c]+b2[c]; acc[r][c]=yv; s1+=yv; s2=fmaf(yv,yv,s2); }
    s1=wsum(s1); s2=wsum(s2);
    float m=s1*(1.f/256.f);
    float rstd = rsqrtf(fmaxf(s2*(1.f/256.f)-m*m, 0.f)+1e-5f);
    int sn=s_src[row], dn=s_dst[row];
    const float* Qp = g_Q + (size_t)dn*256;
    const float* Kp = g_K + (size_t)sn*256;
    float4 q0=*(const float4*)(Qp+tx*4), q1=*(const float4*)(Qp+128+tx*4);
    float4 k0=*(const float4*)(Kp+tx*4), k1=*(const float4*)(Kp+128+tx*4);
    float qa[8]={q0.x,q0.y,q0.z,q0.w,q1.x,q1.y,q1.z,q1.w};
    float ka[8]={k0.x,k0.y,k0.z,k0.w,k1.x,k1.y,k1.z,k1.w};
    float plo=0.f, phi=0.f;
    #pragma unroll
    for (int c=0;c<4;c++){
      float pe=(acc[r][c]-m)*rstd*gg[c]+be[c];
      plo = fmaf(qa[c], ka[c]+pe, plo);
    }
    #pragma unroll
    for (int c=4;c<8;c++){
      float pe=(acc[r][c]-m)*rstd*gg[c]+be[c];
      phi = fmaf(qa[c], ka[c]+pe, phi);
    }
    plo += __shfl_xor_sync(0xffffffffu, plo, 1);
    plo += __shfl_xor_sync(0xffffffffu, plo, 2);
    plo += __shfl_xor_sync(0xffffffffu, plo, 4);
    phi += __shfl_xor_sync(0xffffffffu, phi, 1);
    phi += __shfl_xor_sync(0xffffffffu, phi, 2);
    phi += __shfl_xor_sync(0xffffffffu, phi, 4);
    if ((tx&7)==0){
      int h = tx>>3;           // cols tx*4..: head = tx/8 ; hi half: head+4
      g_score[(size_t)e*8 + h]     = plo*SC;
      g_score[(size_t)e*8 + 4 + h] = phi*SC;
    }
  }
}

// ---------------- per-node segment softmax + weighted aggregation ------------
__global__ void __launch_bounds__(256) k_aggr(const int* __restrict__ ei){
  int n = blockIdx.x;
  int beg = g_rowptr[n], end = g_rowptr[n+1];
  int t = threadIdx.x, lane = t&31, w = t>>5;
  __shared__ float s_mx[8], s_rs[8];
  __shared__ float s_at[128*8];
  __shared__ int   s_sc[128];

  { // each warp handles one head: max then sum of exp
    int h = w;
    float mx = -3.0e38f;
    for (int i=beg+lane; i<end; i+=32)
      mx = fmaxf(mx, g_score[(size_t)g_perm[i]*8+h]);
    #pragma unroll
    for (int o=16;o>0;o>>=1) mx = fmaxf(mx, __shfl_xor_sync(0xffffffffu, mx, o));
    float s=0.f;
    for (int i=beg+lane; i<end; i+=32)
      s += __expf(g_score[(size_t)g_perm[i]*8+h]-mx);
    s = wsum(s);
    if (lane==0){ s_mx[h]=mx; s_rs[h]=1.f/(s+1e-16f); }
  }
  __syncthreads();

  float acc=0.f;
  int h = t>>5;
  for (int c0=beg; c0<end; c0+=128){
    int cn = min(128, end-c0);
    for (int j=t; j<cn*8; j+=256){
      int i=j>>3, hh=j&7;
      int e = g_perm[c0+i];
      s_at[i*8+hh] = __expf(g_score[(size_t)e*8+hh]-s_mx[hh])*s_rs[hh];
      if (hh==0) s_sc[i] = ei[e];   // src node
    }
    __syncthreads();
    for (int i=0;i<cn;i++)
      acc = fmaf(s_at[i*8+h], g_V[(size_t)s_sc[i]*256 + t], acc);
    __syncthreads();
  }
  g_aggr[(size_t)n*256+t]=acc;
}

// ---------------- Wo+LN / FFN2+LN -------------------------------------------
__global__ void __launch_bounds__(256) k_gemm_ln(int mode,
    const float* __restrict__ W, const float* __restrict__ bias,
    const float* __restrict__ resx,
    const float* __restrict__ gam, const float* __restrict__ bet,
    float* __restrict__ outp){
  __shared__ float As[64*32];
  __shared__ float Bs[32*256];
  int t=threadIdx.x, tx=t&31, ty=t>>5;
  int r0 = blockIdx.x*64;
  const float* A; const float* res; float* C; int K;
  if (mode==0){ A=g_aggr; res=resx;  C=g_x1; K=256;  }
  else        { A=g_ffn;  res=g_x1; C=outp; K=1024; }
  float acc[8][8];
  #pragma unroll
  for (int r=0;r<8;r++)
    #pragma unroll
    for (int c=0;c<8;c++) acc[r][c]=0.f;
  for (int kt=0; kt<K; kt+=32){
    load_a(As, A, K, N_, r0, kt, t);
    load_b(Bs, W, kt, 256, 0, t);
    __syncthreads();
    mm_inner(As, Bs, acc, tx, ty);
    __syncthreads();
  }
  epi_ln(acc, bias, res, gam, bet, C, N_, r0, tx, ty);
}

// ---------------- FFN1 (relu), 1024-wide via col tiles -----------------------
__global__ void __launch_bounds__(256) k_gemm_relu(
    const float* __restrict__ Wf1, const float* __restrict__ bf1){
  __shared__ float As[64*32];
  __shared__ float Bs[32*256];
  int t=threadIdx.x, tx=t&31, ty=t>>5;
  int r0 = blockIdx.x*64;
  int colOff = blockIdx.y*256;
  float acc[8][8];
  #pragma unroll
  for (int r=0;r<8;r++)
    #pragma unroll
    for (int c=0;c<8;c++) acc[r][c]=0.f;
  for (int kt=0; kt<256; kt+=32){
    load_a(As, g_x1, 256, N_, r0, kt, t);
    load_b(Bs, Wf1, kt, 1024, colOff, t);
    __syncthreads();
    mm_inner(As, Bs, acc, tx, ty);
    __syncthreads();
  }
  epi_bias<true>(acc, bf1, g_ffn, 1024, colOff, N_, r0, tx, ty);
}

// ---------------- launch ------------------------------------------------------
extern "C" void kernel_launch(void* const* d_in, const int* in_sizes, int n_in,
                              void* d_out, int out_size){
  const float* x    = (const float*)d_in[0];
  const float* pos  = (const float*)d_in[1];
  const int*   ei   = (const int*)  d_in[2];
  const float* Wq   = (const float*)d_in[3];
  const float* bq   = (const float*)d_in[4];
  const float* Wk   = (const float*)d_in[5];
  const float* bk   = (const float*)d_in[6];
  const float* Wv   = (const float*)d_in[7];
  const float* bv   = (const float*)d_in[8];
  const float* Wp1  = (const float*)d_in[9];
  const float* bp1  = (const float*)d_in[10];
  const float* Wp2  = (const float*)d_in[11];
  const float* bp2  = (const float*)d_in[12];
  const float* gp   = (const float*)d_in[13];
  const float* bp   = (const float*)d_in[14];
  const float* Wo   = (const float*)d_in[15];
  const float* bo   = (const float*)d_in[16];
  const float* g1   = (const float*)d_in[17];
  const float* b1n  = (const float*)d_in[18];
  const float* Wf1  = (const float*)d_in[19];
  const float* bf1  = (const float*)d_in[20];
  const float* Wf2  = (const float*)d_in[21];
  const float* bf2  = (const float*)d_in[22];
  const float* g2   = (const float*)d_in[23];
  const float* b2n  = (const float*)d_in[24];
  float* out = (float*)d_out;

  const int MBLK = (N_ + 63) / 64;     // 157

  // CSR build
  k_zero   <<<(N_+255)/256, 256>>>();
  k_count  <<<(E_+255)/256, 256>>>(ei);
  k_scan   <<<1, 1024>>>();
  k_scatter<<<(E_+255)/256, 256>>>(ei);

  // per-node Q/K/V
  k_gemm_qkv<<<dim3(MBLK,3), 256>>>(x, Wq,bq, Wk,bk, Wv,bv);

  // fused pe-MLP + LN + attention scores (per edge)
  k_edge_score<<<E_/64, 256>>>(pos, ei, Wp1,bp1, Wp2,bp2, gp,bp);

  // segment softmax + weighted aggregation
  k_aggr<<<N_, 256>>>(ei);

  // out = aggr@Wo+bo ; x1 = LN(out + x)
  k_gemm_ln<<<MBLK, 256>>>(0, Wo, bo, x, g1, b1n, nullptr);

  // ffn = relu(x1@Wf1+bf1)
  k_gemm_relu<<<dim3(MBLK,4), 256>>>(Wf1, bf1);

  // out = LN(ffn@Wf2+bf2 + x1)
  k_gemm_ln<<<MBLK, 256>>>(1, Wf2, bf2, nullptr, g2, b2n, out);

  (void)in_sizes; (void)n_in; (void)out_size;
}

// round 2
// speedup vs baseline: 1.0692x; 1.0692x over previous
#include <cuda_runtime.h>
#include <math.h>

#define N_ 10000
#define E_ 160000
#define D_ 256

typedef unsigned long long ull;

// ---------------- scratch (device globals: no allocations allowed) ----------
__device__ float g_Q[N_*D_];
__device__ float g_K[N_*D_];
__device__ float g_V[N_*D_];
__device__ float g_score[E_*8];
__device__ float g_aggr[N_*D_];
__device__ float g_x1[N_*D_];
__device__ float g_ffn[N_*4*D_];
__device__ int   g_cnt[N_];
__device__ int   g_rowptr[N_+1];
__device__ int   g_cur[N_];
__device__ int   g_perm[E_];

// ---------------- helpers ---------------------------------------------------
__device__ __forceinline__ float wsum(float v){
  #pragma unroll
  for (int o=16;o>0;o>>=1) v += __shfl_xor_sync(0xffffffffu, v, o);
  return v;
}

__device__ __forceinline__ ull pk2(float v){
  ull r;
  asm("mov.b64 %0, {%1, %1};" : "=l"(r) : "f"(v));
  return r;
}
__device__ __forceinline__ void fma2(ull &d, ull a, ull b){
  asm("fma.rn.f32x2 %0, %1, %2, %0;" : "+l"(d) : "l"(a), "l"(b));
}
__device__ __forceinline__ float2 upk(ull v){
  float2 r;
  asm("mov.b64 {%0, %1}, %2;" : "=f"(r.x), "=f"(r.y) : "l"(v));
  return r;
}

// As_t layout: k-major, [32][64] padded to 72 floats/row.
// Reads (per k, per thread): As_t + k*72 + ty*8 .. +7  -> 2 LDS.128, warp-broadcast.
#define APAD 72

// A tile (transposed store): 64 rows x 32 k, zero-padded past M. Conflict-free STS.
__device__ __forceinline__ void load_a_t(float* As, const float* __restrict__ A,
                                         int lda, int M, int r0, int kt, int t){
  #pragma unroll
  for (int s=0;s<2;s++){
    int slot = t + s*256;
    int row = slot & 63;
    int kb  = (slot >> 6) * 4;
    float4 v = make_float4(0.f,0.f,0.f,0.f);
    if (r0+row < M) v = *(const float4*)(A + (size_t)(r0+row)*lda + kt + kb);
    As[(kb+0)*APAD + row] = v.x;
    As[(kb+1)*APAD + row] = v.y;
    As[(kb+2)*APAD + row] = v.z;
    As[(kb+3)*APAD + row] = v.w;
  }
}

// B tile: 32 k x 256 cols
__device__ __forceinline__ void load_b(float* Bs, const float* __restrict__ W,
                                       int kt, int ldw, int colOff, int t){
  #pragma unroll
  for (int s=0;s<8;s++){
    int slot=t+s*256;
    int k=slot>>6, c4=(slot&63)<<2;
    *(float4*)(Bs + k*256 + c4) = *(const float4*)(W + (size_t)(kt+k)*ldw + colOff + c4);
  }
}

// FFMA2 microtile: 4 row-pairs x 8 cols per thread (= 8x8 scalar rows x cols).
// accp[rp][c] holds rows (ty*8+2rp, ty*8+2rp+1), col mapping as before:
// cols {tx*4..+4} U {128+tx*4..+4}
__device__ __forceinline__ void mm_inner2(const float* As, const float* Bs,
                                          ull (&accp)[4][8], int tx, int ty){
  #pragma unroll 8
  for (int k=0;k<32;k++){
    const ulonglong2* ap = (const ulonglong2*)(As + k*APAD + ty*8);
    ulonglong2 A0 = ap[0];   // (r0,r1), (r2,r3)
    ulonglong2 A1 = ap[1];   // (r4,r5), (r6,r7)
    float4 b0 = *(const float4*)(Bs + k*256 + tx*4);
    float4 b1 = *(const float4*)(Bs + k*256 + 128 + tx*4);
    ull bd[8];
    bd[0]=pk2(b0.x); bd[1]=pk2(b0.y); bd[2]=pk2(b0.z); bd[3]=pk2(b0.w);
    bd[4]=pk2(b1.x); bd[5]=pk2(b1.y); bd[6]=pk2(b1.z); bd[7]=pk2(b1.w);
    #pragma unroll
    for (int c=0;c<8;c++){
      fma2(accp[0][c], A0.x, bd[c]);
      fma2(accp[1][c], A0.y, bd[c]);
      fma2(accp[2][c], A1.x, bd[c]);
      fma2(accp[3][c], A1.y, bd[c]);
    }
  }
}

__device__ __forceinline__ void unpack_acc(const ull (&accp)[4][8], float (&acc)[8][8]){
  #pragma unroll
  for (int rp=0;rp<4;rp++){
    #pragma unroll
    for (int c=0;c<8;c++){
      float2 p = upk(accp[rp][c]);
      acc[2*rp][c]   = p.x;
      acc[2*rp+1][c] = p.y;
    }
  }
}

template<bool RELU>
__device__ __forceinline__ void epi_bias(float (&acc)[8][8], const float* __restrict__ bias,
    float* __restrict__ C, int ldc, int colOff, int M, int r0, int tx, int ty){
  float bb[8];
  #pragma unroll
  for (int c=0;c<4;c++){ bb[c]=bias[colOff+tx*4+c]; bb[4+c]=bias[colOff+128+tx*4+c]; }
  #pragma unroll
  for (int r=0;r<8;r++){
    int row = r0+ty*8+r;
    if (row >= M) continue;
    float v[8];
    #pragma unroll
    for (int c=0;c<8;c++){
      float u = acc[r][c]+bb[c];
      v[c] = RELU ? fmaxf(u,0.f) : u;
    }
    float4 o0 = make_float4(v[0],v[1],v[2],v[3]);
    float4 o1 = make_float4(v[4],v[5],v[6],v[7]);
    *(float4*)(C + (size_t)row*ldc + colOff + tx*4) = o0;
    *(float4*)(C + (size_t)row*ldc + colOff + 128 + tx*4) = o1;
  }
}

// fused: y = acc + bias + res; C = LN(y)*g + b   (row of 256 lives in one warp)
__device__ __forceinline__ void epi_ln(float (&acc)[8][8], const float* __restrict__ bias,
    const float* __restrict__ res, const float* __restrict__ gam, const float* __restrict__ bet,
    float* __restrict__ C, int M, int r0, int tx, int ty){
  float bb[8], gg[8], be[8];
  #pragma unroll
  for (int c=0;c<4;c++){
    int lo=tx*4+c, hi=128+tx*4+c;
    bb[c]=bias[lo]; bb[4+c]=bias[hi];
    gg[c]=gam[lo];  gg[4+c]=gam[hi];
    be[c]=bet[lo];  be[4+c]=bet[hi];
  }
  #pragma unroll
  for (int r=0;r<8;r++){
    int row=r0+ty*8+r;
    bool ok = row<M;
    float y[8];
    if (ok){
      float4 v0 = *(const float4*)(res + (size_t)row*256 + tx*4);
      float4 v1 = *(const float4*)(res + (size_t)row*256 + 128 + tx*4);
      y[0]=v0.x; y[1]=v0.y; y[2]=v0.z; y[3]=v0.w;
      y[4]=v1.x; y[5]=v1.y; y[6]=v1.z; y[7]=v1.w;
    } else {
      #pragma unroll
      for (int c=0;c<8;c++) y[c]=0.f;
    }
    float s1=0.f, s2=0.f;
    #pragma unroll
    for (int c=0;c<8;c++){ y[c] += acc[r][c]+bb[c]; s1+=y[c]; s2=fmaf(y[c],y[c],s2); }
    s1=wsum(s1); s2=wsum(s2);
    float m=s1*(1.f/256.f);
    float rstd = rsqrtf(fmaxf(s2*(1.f/256.f)-m*m, 0.f)+1e-5f);
    if (ok){
      float4 o0, o1;
      o0.x=(y[0]-m)*rstd*gg[0]+be[0];
      o0.y=(y[1]-m)*rstd*gg[1]+be[1];
      o0.z=(y[2]-m)*rstd*gg[2]+be[2];
      o0.w=(y[3]-m)*rstd*gg[3]+be[3];
      o1.x=(y[4]-m)*rstd*gg[4]+be[4];
      o1.y=(y[5]-m)*rstd*gg[5]+be[5];
      o1.z=(y[6]-m)*rstd*gg[6]+be[6];
      o1.w=(y[7]-m)*rstd*gg[7]+be[7];
      *(float4*)(C + (size_t)row*256 + tx*4) = o0;
      *(float4*)(C + (size_t)row*256 + 128 + tx*4) = o1;
    }
  }
}

// ---------------- CSR build --------------------------------------------------
__global__ void k_zero(){
  int i = blockIdx.x*256+threadIdx.x;
  if (i<N_) g_cnt[i]=0;
}
__global__ void k_count(const int* __restrict__ ei){
  int e = blockIdx.x*256+threadIdx.x;
  if (e<E_) atomicAdd(&g_cnt[ei[E_+e]], 1);
}
__global__ void k_scan(){
  __shared__ int sh[1024];
  int t = threadIdx.x;
  int base = t*10;
  int loc[10]; int run=0;
  #pragma unroll
  for (int i=0;i<10;i++){ int idx=base+i; int v=(idx<N_)? g_cnt[idx]:0; loc[i]=run; run+=v; }
  sh[t]=run; __syncthreads();
  for (int off=1; off<1024; off<<=1){
    int v = (t>=off)? sh[t-off] : 0;
    __syncthreads();
    sh[t] += v;
    __syncthreads();
  }
  int pre = (t>0)? sh[t-1] : 0;
  #pragma unroll
  for (int i=0;i<10;i++){ int idx=base+i; if (idx<N_){ int p=pre+loc[i]; g_rowptr[idx]=p; g_cur[idx]=p; } }
  if (t==1023) g_rowptr[N_] = sh[1023];
}
__global__ void k_scatter(const int* __restrict__ ei){
  int e = blockIdx.x*256+threadIdx.x;
  if (e<E_){
    int d = ei[E_+e];
    int p = atomicAdd(&g_cur[d], 1);
    g_perm[p] = e;
  }
}

// ---------------- node QKV GEMMs (blockIdx.y picks set) ----------------------
__global__ void __launch_bounds__(256) k_gemm_qkv(
    const float* __restrict__ x,
    const float* __restrict__ Wq, const float* __restrict__ bq,
    const float* __restrict__ Wk, const float* __restrict__ bk,
    const float* __restrict__ Wv, const float* __restrict__ bv){
  __shared__ float As[32*APAD];
  __shared__ float Bs[32*256];
  int t=threadIdx.x, tx=t&31, ty=t>>5;
  int r0 = blockIdx.x*64;
  const float* W; const float* bias; float* C;
  if (blockIdx.y==0){ W=Wq; bias=bq; C=g_Q; }
  else if (blockIdx.y==1){ W=Wk; bias=bk; C=g_K; }
  else { W=Wv; bias=bv; C=g_V; }
  ull accp[4][8];
  #pragma unroll
  for (int r=0;r<4;r++)
    #pragma unroll
    for (int c=0;c<8;c++) accp[r][c]=0ull;
  for (int kt=0; kt<256; kt+=32){
    load_a_t(As, x, 256, N_, r0, kt, t);
    load_b(Bs, W, kt, 256, 0, t);
    __syncthreads();
    mm_inner2(As, Bs, accp, tx, ty);
    __syncthreads();
  }
  float acc[8][8];
  unpack_acc(accp, acc);
  epi_bias<false>(acc, bias, C, 256, 0, N_, r0, tx, ty);
}

// ---------------- fused edge kernel: pe-MLP GEMM + LN + attention score ------
__global__ void __launch_bounds__(256) k_edge_score(
    const float* __restrict__ pos, const int* __restrict__ ei,
    const float* __restrict__ Wp1, const float* __restrict__ bp1,
    const float* __restrict__ Wp2, const float* __restrict__ bp2,
    const float* __restrict__ gp, const float* __restrict__ bpn){
  __shared__ float As[32*APAD];
  __shared__ float Bs[32*256];
  __shared__ float s_w1[3*256];
  __shared__ float s_b1[256];
  __shared__ float s_dp[64*4];
  __shared__ int   s_src[64], s_dst[64];
  int t=threadIdx.x, tx=t&31, ty=t>>5;
  int e0 = blockIdx.x*64;
  if (t < 64){
    int e = e0+t;
    int sn = ei[e], dn = ei[E_+e];
    s_src[t]=sn; s_dst[t]=dn;
    s_dp[t*4+0] = pos[dn*3+0]-pos[sn*3+0];
    s_dp[t*4+1] = pos[dn*3+1]-pos[sn*3+1];
    s_dp[t*4+2] = pos[dn*3+2]-pos[sn*3+2];
  }
  s_w1[t]=Wp1[t]; s_w1[256+t]=Wp1[256+t]; s_w1[512+t]=Wp1[512+t]; s_b1[t]=bp1[t];
  __syncthreads();

  ull accp[4][8];
  #pragma unroll
  for (int r=0;r<4;r++)
    #pragma unroll
    for (int c=0;c<8;c++) accp[r][c]=0ull;

  for (int kt=0; kt<256; kt+=32){
    // A tile generated on the fly (k-major): h = relu(dp @ Wp1 + bp1)
    // slot -> k = slot>>6 (0..31), i = slot&63; conflict-free STS (bank = k*8+lane)
    #pragma unroll
    for (int s=0;s<8;s++){
      int slot=t+s*256;
      int k=slot>>6, i=slot&63, kk=kt+k;
      float hv = fmaf(s_dp[i*4+2], s_w1[512+kk],
                 fmaf(s_dp[i*4+1], s_w1[256+kk],
                 fmaf(s_dp[i*4+0], s_w1[kk], s_b1[kk])));
      As[k*APAD+i] = fmaxf(hv, 0.f);
    }
    load_b(Bs, Wp2, kt, 256, 0, t);
    __syncthreads();
    mm_inner2(As, Bs, accp, tx, ty);
    __syncthreads();
  }

  float acc[8][8];
  unpack_acc(accp, acc);

  // epilogue: LN(pe) then per-head score = sum Q[dst]*(K[src]+pe) / sqrt(32)
  float gg[8], be[8], b2[8];
  #pragma unroll
  for (int c=0;c<4;c++){
    int lo=tx*4+c, hi=128+tx*4+c;
    gg[c]=gp[lo]; gg[4+c]=gp[hi];
    be[c]=bpn[lo]; be[4+c]=bpn[hi];
    b2[c]=bp2[lo]; b2[4+c]=bp2[hi];
  }
  const float SC = 0.17677669529663688f; // 1/sqrt(32)
  #pragma unroll
  for (int r=0;r<8;r++){
    int row = ty*8+r;
    int e = e0+row;
    float s1=0.f, s2=0.f;
    #pragma unroll
    for (int c=0;c<8;c++){ float yv=acc[r][c]+b2[c]; acc[r][c]=yv; s1+=yv; s2=fmaf(yv,yv,s2); }
    s1=wsum(s1); s2=wsum(s2);
    float m=s1*(1.f/256.f);
    float rstd = rsqrtf(fmaxf(s2*(1.f/256.f)-m*m, 0.f)+1e-5f);
    int sn=s_src[row], dn=s_dst[row];
    const float* Qp = g_Q + (size_t)dn*256;
    const float* Kp = g_K + (size_t)sn*256;
    float4 q0=*(const float4*)(Qp+tx*4), q1=*(const float4*)(Qp+128+tx*4);
    float4 k0=*(const float4*)(Kp+tx*4), k1=*(const float4*)(Kp+128+tx*4);
    float qa[8]={q0.x,q0.y,q0.z,q0.w,q1.x,q1.y,q1.z,q1.w};
    float ka[8]={k0.x,k0.y,k0.z,k0.w,k1.x,k1.y,k1.z,k1.w};
    float plo=0.f, phi=0.f;
    #pragma unroll
    for (int c=0;c<4;c++){
      float pe=(acc[r][c]-m)*rstd*gg[c]+be[c];
      plo = fmaf(qa[c], ka[c]+pe, plo);
    }
    #pragma unroll
    for (int c=4;c<8;c++){
      float pe=(acc[r][c]-m)*rstd*gg[c]+be[c];
      phi = fmaf(qa[c], ka[c]+pe, phi);
    }
    plo += __shfl_xor_sync(0xffffffffu, plo, 1);
    plo += __shfl_xor_sync(0xffffffffu, plo, 2);
    plo += __shfl_xor_sync(0xffffffffu, plo, 4);
    phi += __shfl_xor_sync(0xffffffffu, phi, 1);
    phi += __shfl_xor_sync(0xffffffffu, phi, 2);
    phi += __shfl_xor_sync(0xffffffffu, phi, 4);
    if ((tx&7)==0){
      int h = tx>>3;           // cols tx*4..: head = tx/8 ; hi half: head+4
      g_score[(size_t)e*8 + h]     = plo*SC;
      g_score[(size_t)e*8 + 4 + h] = phi*SC;
    }
  }
}

// ---------------- per-node segment softmax + weighted aggregation ------------
__global__ void __launch_bounds__(256) k_aggr(const int* __restrict__ ei){
  int n = blockIdx.x;
  int beg = g_rowptr[n], end = g_rowptr[n+1];
  int t = threadIdx.x, lane = t&31, w = t>>5;
  __shared__ float s_mx[8], s_rs[8];
  __shared__ float s_at[128*8];
  __shared__ int   s_sc[128];

  { // each warp handles one head: max then sum of exp
    int h = w;
    float mx = -3.0e38f;
    for (int i=beg+lane; i<end; i+=32)
      mx = fmaxf(mx, g_score[(size_t)g_perm[i]*8+h]);
    #pragma unroll
    for (int o=16;o>0;o>>=1) mx = fmaxf(mx, __shfl_xor_sync(0xffffffffu, mx, o));
    float s=0.f;
    for (int i=beg+lane; i<end; i+=32)
      s += __expf(g_score[(size_t)g_perm[i]*8+h]-mx);
    s = wsum(s);
    if (lane==0){ s_mx[h]=mx; s_rs[h]=1.f/(s+1e-16f); }
  }
  __syncthreads();

  float acc=0.f;
  int h = t>>5;
  for (int c0=beg; c0<end; c0+=128){
    int cn = min(128, end-c0);
    for (int j=t; j<cn*8; j+=256){
      int i=j>>3, hh=j&7;
      int e = g_perm[c0+i];
      s_at[i*8+hh] = __expf(g_score[(size_t)e*8+hh]-s_mx[hh])*s_rs[hh];
      if (hh==0) s_sc[i] = ei[e];   // src node
    }
    __syncthreads();
    for (int i=0;i<cn;i++)
      acc = fmaf(s_at[i*8+h], g_V[(size_t)s_sc[i]*256 + t], acc);
    __syncthreads();
  }
  g_aggr[(size_t)n*256+t]=acc;
}

// ---------------- Wo+LN / FFN2+LN -------------------------------------------
__global__ void __launch_bounds__(256) k_gemm_ln(int mode,
    const float* __restrict__ W, const float* __restrict__ bias,
    const float* __restrict__ resx,
    const float* __restrict__ gam, const float* __restrict__ bet,
    float* __restrict__ outp){
  __shared__ float As[32*APAD];
  __shared__ float Bs[32*256];
  int t=threadIdx.x, tx=t&31, ty=t>>5;
  int r0 = blockIdx.x*64;
  const float* A; const float* res; float* C; int K;
  if (mode==0){ A=g_aggr; res=resx;  C=g_x1; K=256;  }
  else        { A=g_ffn;  res=g_x1; C=outp; K=1024; }
  ull accp[4][8];
  #pragma unroll
  for (int r=0;r<4;r++)
    #pragma unroll
    for (int c=0;c<8;c++) accp[r][c]=0ull;
  for (int kt=0; kt<K; kt+=32){
    load_a_t(As, A, K, N_, r0, kt, t);
    load_b(Bs, W, kt, 256, 0, t);
    __syncthreads();
    mm_inner2(As, Bs, accp, tx, ty);
    __syncthreads();
  }
  float acc[8][8];
  unpack_acc(accp, acc);
  epi_ln(acc, bias, res, gam, bet, C, N_, r0, tx, ty);
}

// ---------------- FFN1 (relu), 1024-wide via col tiles -----------------------
__global__ void __launch_bounds__(256) k_gemm_relu(
    const float* __restrict__ Wf1, const float* __restrict__ bf1){
  __shared__ float As[32*APAD];
  __shared__ float Bs[32*256];
  int t=threadIdx.x, tx=t&31, ty=t>>5;
  int r0 = blockIdx.x*64;
  int colOff = blockIdx.y*256;
  ull accp[4][8];
  #pragma unroll
  for (int r=0;r<4;r++)
    #pragma unroll
    for (int c=0;c<8;c++) accp[r][c]=0ull;
  for (int kt=0; kt<256; kt+=32){
    load_a_t(As, g_x1, 256, N_, r0, kt, t);
    load_b(Bs, Wf1, kt, 1024, colOff, t);
    __syncthreads();
    mm_inner2(As, Bs, accp, tx, ty);
    __syncthreads();
  }
  float acc[8][8];
  unpack_acc(accp, acc);
  epi_bias<true>(acc, bf1, g_ffn, 1024, colOff, N_, r0, tx, ty);
}

// ---------------- launch ------------------------------------------------------
extern "C" void kernel_launch(void* const* d_in, const int* in_sizes, int n_in,
                              void* d_out, int out_size){
  const float* x    = (const float*)d_in[0];
  const float* pos  = (const float*)d_in[1];
  const int*   ei   = (const int*)  d_in[2];
  const float* Wq   = (const float*)d_in[3];
  const float* bq   = (const float*)d_in[4];
  const float* Wk   = (const float*)d_in[5];
  const float* bk   = (const float*)d_in[6];
  const float* Wv   = (const float*)d_in[7];
  const float* bv   = (const float*)d_in[8];
  const float* Wp1  = (const float*)d_in[9];
  const float* bp1  = (const float*)d_in[10];
  const float* Wp2  = (const float*)d_in[11];
  const float* bp2  = (const float*)d_in[12];
  const float* gp   = (const float*)d_in[13];
  const float* bp   = (const float*)d_in[14];
  const float* Wo   = (const float*)d_in[15];
  const float* bo   = (const float*)d_in[16];
  const float* g1   = (const float*)d_in[17];
  const float* b1n  = (const float*)d_in[18];
  const float* Wf1  = (const float*)d_in[19];
  const float* bf1  = (const float*)d_in[20];
  const float* Wf2  = (const float*)d_in[21];
  const float* bf2  = (const float*)d_in[22];
  const float* g2   = (const float*)d_in[23];
  const float* b2n  = (const float*)d_in[24];
  float* out = (float*)d_out;

  const int MBLK = (N_ + 63) / 64;     // 157

  // CSR build
  k_zero   <<<(N_+255)/256, 256>>>();
  k_count  <<<(E_+255)/256, 256>>>(ei);
  k_scan   <<<1, 1024>>>();
  k_scatter<<<(E_+255)/256, 256>>>(ei);

  // per-node Q/K/V
  k_gemm_qkv<<<dim3(MBLK,3), 256>>>(x, Wq,bq, Wk,bk, Wv,bv);

  // fused pe-MLP + LN + attention scores (per edge)
  k_edge_score<<<E_/64, 256>>>(pos, ei, Wp1,bp1, Wp2,bp2, gp,bp);

  // segment softmax + weighted aggregation
  k_aggr<<<N_, 256>>>(ei);

  // out = aggr@Wo+bo ; x1 = LN(out + x)
  k_gemm_ln<<<MBLK, 256>>>(0, Wo, bo, x, g1, b1n, nullptr);

  // ffn = relu(x1@Wf1+bf1)
  k_gemm_relu<<<dim3(MBLK,4), 256>>>(Wf1, bf1);

  // out = LN(ffn@Wf2+bf2 + x1)
  k_gemm_ln<<<MBLK, 256>>>(1, Wf2, bf2, nullptr, g2, b2n, out);

  (void)in_sizes; (void)n_in; (void)out_size;
}

// round 4
// speedup vs baseline: 1.7662x; 1.6519x over previous
#include <cuda_runtime.h>
#include <cuda_bf16.h>
#include <math.h>

#define N_ 10000
#define E_ 160000

typedef unsigned int uint32;

// ---------------- device scratch ---------------------------------------------
__device__ __align__(16) float g_Q[N_*256];
__device__ __align__(16) float g_K[N_*256];
__device__ __align__(16) float g_V[N_*256];
__device__ __align__(16) float g_score[E_*8];
__device__ __align__(16) float g_aggr[N_*256];
__device__ __align__(16) float g_x1[N_*256];
__device__ __align__(16) float g_ffn[N_*1024];
__device__ int   g_cnt[N_];
__device__ int   g_rowptr[N_+1];
__device__ int   g_cur[N_];
__device__ int   g_perm[E_];

// transposed+split weights, [N][K] bf16 (K contiguous)
#define OFF_Q  0u
#define OFF_K  65536u
#define OFF_V  131072u
#define OFF_P2 196608u
#define OFF_O  262144u
#define OFF_F1 327680u      /* [1024][256] */
#define OFF_F2 589824u      /* [256][1024] */
#define WT_TOTAL 851968u
__device__ __align__(16) __nv_bfloat16 g_wth[WT_TOTAL];
__device__ __align__(16) __nv_bfloat16 g_wtl[WT_TOTAL];

// ---------------- smem layout --------------------------------------------------
// A tiles: 64 rows x 64 k bf16, 128B rows -> 8192 B each (hi, lo)
// B tiles: 256 rows x 64 k bf16 -> 32768 B each (hi, lo)
// C staging: 64 x 264 fp32 = 67584 B (reuses A/B region)
// params at 81920
#define SM_A_HI 0
#define SM_A_LO 8192
#define SM_B_HI 16384
#define SM_B_LO 49152
#define SM_PAR  81920
#define CSTR    264
#define SMEM_DYN 92160

__device__ __forceinline__ uint32 smem_to_u32(const void* p){
  uint32 a;
  asm("{ .reg .u64 t; cvta.to.shared.u64 t, %1; cvt.u32.u64 %0, t; }" : "=r"(a) : "l"(p));
  return a;
}
__device__ __forceinline__ uint32 swz(int row, int c16){
  return (uint32)(row*128 + (((c16) ^ (row & 7)) << 4));
}
__device__ __forceinline__ void ldsm4(uint32* r, uint32 addr){
  asm volatile("ldmatrix.sync.aligned.m8n8.x4.shared.b16 {%0,%1,%2,%3}, [%4];"
    : "=r"(r[0]),"=r"(r[1]),"=r"(r[2]),"=r"(r[3]) : "r"(addr));
}
__device__ __forceinline__ void mma_bf16(float* c, const uint32* a, uint32 b0, uint32 b1){
  asm volatile("mma.sync.aligned.m16n8k16.row.col.f32.bf16.bf16.f32 "
    "{%0,%1,%2,%3}, {%4,%5,%6,%7}, {%8,%9}, {%0,%1,%2,%3};"
    : "+f"(c[0]),"+f"(c[1]),"+f"(c[2]),"+f"(c[3])
    : "r"(a[0]),"r"(a[1]),"r"(a[2]),"r"(a[3]), "r"(b0),"r"(b1));
}

union BU { __nv_bfloat16 b[8]; uint4 u; };

// ---------------- staging -------------------------------------------------------
// B tile: 256 rows (N) x 64 (K) bf16 hi/lo from transposed weights
__device__ __forceinline__ void stage_b(char* smem, uint32 baseOff, int Kst,
                                        int kk, int t){
  #pragma unroll
  for (int s=0; s<8; s++){
    int slot = t + s*256;
    int n = slot >> 3, g = slot & 7;
    size_t src = (size_t)baseOff + (size_t)n*Kst + kk + g*8;
    uint32 dst = swz(n, g);
    *(uint4*)(smem + SM_B_HI + dst) = *(const uint4*)(const void*)(g_wth + src);
    *(uint4*)(smem + SM_B_LO + dst) = *(const uint4*)(const void*)(g_wtl + src);
  }
}

// A tile from fp32 gmem: 64 rows x 64 k, split to bf16 hi/lo, zero-pad past M
__device__ __forceinline__ void stage_a(char* smem, const float* __restrict__ A,
                                        int lda, int M, int r0, int kk, int t){
  int r = t >> 2;           // 0..63
  int q = t & 3;            // 16-col quarter
  int row = r0 + r;
  bool ok = row < M;
  const float* src = A + (size_t)row*lda + kk + q*16;
  #pragma unroll
  for (int half=0; half<2; half++){
    float v[8];
    if (ok){
      float4 a = *(const float4*)(src + half*8);
      float4 b = *(const float4*)(src + half*8 + 4);
      v[0]=a.x; v[1]=a.y; v[2]=a.z; v[3]=a.w; v[4]=b.x; v[5]=b.y; v[6]=b.z; v[7]=b.w;
    } else {
      #pragma unroll
      for (int j=0;j<8;j++) v[j]=0.f;
    }
    BU H, L;
    #pragma unroll
    for (int j=0;j<8;j++){
      H.b[j] = __float2bfloat16(v[j]);
      L.b[j] = __float2bfloat16(v[j] - __bfloat162float(H.b[j]));
    }
    uint32 dst = swz(r, q*2 + half);
    *(uint4*)(smem + SM_A_HI + dst) = H.u;
    *(uint4*)(smem + SM_A_LO + dst) = L.u;
  }
}

// ---------------- warp MMA mainloop --------------------------------------------
__device__ __forceinline__ void compute_chunk(uint32 sb, int lane, int wm, int wn,
                                              float (&acc)[2][8][4]){
  uint32 rbA[2]; int rxA[2];
  #pragma unroll
  for (int mi=0;mi<2;mi++){
    int row = wm*32 + mi*16 + (lane&15);
    rbA[mi] = sb + SM_A_HI + row*128;
    rxA[mi] = row & 7;
  }
  int hi4 = lane>>4;
  uint32 rbB[4]; int rxB[4];
  #pragma unroll
  for (int g=0; g<4; g++){
    int n = wn*64 + g*16 + ((lane>>4)<<3) + (lane&7);
    rbB[g] = sb + SM_B_HI + n*128;
    rxB[g] = n & 7;
  }
  int cB = (lane>>3)&1;
  #pragma unroll
  for (int ks=0; ks<4; ks++){
    int c16 = ks*2;
    uint32 Ah[2][4], Al[2][4];
    #pragma unroll
    for (int mi=0;mi<2;mi++){
      uint32 off = ((uint32)((c16 + hi4) ^ rxA[mi])) << 4;
      ldsm4(Ah[mi], rbA[mi] + off);
      ldsm4(Al[mi], rbA[mi] + 8192 + off);
    }
    uint32 Bh[4][4], Bl[4][4];
    #pragma unroll
    for (int g=0; g<4; g++){
      uint32 off = ((uint32)((c16 + cB) ^ rxB[g])) << 4;
      ldsm4(Bh[g], rbB[g] + off);
      ldsm4(Bl[g], rbB[g] + 32768 + off);
    }
    #pragma unroll
    for (int mi=0;mi<2;mi++){
      #pragma unroll
      for (int ni=0;ni<8;ni++){
        uint32 b0h = Bh[ni>>1][(ni&1)*2], b1h = Bh[ni>>1][(ni&1)*2+1];
        uint32 b0l = Bl[ni>>1][(ni&1)*2], b1l = Bl[ni>>1][(ni&1)*2+1];
        mma_bf16(acc[mi][ni], Ah[mi], b0h, b1h);
        mma_bf16(acc[mi][ni], Al[mi], b0h, b1h);
        mma_bf16(acc[mi][ni], Ah[mi], b0l, b1l);
      }
    }
  }
}

__device__ __forceinline__ void store_cs(char* smem, int lane, int wm, int wn,
                                         float (&acc)[2][8][4]){
  float* Cs = (float*)smem;
  #pragma unroll
  for (int mi=0;mi<2;mi++){
    int r = wm*32 + mi*16 + (lane>>2);
    #pragma unroll
    for (int ni=0;ni<8;ni++){
      int c = wn*64 + ni*8 + (lane&3)*2;
      *(float2*)(Cs + r*CSTR + c)     = make_float2(acc[mi][ni][0], acc[mi][ni][1]);
      *(float2*)(Cs + (r+8)*CSTR + c) = make_float2(acc[mi][ni][2], acc[mi][ni][3]);
    }
  }
}

// ---------------- CSR build ----------------------------------------------------
__global__ void k_zero(){
  int i = blockIdx.x*256+threadIdx.x;
  if (i<N_) g_cnt[i]=0;
}
__global__ void k_count(const int* __restrict__ ei){
  int e = blockIdx.x*256+threadIdx.x;
  if (e<E_) atomicAdd(&g_cnt[ei[E_+e]], 1);
}
__global__ void k_scan(){
  __shared__ int sh[1024];
  int t = threadIdx.x;
  int base = t*10;
  int loc[10]; int run=0;
  #pragma unroll
  for (int i=0;i<10;i++){ int idx=base+i; int v=(idx<N_)? g_cnt[idx]:0; loc[i]=run; run+=v; }
  sh[t]=run; __syncthreads();
  for (int off=1; off<1024; off<<=1){
    int v = (t>=off)? sh[t-off] : 0;
    __syncthreads();
    sh[t] += v;
    __syncthreads();
  }
  int pre = (t>0)? sh[t-1] : 0;
  #pragma unroll
  for (int i=0;i<10;i++){ int idx=base+i; if (idx<N_){ int p=pre+loc[i]; g_rowptr[idx]=p; g_cur[idx]=p; } }
  if (t==1023) g_rowptr[N_] = sh[1023];
}
__global__ void k_scatter(const int* __restrict__ ei){
  int e = blockIdx.x*256+threadIdx.x;
  if (e<E_){
    int d = ei[E_+e];
    int p = atomicAdd(&g_cur[d], 1);
    g_perm[p] = e;
  }
}

// ---------------- weight transpose + split ------------------------------------
__global__ void k_prep_w(const float* __restrict__ W, int K, int N, uint32 off){
  __shared__ float tile[32][33];
  int k0 = blockIdx.x*32, n0 = blockIdx.y*32;
  int tx = threadIdx.x, ty = threadIdx.y;   // 32 x 8
  #pragma unroll
  for (int i=0;i<4;i++)
    tile[ty+i*8][tx] = W[(size_t)(k0+ty+i*8)*N + n0 + tx];
  __syncthreads();
  #pragma unroll
  for (int i=0;i<4;i++){
    int n = n0 + ty + i*8, k = k0 + tx;
    float v = tile[tx][ty+i*8];
    __nv_bfloat16 h = __float2bfloat16(v);
    g_wth[(size_t)off + (size_t)n*K + k] = h;
    g_wtl[(size_t)off + (size_t)n*K + k] = __float2bfloat16(v - __bfloat162float(h));
  }
}

// ---------------- QKV GEMMs (blockIdx.y picks set) -----------------------------
__global__ void __launch_bounds__(256,1) k_mm_qkv(
    const float* __restrict__ x,
    const float* __restrict__ bq, const float* __restrict__ bk,
    const float* __restrict__ bv){
  extern __shared__ char smem[];
  uint32 sb = smem_to_u32(smem);
  int t = threadIdx.x, lane = t&31, wid = t>>5;
  int wm = wid>>2, wn = wid&3;
  int r0 = blockIdx.x*64;
  uint32 wbase; const float* bias; float* C;
  if (blockIdx.y==0){ wbase=OFF_Q; bias=bq; C=g_Q; }
  else if (blockIdx.y==1){ wbase=OFF_K; bias=bk; C=g_K; }
  else { wbase=OFF_V; bias=bv; C=g_V; }
  float* s_bias = (float*)(smem + SM_PAR);
  s_bias[t] = bias[t];

  float acc[2][8][4];
  #pragma unroll
  for (int a=0;a<2;a++)
    #pragma unroll
    for (int b=0;b<8;b++)
      #pragma unroll
      for (int c=0;c<4;c++) acc[a][b][c]=0.f;

  for (int ck=0; ck<4; ck++){
    __syncthreads();
    stage_a(smem, x, 256, N_, r0, ck*64, t);
    stage_b(smem, wbase, 256, ck*64, t);
    __syncthreads();
    compute_chunk(sb, lane, wm, wn, acc);
  }
  __syncthreads();
  store_cs(smem, lane, wm, wn, acc);
  __syncthreads();

  float* Cs = (float*)smem;
  #pragma unroll
  for (int p=0;p<8;p++){
    int r = p*8 + wid;
    int row = r0 + r;
    if (row < N_){
      float4 v0 = *(float4*)(Cs + r*CSTR + lane*8);
      float4 v1 = *(float4*)(Cs + r*CSTR + lane*8 + 4);
      v0.x += s_bias[lane*8+0]; v0.y += s_bias[lane*8+1];
      v0.z += s_bias[lane*8+2]; v0.w += s_bias[lane*8+3];
      v1.x += s_bias[lane*8+4]; v1.y += s_bias[lane*8+5];
      v1.z += s_bias[lane*8+6]; v1.w += s_bias[lane*8+7];
      *(float4*)(C + (size_t)row*256 + lane*8)     = v0;
      *(float4*)(C + (size_t)row*256 + lane*8 + 4) = v1;
    }
  }
}

// ---------------- edge: pe-MLP GEMM + LN + scores ------------------------------
__global__ void __launch_bounds__(256,1) k_mm_edge(
    const float* __restrict__ pos, const int* __restrict__ ei,
    const float* __restrict__ Wp1, const float* __restrict__ bp1,
    const float* __restrict__ bp2, const float* __restrict__ gp,
    const float* __restrict__ bpn){
  extern __shared__ char smem[];
  uint32 sb = smem_to_u32(smem);
  int t = threadIdx.x, lane = t&31, wid = t>>5;
  int wm = wid>>2, wn = wid&3;
  int e0 = blockIdx.x*64;

  float* s_w1 = (float*)(smem + SM_PAR);  // 768
  float* s_b1 = s_w1 + 768;               // 256
  float* s_p2 = s_b1 + 256;               // 256
  float* s_gp = s_p2 + 256;               // 256
  float* s_bn = s_gp + 256;               // 256
  float* s_dp = s_bn + 256;               // 64*3
  int*   s_nd = (int*)(s_dp + 192);       // 128

  s_w1[t]     = Wp1[t];
  s_w1[256+t] = Wp1[256+t];
  s_w1[512+t] = Wp1[512+t];
  s_b1[t] = bp1[t]; s_p2[t] = bp2[t]; s_gp[t] = gp[t]; s_bn[t] = bpn[t];
  if (t < 64){
    int e = e0 + t;
    int sn = ei[e], dn = ei[E_+e];
    s_nd[t] = sn; s_nd[64+t] = dn;
    s_dp[t*3+0] = pos[dn*3+0]-pos[sn*3+0];
    s_dp[t*3+1] = pos[dn*3+1]-pos[sn*3+1];
    s_dp[t*3+2] = pos[dn*3+2]-pos[sn*3+2];
  }
  __syncthreads();

  int rr = t>>2, q = t&3;
  float dx = s_dp[rr*3+0], dy = s_dp[rr*3+1], dz = s_dp[rr*3+2];

  float acc[2][8][4];
  #pragma unroll
  for (int a=0;a<2;a++)
    #pragma unroll
    for (int b=0;b<8;b++)
      #pragma unroll
      for (int c=0;c<4;c++) acc[a][b][c]=0.f;

  for (int ck=0; ck<4; ck++){
    int kk = ck*64;
    __syncthreads();
    // A tile generated on the fly: h = relu(dp @ Wp1 + bp1), split hi/lo
    #pragma unroll
    for (int half=0; half<2; half++){
      BU H, L;
      #pragma unroll
      for (int j=0; j<8; j++){
        int c = kk + q*16 + half*8 + j;
        float v = fmaf(dz, s_w1[512+c], fmaf(dy, s_w1[256+c], fmaf(dx, s_w1[c], s_b1[c])));
        v = fmaxf(v, 0.f);
        H.b[j] = __float2bfloat16(v);
        L.b[j] = __float2bfloat16(v - __bfloat162float(H.b[j]));
      }
      uint32 dst = swz(rr, q*2 + half);
      *(uint4*)(smem + SM_A_HI + dst) = H.u;
      *(uint4*)(smem + SM_A_LO + dst) = L.u;
    }
    stage_b(smem, OFF_P2, 256, kk, t);
    __syncthreads();
    compute_chunk(sb, lane, wm, wn, acc);
  }
  __syncthreads();
  store_cs(smem, lane, wm, wn, acc);
  __syncthreads();

  float* Cs = (float*)smem;
  const float SC = 0.17677669529663688f;  // 1/sqrt(32)
  #pragma unroll
  for (int p=0;p<8;p++){
    int r = p*8 + wid;
    int e = e0 + r;
    float vals[8];
    float s1=0.f, s2=0.f;
    #pragma unroll
    for (int j=0;j<8;j++){
      vals[j] = Cs[r*CSTR + lane*8 + j] + s_p2[lane*8+j];
      s1 += vals[j]; s2 = fmaf(vals[j], vals[j], s2);
    }
    #pragma unroll
    for (int o=16;o>0;o>>=1){
      s1 += __shfl_xor_sync(0xffffffffu, s1, o);
      s2 += __shfl_xor_sync(0xffffffffu, s2, o);
    }
    float m = s1*(1.f/256.f);
    float rstd = rsqrtf(fmaxf(s2*(1.f/256.f) - m*m, 0.f) + 1e-5f);
    int sn = s_nd[r], dn = s_nd[64+r];
    const float* Qp = g_Q + (size_t)dn*256 + lane*8;
    const float* Kp = g_K + (size_t)sn*256 + lane*8;
    float4 q0 = *(const float4*)(Qp), q1 = *(const float4*)(Qp+4);
    float4 k0 = *(const float4*)(Kp), k1 = *(const float4*)(Kp+4);
    float qa[8] = {q0.x,q0.y,q0.z,q0.w,q1.x,q1.y,q1.z,q1.w};
    float ka[8] = {k0.x,k0.y,k0.z,k0.w,k1.x,k1.y,k1.z,k1.w};
    float partial = 0.f;
    #pragma unroll
    for (int j=0;j<8;j++){
      float pe = (vals[j]-m)*rstd*s_gp[lane*8+j] + s_bn[lane*8+j];
      partial = fmaf(qa[j], ka[j] + pe, partial);
    }
    partial += __shfl_xor_sync(0xffffffffu, partial, 1);
    partial += __shfl_xor_sync(0xffffffffu, partial, 2);
    if ((lane&3)==0)
      g_score[(size_t)e*8 + (lane>>2)] = partial*SC;
  }
}

// ---------------- segment softmax + weighted aggregation -----------------------
__global__ void __launch_bounds__(256) k_aggr(const int* __restrict__ ei){
  int n = blockIdx.x;
  int beg = g_rowptr[n], end = g_rowptr[n+1];
  int t = threadIdx.x, lane = t&31, w = t>>5;
  __shared__ float s_mx[8], s_rs[8];
  __shared__ float s_at[128*8];
  __shared__ int   s_sc[128];

  {
    int h = w;
    float mx = -3.0e38f;
    for (int i=beg+lane; i<end; i+=32)
      mx = fmaxf(mx, g_score[(size_t)g_perm[i]*8+h]);
    #pragma unroll
    for (int o=16;o>0;o>>=1) mx = fmaxf(mx, __shfl_xor_sync(0xffffffffu, mx, o));
    float s=0.f;
    for (int i=beg+lane; i<end; i+=32)
      s += __expf(g_score[(size_t)g_perm[i]*8+h]-mx);
    #pragma unroll
    for (int o=16;o>0;o>>=1) s += __shfl_xor_sync(0xffffffffu, s, o);
    if (lane==0){ s_mx[h]=mx; s_rs[h]=1.f/(s+1e-16f); }
  }
  __syncthreads();

  float acc=0.f;
  int h = t>>5;
  for (int c0=beg; c0<end; c0+=128){
    int cn = min(128, end-c0);
    for (int j=t; j<cn*8; j+=256){
      int i=j>>3, hh=j&7;
      int e = g_perm[c0+i];
      s_at[i*8+hh] = __expf(g_score[(size_t)e*8+hh]-s_mx[hh])*s_rs[hh];
      if (hh==0) s_sc[i] = ei[e];
    }
    __syncthreads();
    for (int i=0;i<cn;i++)
      acc = fmaf(s_at[i*8+h], g_V[(size_t)s_sc[i]*256 + t], acc);
    __syncthreads();
  }
  g_aggr[(size_t)n*256+t]=acc;
}

// ---------------- GEMM + LN (Wo and FFN2) --------------------------------------
__global__ void __launch_bounds__(256,1) k_mm_ln(int mode,
    const float* __restrict__ bias, const float* __restrict__ resx,
    const float* __restrict__ gam, const float* __restrict__ bet,
    float* __restrict__ outp){
  extern __shared__ char smem[];
  uint32 sb = smem_to_u32(smem);
  int t = threadIdx.x, lane = t&31, wid = t>>5;
  int wm = wid>>2, wn = wid&3;
  int r0 = blockIdx.x*64;
  const float* A; const float* res; float* C; int K; uint32 wbase;
  if (mode==0){ A=g_aggr; res=resx; C=g_x1; K=256;  wbase=OFF_O; }
  else        { A=g_ffn;  res=g_x1; C=outp; K=1024; wbase=OFF_F2; }

  float* s_bias = (float*)(smem + SM_PAR);
  float* s_g    = s_bias + 256;
  float* s_b    = s_g + 256;
  s_bias[t] = bias[t]; s_g[t] = gam[t]; s_b[t] = bet[t];

  float acc[2][8][4];
  #pragma unroll
  for (int a=0;a<2;a++)
    #pragma unroll
    for (int b=0;b<8;b++)
      #pragma unroll
      for (int c=0;c<4;c++) acc[a][b][c]=0.f;

  int nchunks = K/64;
  for (int ck=0; ck<nchunks; ck++){
    __syncthreads();
    stage_a(smem, A, K, N_, r0, ck*64, t);
    stage_b(smem, wbase, K, ck*64, t);
    __syncthreads();
    compute_chunk(sb, lane, wm, wn, acc);
  }
  __syncthreads();
  store_cs(smem, lane, wm, wn, acc);
  __syncthreads();

  float* Cs = (float*)smem;
  #pragma unroll
  for (int p=0;p<8;p++){
    int r = p*8 + wid;
    int row = r0 + r;
    if (row < N_){
      float4 r0v = *(const float4*)(res + (size_t)row*256 + lane*8);
      float4 r1v = *(const float4*)(res + (size_t)row*256 + lane*8 + 4);
      float vals[8];
      vals[0] = Cs[r*CSTR+lane*8+0] + s_bias[lane*8+0] + r0v.x;
      vals[1] = Cs[r*CSTR+lane*8+1] + s_bias[lane*8+1] + r0v.y;
      vals[2] = Cs[r*CSTR+lane*8+2] + s_bias[lane*8+2] + r0v.z;
      vals[3] = Cs[r*CSTR+lane*8+3] + s_bias[lane*8+3] + r0v.w;
      vals[4] = Cs[r*CSTR+lane*8+4] + s_bias[lane*8+4] + r1v.x;
      vals[5] = Cs[r*CSTR+lane*8+5] + s_bias[lane*8+5] + r1v.y;
      vals[6] = Cs[r*CSTR+lane*8+6] + s_bias[lane*8+6] + r1v.z;
      vals[7] = Cs[r*CSTR+lane*8+7] + s_bias[lane*8+7] + r1v.w;
      float s1=0.f, s2=0.f;
      #pragma unroll
      for (int j=0;j<8;j++){ s1 += vals[j]; s2 = fmaf(vals[j], vals[j], s2); }
      #pragma unroll
      for (int o=16;o>0;o>>=1){
        s1 += __shfl_xor_sync(0xffffffffu, s1, o);
        s2 += __shfl_xor_sync(0xffffffffu, s2, o);
      }
      float m = s1*(1.f/256.f);
      float rstd = rsqrtf(fmaxf(s2*(1.f/256.f) - m*m, 0.f) + 1e-5f);
      float4 o0, o1;
      o0.x = (vals[0]-m)*rstd*s_g[lane*8+0] + s_b[lane*8+0];
      o0.y = (vals[1]-m)*rstd*s_g[lane*8+1] + s_b[lane*8+1];
      o0.z = (vals[2]-m)*rstd*s_g[lane*8+2] + s_b[lane*8+2];
      o0.w = (vals[3]-m)*rstd*s_g[lane*8+3] + s_b[lane*8+3];
      o1.x = (vals[4]-m)*rstd*s_g[lane*8+4] + s_b[lane*8+4];
      o1.y = (vals[5]-m)*rstd*s_g[lane*8+5] + s_b[lane*8+5];
      o1.z = (vals[6]-m)*rstd*s_g[lane*8+6] + s_b[lane*8+6];
      o1.w = (vals[7]-m)*rstd*s_g[lane*8+7] + s_b[lane*8+7];
      *(float4*)(C + (size_t)row*256 + lane*8)     = o0;
      *(float4*)(C + (size_t)row*256 + lane*8 + 4) = o1;
    }
  }
}

// ---------------- FFN1 (relu), N=1024 via col tiles -----------------------------
__global__ void __launch_bounds__(256,1) k_mm_ffn1(const float* __restrict__ bf1){
  extern __shared__ char smem[];
  uint32 sb = smem_to_u32(smem);
  int t = threadIdx.x, lane = t&31, wid = t>>5;
  int wm = wid>>2, wn = wid&3;
  int r0 = blockIdx.x*64;
  int colOff = blockIdx.y*256;
  uint32 wbase = OFF_F1 + (uint32)colOff*256;

  float* s_bias = (float*)(smem + SM_PAR);
  s_bias[t] = bf1[colOff + t];

  float acc[2][8][4];
  #pragma unroll
  for (int a=0;a<2;a++)
    #pragma unroll
    for (int b=0;b<8;b++)
      #pragma unroll
      for (int c=0;c<4;c++) acc[a][b][c]=0.f;

  for (int ck=0; ck<4; ck++){
    __syncthreads();
    stage_a(smem, g_x1, 256, N_, r0, ck*64, t);
    stage_b(smem, wbase, 256, ck*64, t);
    __syncthreads();
    compute_chunk(sb, lane, wm, wn, acc);
  }
  __syncthreads();
  store_cs(smem, lane, wm, wn, acc);
  __syncthreads();

  float* Cs = (float*)smem;
  #pragma unroll
  for (int p=0;p<8;p++){
    int r = p*8 + wid;
    int row = r0 + r;
    if (row < N_){
      float4 v0, v1;
      v0.x = fmaxf(Cs[r*CSTR+lane*8+0] + s_bias[lane*8+0], 0.f);
      v0.y = fmaxf(Cs[r*CSTR+lane*8+1] + s_bias[lane*8+1], 0.f);
      v0.z = fmaxf(Cs[r*CSTR+lane*8+2] + s_bias[lane*8+2], 0.f);
      v0.w = fmaxf(Cs[r*CSTR+lane*8+3] + s_bias[lane*8+3], 0.f);
      v1.x = fmaxf(Cs[r*CSTR+lane*8+4] + s_bias[lane*8+4], 0.f);
      v1.y = fmaxf(Cs[r*CSTR+lane*8+5] + s_bias[lane*8+5], 0.f);
      v1.z = fmaxf(Cs[r*CSTR+lane*8+6] + s_bias[lane*8+6], 0.f);
      v1.w = fmaxf(Cs[r*CSTR+lane*8+7] + s_bias[lane*8+7], 0.f);
      *(float4*)(g_ffn + (size_t)row*1024 + colOff + lane*8)     = v0;
      *(float4*)(g_ffn + (size_t)row*1024 + colOff + lane*8 + 4) = v1;
    }
  }
}

// ---------------- launch --------------------------------------------------------
extern "C" void kernel_launch(void* const* d_in, const int* in_sizes, int n_in,
                              void* d_out, int out_size){
  const float* x    = (const float*)d_in[0];
  const float* pos  = (const float*)d_in[1];
  const int*   ei   = (const int*)  d_in[2];
  const float* Wq   = (const float*)d_in[3];
  const float* bq   = (const float*)d_in[4];
  const float* Wk   = (const float*)d_in[5];
  const float* bk   = (const float*)d_in[6];
  const float* Wv   = (const float*)d_in[7];
  const float* bv   = (const float*)d_in[8];
  const float* Wp1  = (const float*)d_in[9];
  const float* bp1  = (const float*)d_in[10];
  const float* Wp2  = (const float*)d_in[11];
  const float* bp2  = (const float*)d_in[12];
  const float* gp   = (const float*)d_in[13];
  const float* bp   = (const float*)d_in[14];
  const float* Wo   = (const float*)d_in[15];
  const float* bo   = (const float*)d_in[16];
  const float* g1   = (const float*)d_in[17];
  const float* b1n  = (const float*)d_in[18];
  const float* Wf1  = (const float*)d_in[19];
  const float* bf1  = (const float*)d_in[20];
  const float* Wf2  = (const float*)d_in[21];
  const float* bf2  = (const float*)d_in[22];
  const float* g2   = (const float*)d_in[23];
  const float* b2n  = (const float*)d_in[24];
  float* out = (float*)d_out;

  cudaFuncSetAttribute(k_mm_qkv,  cudaFuncAttributeMaxDynamicSharedMemorySize, SMEM_DYN);
  cudaFuncSetAttribute(k_mm_edge, cudaFuncAttributeMaxDynamicSharedMemorySize, SMEM_DYN);
  cudaFuncSetAttribute(k_mm_ln,   cudaFuncAttributeMaxDynamicSharedMemorySize, SMEM_DYN);
  cudaFuncSetAttribute(k_mm_ffn1, cudaFuncAttributeMaxDynamicSharedMemorySize, SMEM_DYN);

  const int MT = (N_ + 63) / 64;     // 157
  const int ET = E_ / 64;            // 2500

  // CSR build
  k_zero   <<<(N_+255)/256, 256>>>();
  k_count  <<<(E_+255)/256, 256>>>(ei);
  k_scan   <<<1, 1024>>>();
  k_scatter<<<(E_+255)/256, 256>>>(ei);

  // weight transpose + bf16 split
  k_prep_w<<<dim3(8,8),  dim3(32,8)>>>(Wq,  256, 256,  OFF_Q);
  k_prep_w<<<dim3(8,8),  dim3(32,8)>>>(Wk,  256, 256,  OFF_K);
  k_prep_w<<<dim3(8,8),  dim3(32,8)>>>(Wv,  256, 256,  OFF_V);
  k_prep_w<<<dim3(8,8),  dim3(32,8)>>>(Wp2, 256, 256,  OFF_P2);
  k_prep_w<<<dim3(8,8),  dim3(32,8)>>>(Wo,  256, 256,  OFF_O);
  k_prep_w<<<dim3(8,32), dim3(32,8)>>>(Wf1, 256, 1024, OFF_F1);
  k_prep_w<<<dim3(32,8), dim3(32,8)>>>(Wf2, 1024, 256, OFF_F2);

  // Q/K/V
  k_mm_qkv<<<dim3(MT,3), 256, SMEM_DYN>>>(x, bq, bk, bv);

  // edge: pe-MLP GEMM + LN + scores
  k_mm_edge<<<ET, 256, SMEM_DYN>>>(pos, ei, Wp1, bp1, bp2, gp, bp);

  // segment softmax + aggregation
  k_aggr<<<N_, 256>>>(ei);

  // x1 = LN(aggr@Wo + bo + x)
  k_mm_ln<<<MT, 256, SMEM_DYN>>>(0, bo, x, g1, b1n, nullptr);

  // ffn = relu(x1@Wf1 + bf1)
  k_mm_ffn1<<<dim3(MT,4), 256, SMEM_DYN>>>(bf1);

  // out = LN(ffn@Wf2 + bf2 + x1)
  k_mm_ln<<<MT, 256, SMEM_DYN>>>(1, bf2, nullptr, g2, b2n, out);

  (void)in_sizes; (void)n_in; (void)out_size;
}

// round 5
// speedup vs baseline: 1.9979x; 1.1312x over previous
#include <cuda_runtime.h>
#include <cuda_bf16.h>
#include <math.h>

#define N_ 10000
#define E_ 160000

typedef unsigned int uint32;

// ---------------- device scratch ---------------------------------------------
__device__ __align__(16) float g_Q[N_*256];
__device__ __align__(16) float g_K[N_*256];
__device__ __align__(16) float g_V[N_*256];
__device__ __align__(16) float g_score[E_*8];
__device__ __align__(16) float g_aggr[N_*256];
__device__ __align__(16) float g_x1[N_*256];
__device__ __align__(16) float g_ffn[N_*1024];
__device__ int   g_cnt[N_];
__device__ int   g_rowptr[N_+1];
__device__ int   g_cur[N_];
__device__ int   g_perm[E_];

// transposed+split weights, [N][K] bf16 (K contiguous)
#define OFF_Q  0u
#define OFF_K  65536u
#define OFF_V  131072u
#define OFF_P2 196608u
#define OFF_O  262144u
#define OFF_F1 327680u      /* [1024][256] */
#define OFF_F2 589824u      /* [256][1024] */
#define WT_TOTAL 851968u
__device__ __align__(16) __nv_bfloat16 g_wth[WT_TOTAL];
__device__ __align__(16) __nv_bfloat16 g_wtl[WT_TOTAL];

// ---------------- smem layout ---------------------------------------------------
// A bufs: 128 rows x 64 k bf16 (hi 16K + lo 16K) = 32K each
// B bufs: 256 rows x 64 k bf16 (hi 32K + lo 32K) = 64K each
// C staging (epilogue, reuses bufs): 128 x 264 fp32 = 135168 B
#define SM_A0   0
#define SM_A1   32768
#define SM_B0   65536
#define SM_B1   131072
#define SM_PAR  196608
#define SMEM_DYN 206848
#define A_LO_OFF 16384
#define B_LO_OFF 32768
#define CSTR    264

__device__ __forceinline__ uint32 smem_to_u32(const void* p){
  uint32 a;
  asm("{ .reg .u64 t; cvta.to.shared.u64 t, %1; cvt.u32.u64 %0, t; }" : "=r"(a) : "l"(p));
  return a;
}
__device__ __forceinline__ uint32 swz(int row, int c16){
  return (uint32)(row*128 + (((c16) ^ (row & 7)) << 4));
}
__device__ __forceinline__ void ldsm4(uint32* r, uint32 addr){
  asm volatile("ldmatrix.sync.aligned.m8n8.x4.shared.b16 {%0,%1,%2,%3}, [%4];"
    : "=r"(r[0]),"=r"(r[1]),"=r"(r[2]),"=r"(r[3]) : "r"(addr));
}
__device__ __forceinline__ void mma_bf16(float* c, const uint32* a, uint32 b0, uint32 b1){
  asm volatile("mma.sync.aligned.m16n8k16.row.col.f32.bf16.bf16.f32 "
    "{%0,%1,%2,%3}, {%4,%5,%6,%7}, {%8,%9}, {%0,%1,%2,%3};"
    : "+f"(c[0]),"+f"(c[1]),"+f"(c[2]),"+f"(c[3])
    : "r"(a[0]),"r"(a[1]),"r"(a[2]),"r"(a[3]), "r"(b0),"r"(b1));
}
__device__ __forceinline__ void cpa16(uint32 dst, const void* src){
  asm volatile("cp.async.cg.shared.global [%0], [%1], 16;" :: "r"(dst), "l"(src));
}
#define CPA_COMMIT() asm volatile("cp.async.commit_group;" ::: "memory")
#define CPA_WAIT(n)  asm volatile("cp.async.wait_group %0;" :: "n"(n) : "memory")

union BU { __nv_bfloat16 b[8]; uint4 u; };

// ---------------- staging -------------------------------------------------------
// B tile via cp.async: 256 rows (N) x 64 (K) bf16 hi/lo
__device__ __forceinline__ void stage_b_async(uint32 dstbase, uint32 baseOff, int Kst,
                                              int kk, int t){
  #pragma unroll
  for (int s=0; s<8; s++){
    int slot = t + s*256;
    int n = slot >> 3, g = slot & 7;
    size_t src = (size_t)baseOff + (size_t)n*Kst + kk + g*8;
    uint32 dst = dstbase + swz(n, g);
    cpa16(dst,             (const void*)(g_wth + src));
    cpa16(dst + B_LO_OFF,  (const void*)(g_wtl + src));
  }
}

// A tile from fp32 gmem: 128 rows x 64 k, split hi/lo, zero-pad past M
__device__ __forceinline__ void stage_a(char* smem, uint32 aoff,
                                        const float* __restrict__ A,
                                        int lda, int M, int r0, int kk, int t){
  int r = t >> 1;             // 0..127
  int h32 = (t & 1) * 32;     // col half
  int row = r0 + r;
  bool ok = row < M;
  const float* src = A + (size_t)row*lda + kk + h32;
  #pragma unroll
  for (int g=0; g<4; g++){
    float v[8];
    if (ok){
      float4 a = *(const float4*)(src + g*8);
      float4 b = *(const float4*)(src + g*8 + 4);
      v[0]=a.x; v[1]=a.y; v[2]=a.z; v[3]=a.w; v[4]=b.x; v[5]=b.y; v[6]=b.z; v[7]=b.w;
    } else {
      #pragma unroll
      for (int j=0;j<8;j++) v[j]=0.f;
    }
    BU H, L;
    #pragma unroll
    for (int j=0;j<8;j++){
      H.b[j] = __float2bfloat16(v[j]);
      L.b[j] = __float2bfloat16(v[j] - __bfloat162float(H.b[j]));
    }
    uint32 dst = swz(r, (h32>>3) + g);
    *(uint4*)(smem + aoff + dst)            = H.u;
    *(uint4*)(smem + aoff + A_LO_OFF + dst) = L.u;
  }
}

// ---------------- warp MMA mainloop: warp tile 32 x 128 -------------------------
__device__ __forceinline__ void compute_chunk(uint32 sb, uint32 aoff, uint32 boff,
                                              int lane, int wm, int wn,
                                              float (&acc)[2][16][4]){
  uint32 rbA[2]; int rxA[2];
  #pragma unroll
  for (int mi=0;mi<2;mi++){
    int row = wm*32 + mi*16 + (lane&15);
    rbA[mi] = sb + aoff + row*128;
    rxA[mi] = row & 7;
  }
  int hi4 = lane>>4;
  uint32 rbB[8]; int rxB[8];
  #pragma unroll
  for (int g=0; g<8; g++){
    int n = wn*128 + g*16 + ((lane>>4)<<3) + (lane&7);
    rbB[g] = sb + boff + n*128;
    rxB[g] = n & 7;
  }
  int cB = (lane>>3)&1;
  #pragma unroll
  for (int ks=0; ks<4; ks++){
    int c16 = ks*2;
    uint32 Ah[2][4], Al[2][4];
    #pragma unroll
    for (int mi=0;mi<2;mi++){
      uint32 off = ((uint32)((c16 + hi4) ^ rxA[mi])) << 4;
      ldsm4(Ah[mi], rbA[mi] + off);
      ldsm4(Al[mi], rbA[mi] + A_LO_OFF + off);
    }
    #pragma unroll
    for (int gp=0; gp<2; gp++){
      uint32 Bh[4][4], Bl[4][4];
      #pragma unroll
      for (int gg=0; gg<4; gg++){
        int g = gp*4+gg;
        uint32 off = ((uint32)((c16 + cB) ^ rxB[g])) << 4;
        ldsm4(Bh[gg], rbB[g] + off);
        ldsm4(Bl[gg], rbB[g] + B_LO_OFF + off);
      }
      #pragma unroll
      for (int mi=0;mi<2;mi++){
        #pragma unroll
        for (int nn=0;nn<8;nn++){
          int ni = gp*8+nn;
          uint32 b0h = Bh[nn>>1][(nn&1)*2], b1h = Bh[nn>>1][(nn&1)*2+1];
          uint32 b0l = Bl[nn>>1][(nn&1)*2], b1l = Bl[nn>>1][(nn&1)*2+1];
          mma_bf16(acc[mi][ni], Ah[mi], b0h, b1h);
          mma_bf16(acc[mi][ni], Al[mi], b0h, b1h);
          mma_bf16(acc[mi][ni], Ah[mi], b0l, b1l);
        }
      }
    }
  }
}

__device__ __forceinline__ void store_cs(char* smem, int lane, int wm, int wn,
                                         float (&acc)[2][16][4]){
  float* Cs = (float*)smem;
  #pragma unroll
  for (int mi=0;mi<2;mi++){
    int r = wm*32 + mi*16 + (lane>>2);
    #pragma unroll
    for (int ni=0;ni<16;ni++){
      int c = wn*128 + ni*8 + (lane&3)*2;
      *(float2*)(Cs + r*CSTR + c)     = make_float2(acc[mi][ni][0], acc[mi][ni][1]);
      *(float2*)(Cs + (r+8)*CSTR + c) = make_float2(acc[mi][ni][2], acc[mi][ni][3]);
    }
  }
}

#define ZERO_ACC(acc) { \
  _Pragma("unroll") for (int _a=0;_a<2;_a++) \
    _Pragma("unroll") for (int _b=0;_b<16;_b++) \
      _Pragma("unroll") for (int _c=0;_c<4;_c++) (acc)[_a][_b][_c]=0.f; }

// ---------------- CSR build -----------------------------------------------------
__global__ void k_zero(){
  int i = blockIdx.x*256+threadIdx.x;
  if (i<N_) g_cnt[i]=0;
}
__global__ void k_count(const int* __restrict__ ei){
  int e = blockIdx.x*256+threadIdx.x;
  if (e<E_) atomicAdd(&g_cnt[ei[E_+e]], 1);
}
__global__ void k_scan(){
  __shared__ int sh[1024];
  int t = threadIdx.x;
  int base = t*10;
  int loc[10]; int run=0;
  #pragma unroll
  for (int i=0;i<10;i++){ int idx=base+i; int v=(idx<N_)? g_cnt[idx]:0; loc[i]=run; run+=v; }
  sh[t]=run; __syncthreads();
  for (int off=1; off<1024; off<<=1){
    int v = (t>=off)? sh[t-off] : 0;
    __syncthreads();
    sh[t] += v;
    __syncthreads();
  }
  int pre = (t>0)? sh[t-1] : 0;
  #pragma unroll
  for (int i=0;i<10;i++){ int idx=base+i; if (idx<N_){ int p=pre+loc[i]; g_rowptr[idx]=p; g_cur[idx]=p; } }
  if (t==1023) g_rowptr[N_] = sh[1023];
}
__global__ void k_scatter(const int* __restrict__ ei){
  int e = blockIdx.x*256+threadIdx.x;
  if (e<E_){
    int d = ei[E_+e];
    int p = atomicAdd(&g_cur[d], 1);
    g_perm[p] = e;
  }
}

// ---------------- weight transpose + split --------------------------------------
__global__ void k_prep_w(const float* __restrict__ W, int K, int N, uint32 off){
  __shared__ float tile[32][33];
  int k0 = blockIdx.x*32, n0 = blockIdx.y*32;
  int tx = threadIdx.x, ty = threadIdx.y;   // 32 x 8
  #pragma unroll
  for (int i=0;i<4;i++)
    tile[ty+i*8][tx] = W[(size_t)(k0+ty+i*8)*N + n0 + tx];
  __syncthreads();
  #pragma unroll
  for (int i=0;i<4;i++){
    int n = n0 + ty + i*8, k = k0 + tx;
    float v = tile[tx][ty+i*8];
    __nv_bfloat16 h = __float2bfloat16(v);
    g_wth[(size_t)off + (size_t)n*K + k] = h;
    g_wtl[(size_t)off + (size_t)n*K + k] = __float2bfloat16(v - __bfloat162float(h));
  }
}

// ---------------- QKV GEMMs (blockIdx.y picks set) ------------------------------
__global__ void __launch_bounds__(256,1) k_mm_qkv(
    const float* __restrict__ x,
    const float* __restrict__ bq, const float* __restrict__ bk,
    const float* __restrict__ bv){
  extern __shared__ char smem[];
  uint32 sb = smem_to_u32(smem);
  int t = threadIdx.x, lane = t&31, wid = t>>5;
  int wm = wid>>1, wn = wid&1;
  int r0 = blockIdx.x*128;
  uint32 wbase; const float* bias; float* C;
  if (blockIdx.y==0){ wbase=OFF_Q; bias=bq; C=g_Q; }
  else if (blockIdx.y==1){ wbase=OFF_K; bias=bk; C=g_K; }
  else { wbase=OFF_V; bias=bv; C=g_V; }
  float* s_bias = (float*)(smem + SM_PAR);
  s_bias[t] = bias[t];

  float acc[2][16][4];
  ZERO_ACC(acc);

  stage_a(smem, SM_A0, x, 256, N_, r0, 0, t);
  stage_b_async(sb + SM_B0, wbase, 256, 0, t);
  CPA_COMMIT();
  #pragma unroll
  for (int ck=0; ck<4; ck++){
    if (ck<3){
      uint32 ao = (ck&1)? SM_A0 : SM_A1;
      uint32 bo = (ck&1)? SM_B0 : SM_B1;
      stage_a(smem, ao, x, 256, N_, r0, (ck+1)*64, t);
      stage_b_async(sb + bo, wbase, 256, (ck+1)*64, t);
      CPA_COMMIT();
      CPA_WAIT(1);
    } else {
      CPA_WAIT(0);
    }
    __syncthreads();
    compute_chunk(sb, (ck&1)? SM_A1:SM_A0, (ck&1)? SM_B1:SM_B0, lane, wm, wn, acc);
    __syncthreads();
  }
  store_cs(smem, lane, wm, wn, acc);
  __syncthreads();

  float* Cs = (float*)smem;
  #pragma unroll
  for (int p=0;p<16;p++){
    int r = p*8 + wid;
    int row = r0 + r;
    if (row < N_){
      float4 v0 = *(float4*)(Cs + r*CSTR + lane*8);
      float4 v1 = *(float4*)(Cs + r*CSTR + lane*8 + 4);
      v0.x += s_bias[lane*8+0]; v0.y += s_bias[lane*8+1];
      v0.z += s_bias[lane*8+2]; v0.w += s_bias[lane*8+3];
      v1.x += s_bias[lane*8+4]; v1.y += s_bias[lane*8+5];
      v1.z += s_bias[lane*8+6]; v1.w += s_bias[lane*8+7];
      *(float4*)(C + (size_t)row*256 + lane*8)     = v0;
      *(float4*)(C + (size_t)row*256 + lane*8 + 4) = v1;
    }
  }
}

// ---------------- edge: pe-MLP GEMM + LN + scores -------------------------------
__global__ void __launch_bounds__(256,1) k_mm_edge(
    const float* __restrict__ pos, const int* __restrict__ ei,
    const float* __restrict__ Wp1, const float* __restrict__ bp1,
    const float* __restrict__ bp2, const float* __restrict__ gp,
    const float* __restrict__ bpn){
  extern __shared__ char smem[];
  uint32 sb = smem_to_u32(smem);
  int t = threadIdx.x, lane = t&31, wid = t>>5;
  int wm = wid>>1, wn = wid&1;
  int e0 = blockIdx.x*128;

  float* s_w1 = (float*)(smem + SM_PAR);  // 768
  float* s_b1 = s_w1 + 768;               // 256
  float* s_p2 = s_b1 + 256;               // 256
  float* s_gp = s_p2 + 256;               // 256
  float* s_bn = s_gp + 256;               // 256
  float* s_dp = s_bn + 256;               // 128*3
  int*   s_nd = (int*)(s_dp + 384);       // 256

  s_w1[t]     = Wp1[t];
  s_w1[256+t] = Wp1[256+t];
  s_w1[512+t] = Wp1[512+t];
  s_b1[t] = bp1[t]; s_p2[t] = bp2[t]; s_gp[t] = gp[t]; s_bn[t] = bpn[t];
  if (t < 128){
    int e = e0 + t;
    int sn = ei[e], dn = ei[E_+e];
    s_nd[t] = sn; s_nd[128+t] = dn;
    s_dp[t*3+0] = pos[dn*3+0]-pos[sn*3+0];
    s_dp[t*3+1] = pos[dn*3+1]-pos[sn*3+1];
    s_dp[t*3+2] = pos[dn*3+2]-pos[sn*3+2];
  }
  __syncthreads();

  int rr = t>>1;
  int h32 = (t&1)*32;
  float dx = s_dp[rr*3+0], dy = s_dp[rr*3+1], dz = s_dp[rr*3+2];

  float acc[2][16][4];
  ZERO_ACC(acc);

  // A-tile generator: h = relu(dp @ Wp1 + bp1), split hi/lo
  auto gen_a = [&](uint32 aoff, int kk){
    #pragma unroll
    for (int g=0; g<4; g++){
      BU H, L;
      #pragma unroll
      for (int j=0; j<8; j++){
        int c = kk + h32 + g*8 + j;
        float v = fmaf(dz, s_w1[512+c], fmaf(dy, s_w1[256+c], fmaf(dx, s_w1[c], s_b1[c])));
        v = fmaxf(v, 0.f);
        H.b[j] = __float2bfloat16(v);
        L.b[j] = __float2bfloat16(v - __bfloat162float(H.b[j]));
      }
      uint32 dst = swz(rr, (h32>>3) + g);
      *(uint4*)(smem + aoff + dst)            = H.u;
      *(uint4*)(smem + aoff + A_LO_OFF + dst) = L.u;
    }
  };

  gen_a(SM_A0, 0);
  stage_b_async(sb + SM_B0, OFF_P2, 256, 0, t);
  CPA_COMMIT();
  #pragma unroll
  for (int ck=0; ck<4; ck++){
    if (ck<3){
      gen_a((ck&1)? SM_A0 : SM_A1, (ck+1)*64);
      stage_b_async(sb + ((ck&1)? SM_B0 : SM_B1), OFF_P2, 256, (ck+1)*64, t);
      CPA_COMMIT();
      CPA_WAIT(1);
    } else {
      CPA_WAIT(0);
    }
    __syncthreads();
    compute_chunk(sb, (ck&1)? SM_A1:SM_A0, (ck&1)? SM_B1:SM_B0, lane, wm, wn, acc);
    __syncthreads();
  }
  store_cs(smem, lane, wm, wn, acc);
  __syncthreads();

  float* Cs = (float*)smem;
  const float SC = 0.17677669529663688f;  // 1/sqrt(32)
  #pragma unroll
  for (int p=0;p<16;p++){
    int r = p*8 + wid;
    int e = e0 + r;
    float vals[8];
    float s1=0.f, s2=0.f;
    #pragma unroll
    for (int j=0;j<8;j++){
      vals[j] = Cs[r*CSTR + lane*8 + j] + s_p2[lane*8+j];
      s1 += vals[j]; s2 = fmaf(vals[j], vals[j], s2);
    }
    #pragma unroll
    for (int o=16;o>0;o>>=1){
      s1 += __shfl_xor_sync(0xffffffffu, s1, o);
      s2 += __shfl_xor_sync(0xffffffffu, s2, o);
    }
    float m = s1*(1.f/256.f);
    float rstd = rsqrtf(fmaxf(s2*(1.f/256.f) - m*m, 0.f) + 1e-5f);
    int sn = s_nd[r], dn = s_nd[128+r];
    const float* Qp = g_Q + (size_t)dn*256 + lane*8;
    const float* Kp = g_K + (size_t)sn*256 + lane*8;
    float4 q0 = *(const float4*)(Qp), q1 = *(const float4*)(Qp+4);
    float4 k0 = *(const float4*)(Kp), k1 = *(const float4*)(Kp+4);
    float qa[8] = {q0.x,q0.y,q0.z,q0.w,q1.x,q1.y,q1.z,q1.w};
    float ka[8] = {k0.x,k0.y,k0.z,k0.w,k1.x,k1.y,k1.z,k1.w};
    float partial = 0.f;
    #pragma unroll
    for (int j=0;j<8;j++){
      float pe = (vals[j]-m)*rstd*s_gp[lane*8+j] + s_bn[lane*8+j];
      partial = fmaf(qa[j], ka[j] + pe, partial);
    }
    partial += __shfl_xor_sync(0xffffffffu, partial, 1);
    partial += __shfl_xor_sync(0xffffffffu, partial, 2);
    if ((lane&3)==0)
      g_score[(size_t)e*8 + (lane>>2)] = partial*SC;
  }
}

// ---------------- segment softmax + weighted aggregation ------------------------
__global__ void __launch_bounds__(256) k_aggr(const int* __restrict__ ei){
  int n = blockIdx.x;
  int beg = g_rowptr[n], end = g_rowptr[n+1];
  int t = threadIdx.x, lane = t&31, w = t>>5;
  __shared__ float s_mx[8], s_rs[8];
  __shared__ float s_at[128*8];
  __shared__ int   s_sc[128];

  {
    int h = w;
    float mx = -3.0e38f;
    for (int i=beg+lane; i<end; i+=32)
      mx = fmaxf(mx, g_score[(size_t)g_perm[i]*8+h]);
    #pragma unroll
    for (int o=16;o>0;o>>=1) mx = fmaxf(mx, __shfl_xor_sync(0xffffffffu, mx, o));
    float s=0.f;
    for (int i=beg+lane; i<end; i+=32)
      s += __expf(g_score[(size_t)g_perm[i]*8+h]-mx);
    #pragma unroll
    for (int o=16;o>0;o>>=1) s += __shfl_xor_sync(0xffffffffu, s, o);
    if (lane==0){ s_mx[h]=mx; s_rs[h]=1.f/(s+1e-16f); }
  }
  __syncthreads();

  float acc=0.f;
  int h = t>>5;
  for (int c0=beg; c0<end; c0+=128){
    int cn = min(128, end-c0);
    for (int j=t; j<cn*8; j+=256){
      int i=j>>3, hh=j&7;
      int e = g_perm[c0+i];
      s_at[i*8+hh] = __expf(g_score[(size_t)e*8+hh]-s_mx[hh])*s_rs[hh];
      if (hh==0) s_sc[i] = ei[e];
    }
    __syncthreads();
    for (int i=0;i<cn;i++)
      acc = fmaf(s_at[i*8+h], g_V[(size_t)s_sc[i]*256 + t], acc);
    __syncthreads();
  }
  g_aggr[(size_t)n*256+t]=acc;
}

// ---------------- GEMM + LN (Wo and FFN2) ---------------------------------------
__global__ void __launch_bounds__(256,1) k_mm_ln(int mode,
    const float* __restrict__ bias, const float* __restrict__ resx,
    const float* __restrict__ gam, const float* __restrict__ bet,
    float* __restrict__ outp){
  extern __shared__ char smem[];
  uint32 sb = smem_to_u32(smem);
  int t = threadIdx.x, lane = t&31, wid = t>>5;
  int wm = wid>>1, wn = wid&1;
  int r0 = blockIdx.x*128;
  const float* A; const float* res; float* C; int K; uint32 wbase;
  if (mode==0){ A=g_aggr; res=resx; C=g_x1; K=256;  wbase=OFF_O; }
  else        { A=g_ffn;  res=g_x1; C=outp; K=1024; wbase=OFF_F2; }

  float* s_bias = (float*)(smem + SM_PAR);
  float* s_g    = s_bias + 256;
  float* s_b    = s_g + 256;
  s_bias[t] = bias[t]; s_g[t] = gam[t]; s_b[t] = bet[t];

  float acc[2][16][4];
  ZERO_ACC(acc);

  int nchunks = K/64;
  stage_a(smem, SM_A0, A, K, N_, r0, 0, t);
  stage_b_async(sb + SM_B0, wbase, K, 0, t);
  CPA_COMMIT();
  for (int ck=0; ck<nchunks; ck++){
    if (ck+1 < nchunks){
      uint32 ao = (ck&1)? SM_A0 : SM_A1;
      uint32 bo = (ck&1)? SM_B0 : SM_B1;
      stage_a(smem, ao, A, K, N_, r0, (ck+1)*64, t);
      stage_b_async(sb + bo, wbase, K, (ck+1)*64, t);
      CPA_COMMIT();
      CPA_WAIT(1);
    } else {
      CPA_WAIT(0);
    }
    __syncthreads();
    compute_chunk(sb, (ck&1)? SM_A1:SM_A0, (ck&1)? SM_B1:SM_B0, lane, wm, wn, acc);
    __syncthreads();
  }
  store_cs(smem, lane, wm, wn, acc);
  __syncthreads();

  float* Cs = (float*)smem;
  #pragma unroll
  for (int p=0;p<16;p++){
    int r = p*8 + wid;
    int row = r0 + r;
    if (row < N_){
      float4 r0v = *(const float4*)(res + (size_t)row*256 + lane*8);
      float4 r1v = *(const float4*)(res + (size_t)row*256 + lane*8 + 4);
      float vals[8];
      vals[0] = Cs[r*CSTR+lane*8+0] + s_bias[lane*8+0] + r0v.x;
      vals[1] = Cs[r*CSTR+lane*8+1] + s_bias[lane*8+1] + r0v.y;
      vals[2] = Cs[r*CSTR+lane*8+2] + s_bias[lane*8+2] + r0v.z;
      vals[3] = Cs[r*CSTR+lane*8+3] + s_bias[lane*8+3] + r0v.w;
      vals[4] = Cs[r*CSTR+lane*8+4] + s_bias[lane*8+4] + r1v.x;
      vals[5] = Cs[r*CSTR+lane*8+5] + s_bias[lane*8+5] + r1v.y;
      vals[6] = Cs[r*CSTR+lane*8+6] + s_bias[lane*8+6] + r1v.z;
      vals[7] = Cs[r*CSTR+lane*8+7] + s_bias[lane*8+7] + r1v.w;
      float s1=0.f, s2=0.f;
      #pragma unroll
      for (int j=0;j<8;j++){ s1 += vals[j]; s2 = fmaf(vals[j], vals[j], s2); }
      #pragma unroll
      for (int o=16;o>0;o>>=1){
        s1 += __shfl_xor_sync(0xffffffffu, s1, o);
        s2 += __shfl_xor_sync(0xffffffffu, s2, o);
      }
      float m = s1*(1.f/256.f);
      float rstd = rsqrtf(fmaxf(s2*(1.f/256.f) - m*m, 0.f) + 1e-5f);
      float4 o0, o1;
      o0.x = (vals[0]-m)*rstd*s_g[lane*8+0] + s_b[lane*8+0];
      o0.y = (vals[1]-m)*rstd*s_g[lane*8+1] + s_b[lane*8+1];
      o0.z = (vals[2]-m)*rstd*s_g[lane*8+2] + s_b[lane*8+2];
      o0.w = (vals[3]-m)*rstd*s_g[lane*8+3] + s_b[lane*8+3];
      o1.x = (vals[4]-m)*rstd*s_g[lane*8+4] + s_b[lane*8+4];
      o1.y = (vals[5]-m)*rstd*s_g[lane*8+5] + s_b[lane*8+5];
      o1.z = (vals[6]-m)*rstd*s_g[lane*8+6] + s_b[lane*8+6];
      o1.w = (vals[7]-m)*rstd*s_g[lane*8+7] + s_b[lane*8+7];
      *(float4*)(C + (size_t)row*256 + lane*8)     = o0;
      *(float4*)(C + (size_t)row*256 + lane*8 + 4) = o1;
    }
  }
}

// ---------------- FFN1 (relu), N=1024 via col tiles ------------------------------
__global__ void __launch_bounds__(256,1) k_mm_ffn1(const float* __restrict__ bf1){
  extern __shared__ char smem[];
  uint32 sb = smem_to_u32(smem);
  int t = threadIdx.x, lane = t&31, wid = t>>5;
  int wm = wid>>1, wn = wid&1;
  int r0 = blockIdx.x*128;
  int colOff = blockIdx.y*256;
  uint32 wbase = OFF_F1 + (uint32)colOff*256;

  float* s_bias = (float*)(smem + SM_PAR);
  s_bias[t] = bf1[colOff + t];

  float acc[2][16][4];
  ZERO_ACC(acc);

  stage_a(smem, SM_A0, g_x1, 256, N_, r0, 0, t);
  stage_b_async(sb + SM_B0, wbase, 256, 0, t);
  CPA_COMMIT();
  #pragma unroll
  for (int ck=0; ck<4; ck++){
    if (ck<3){
      uint32 ao = (ck&1)? SM_A0 : SM_A1;
      uint32 bo = (ck&1)? SM_B0 : SM_B1;
      stage_a(smem, ao, g_x1, 256, N_, r0, (ck+1)*64, t);
      stage_b_async(sb + bo, wbase, 256, (ck+1)*64, t);
      CPA_COMMIT();
      CPA_WAIT(1);
    } else {
      CPA_WAIT(0);
    }
    __syncthreads();
    compute_chunk(sb, (ck&1)? SM_A1:SM_A0, (ck&1)? SM_B1:SM_B0, lane, wm, wn, acc);
    __syncthreads();
  }
  store_cs(smem, lane, wm, wn, acc);
  __syncthreads();

  float* Cs = (float*)smem;
  #pragma unroll
  for (int p=0;p<16;p++){
    int r = p*8 + wid;
    int row = r0 + r;
    if (row < N_){
      float4 v0, v1;
      v0.x = fmaxf(Cs[r*CSTR+lane*8+0] + s_bias[lane*8+0], 0.f);
      v0.y = fmaxf(Cs[r*CSTR+lane*8+1] + s_bias[lane*8+1], 0.f);
      v0.z = fmaxf(Cs[r*CSTR+lane*8+2] + s_bias[lane*8+2], 0.f);
      v0.w = fmaxf(Cs[r*CSTR+lane*8+3] + s_bias[lane*8+3], 0.f);
      v1.x = fmaxf(Cs[r*CSTR+lane*8+4] + s_bias[lane*8+4], 0.f);
      v1.y = fmaxf(Cs[r*CSTR+lane*8+5] + s_bias[lane*8+5], 0.f);
      v1.z = fmaxf(Cs[r*CSTR+lane*8+6] + s_bias[lane*8+6], 0.f);
      v1.w = fmaxf(Cs[r*CSTR+lane*8+7] + s_bias[lane*8+7], 0.f);
      *(float4*)(g_ffn + (size_t)row*1024 + colOff + lane*8)     = v0;
      *(float4*)(g_ffn + (size_t)row*1024 + colOff + lane*8 + 4) = v1;
    }
  }
}

// ---------------- launch ---------------------------------------------------------
extern "C" void kernel_launch(void* const* d_in, const int* in_sizes, int n_in,
                              void* d_out, int out_size){
  const float* x    = (const float*)d_in[0];
  const float* pos  = (const float*)d_in[1];
  const int*   ei   = (const int*)  d_in[2];
  const float* Wq   = (const float*)d_in[3];
  const float* bq   = (const float*)d_in[4];
  const float* Wk   = (const float*)d_in[5];
  const float* bk   = (const float*)d_in[6];
  const float* Wv   = (const float*)d_in[7];
  const float* bv   = (const float*)d_in[8];
  const float* Wp1  = (const float*)d_in[9];
  const float* bp1  = (const float*)d_in[10];
  const float* Wp2  = (const float*)d_in[11];
  const float* bp2  = (const float*)d_in[12];
  const float* gp   = (const float*)d_in[13];
  const float* bp   = (const float*)d_in[14];
  const float* Wo   = (const float*)d_in[15];
  const float* bo   = (const float*)d_in[16];
  const float* g1   = (const float*)d_in[17];
  const float* b1n  = (const float*)d_in[18];
  const float* Wf1  = (const float*)d_in[19];
  const float* bf1  = (const float*)d_in[20];
  const float* Wf2  = (const float*)d_in[21];
  const float* bf2  = (const float*)d_in[22];
  const float* g2   = (const float*)d_in[23];
  const float* b2n  = (const float*)d_in[24];
  float* out = (float*)d_out;

  cudaFuncSetAttribute(k_mm_qkv,  cudaFuncAttributeMaxDynamicSharedMemorySize, SMEM_DYN);
  cudaFuncSetAttribute(k_mm_edge, cudaFuncAttributeMaxDynamicSharedMemorySize, SMEM_DYN);
  cudaFuncSetAttribute(k_mm_ln,   cudaFuncAttributeMaxDynamicSharedMemorySize, SMEM_DYN);
  cudaFuncSetAttribute(k_mm_ffn1, cudaFuncAttributeMaxDynamicSharedMemorySize, SMEM_DYN);

  const int MT = (N_ + 127) / 128;   // 79
  const int ET = E_ / 128;           // 1250

  // CSR build
  k_zero   <<<(N_+255)/256, 256>>>();
  k_count  <<<(E_+255)/256, 256>>>(ei);
  k_scan   <<<1, 1024>>>();
  k_scatter<<<(E_+255)/256, 256>>>(ei);

  // weight transpose + bf16 split
  k_prep_w<<<dim3(8,8),  dim3(32,8)>>>(Wq,  256, 256,  OFF_Q);
  k_prep_w<<<dim3(8,8),  dim3(32,8)>>>(Wk,  256, 256,  OFF_K);
  k_prep_w<<<dim3(8,8),  dim3(32,8)>>>(Wv,  256, 256,  OFF_V);
  k_prep_w<<<dim3(8,8),  dim3(32,8)>>>(Wp2, 256, 256,  OFF_P2);
  k_prep_w<<<dim3(8,8),  dim3(32,8)>>>(Wo,  256, 256,  OFF_O);
  k_prep_w<<<dim3(8,32), dim3(32,8)>>>(Wf1, 256, 1024, OFF_F1);
  k_prep_w<<<dim3(32,8), dim3(32,8)>>>(Wf2, 1024, 256, OFF_F2);

  // Q/K/V
  k_mm_qkv<<<dim3(MT,3), 256, SMEM_DYN>>>(x, bq, bk, bv);

  // edge: pe-MLP GEMM + LN + scores
  k_mm_edge<<<ET, 256, SMEM_DYN>>>(pos, ei, Wp1, bp1, bp2, gp, bp);

  // segment softmax + aggregation
  k_aggr<<<N_, 256>>>(ei);

  // x1 = LN(aggr@Wo + bo + x)
  k_mm_ln<<<MT, 256, SMEM_DYN>>>(0, bo, x, g1, b1n, nullptr);

  // ffn = relu(x1@Wf1 + bf1)
  k_mm_ffn1<<<dim3(MT,4), 256, SMEM_DYN>>>(bf1);

  // out = LN(ffn@Wf2 + bf2 + x1)
  k_mm_ln<<<MT, 256, SMEM_DYN>>>(1, bf2, nullptr, g2, b2n, out);

  (void)in_sizes; (void)n_in; (void)out_size;
}

// round 6
// speedup vs baseline: 2.5244x; 1.2635x over previous
#include <cuda_runtime.h>
#include <cuda_fp16.h>
#include <math.h>

#define N_ 10000
#define E_ 160000

typedef unsigned int uint32;

// ---------------- device scratch ---------------------------------------------
__device__ __align__(16) float g_Q[N_*256];
__device__ __align__(16) float g_K[N_*256];
__device__ __align__(16) float g_V[N_*256];
__device__ __align__(16) float g_score[E_*8];
__device__ __align__(16) float g_aggr[N_*256];
__device__ __align__(16) float g_x1[N_*256];
__device__ __align__(16) float g_ffn[N_*1024];
__device__ int   g_cnt[N_];
__device__ int   g_rowptr[N_+1];
__device__ int   g_cur[N_];
__device__ int   g_perm[E_];

// transposed weights, [N][K] fp16 (K contiguous)
#define OFF_Q  0u
#define OFF_K  65536u
#define OFF_V  131072u
#define OFF_P2 196608u
#define OFF_O  262144u
#define OFF_F1 327680u      /* [1024][256] */
#define OFF_F2 589824u      /* [256][1024] */
#define WT_TOTAL 851968u
__device__ __align__(16) __half g_wt[WT_TOTAL];

// ---------------- smem layout ---------------------------------------------------
// A bufs: 128 rows x 64 k fp16 (hi 16K + lo 16K) = 32K each
// B bufs: 256 rows x 64 k fp16 = 32K each (hi only)
// C staging (epilogue, reuses bufs): 128 x 264 fp32 = 135168 B
#define SM_A0   0
#define SM_A1   32768
#define SM_B0   65536
#define SM_B1   98304
#define SM_PAR  136192
#define SMEM_DYN 146432
#define A_LO_OFF 16384
#define CSTR    264

__device__ __forceinline__ uint32 smem_to_u32(const void* p){
  uint32 a;
  asm("{ .reg .u64 t; cvta.to.shared.u64 t, %1; cvt.u32.u64 %0, t; }" : "=r"(a) : "l"(p));
  return a;
}
__device__ __forceinline__ uint32 swz(int row, int c16){
  return (uint32)(row*128 + (((c16) ^ (row & 7)) << 4));
}
__device__ __forceinline__ void ldsm4(uint32* r, uint32 addr){
  asm volatile("ldmatrix.sync.aligned.m8n8.x4.shared.b16 {%0,%1,%2,%3}, [%4];"
    : "=r"(r[0]),"=r"(r[1]),"=r"(r[2]),"=r"(r[3]) : "r"(addr));
}
__device__ __forceinline__ void mma_f16(float* c, const uint32* a, uint32 b0, uint32 b1){
  asm volatile("mma.sync.aligned.m16n8k16.row.col.f32.f16.f16.f32 "
    "{%0,%1,%2,%3}, {%4,%5,%6,%7}, {%8,%9}, {%0,%1,%2,%3};"
    : "+f"(c[0]),"+f"(c[1]),"+f"(c[2]),"+f"(c[3])
    : "r"(a[0]),"r"(a[1]),"r"(a[2]),"r"(a[3]), "r"(b0),"r"(b1));
}
__device__ __forceinline__ void cpa16(uint32 dst, const void* src){
  asm volatile("cp.async.cg.shared.global [%0], [%1], 16;" :: "r"(dst), "l"(src));
}
#define CPA_COMMIT() asm volatile("cp.async.commit_group;" ::: "memory")
#define CPA_WAIT(n)  asm volatile("cp.async.wait_group %0;" :: "n"(n) : "memory")

union HU { __half h[8]; uint4 u; };

// ---------------- staging -------------------------------------------------------
// B tile via cp.async: 256 rows (N) x 64 (K) fp16
__device__ __forceinline__ void stage_b_async(uint32 dstbase, uint32 baseOff, int Kst,
                                              int kk, int t){
  #pragma unroll
  for (int s=0; s<8; s++){
    int slot = t + s*256;
    int n = slot >> 3, g = slot & 7;
    size_t src = (size_t)baseOff + (size_t)n*Kst + kk + g*8;
    cpa16(dstbase + swz(n, g), (const void*)(g_wt + src));
  }
}

// A tile from fp32 gmem: 128 rows x 64 k, split fp16 hi/lo, zero-pad past M
__device__ __forceinline__ void stage_a(char* smem, uint32 aoff,
                                        const float* __restrict__ A,
                                        int lda, int M, int r0, int kk, int t){
  int r = t >> 1;             // 0..127
  int h32 = (t & 1) * 32;     // col half
  int row = r0 + r;
  bool ok = row < M;
  const float* src = A + (size_t)row*lda + kk + h32;
  #pragma unroll
  for (int g=0; g<4; g++){
    float v[8];
    if (ok){
      float4 a = *(const float4*)(src + g*8);
      float4 b = *(const float4*)(src + g*8 + 4);
      v[0]=a.x; v[1]=a.y; v[2]=a.z; v[3]=a.w; v[4]=b.x; v[5]=b.y; v[6]=b.z; v[7]=b.w;
    } else {
      #pragma unroll
      for (int j=0;j<8;j++) v[j]=0.f;
    }
    HU H, L;
    #pragma unroll
    for (int j=0;j<8;j++){
      H.h[j] = __float2half_rn(v[j]);
      L.h[j] = __float2half_rn(v[j] - __half2float(H.h[j]));
    }
    uint32 dst = swz(r, (h32>>3) + g);
    *(uint4*)(smem + aoff + dst)            = H.u;
    *(uint4*)(smem + aoff + A_LO_OFF + dst) = L.u;
  }
}

// ---------------- warp MMA mainloop: warp tile 32 x 128 -------------------------
__device__ __forceinline__ void compute_chunk(uint32 sb, uint32 aoff, uint32 boff,
                                              int lane, int wm, int wn,
                                              float (&acc)[2][16][4]){
  uint32 rbA[2]; int rxA[2];
  #pragma unroll
  for (int mi=0;mi<2;mi++){
    int row = wm*32 + mi*16 + (lane&15);
    rbA[mi] = sb + aoff + row*128;
    rxA[mi] = row & 7;
  }
  int hi4 = lane>>4;
  uint32 rbB[8]; int rxB[8];
  #pragma unroll
  for (int g=0; g<8; g++){
    int n = wn*128 + g*16 + ((lane>>4)<<3) + (lane&7);
    rbB[g] = sb + boff + n*128;
    rxB[g] = n & 7;
  }
  int cB = (lane>>3)&1;
  #pragma unroll
  for (int ks=0; ks<4; ks++){
    int c16 = ks*2;
    uint32 Ah[2][4], Al[2][4];
    #pragma unroll
    for (int mi=0;mi<2;mi++){
      uint32 off = ((uint32)((c16 + hi4) ^ rxA[mi])) << 4;
      ldsm4(Ah[mi], rbA[mi] + off);
      ldsm4(Al[mi], rbA[mi] + A_LO_OFF + off);
    }
    #pragma unroll
    for (int gp=0; gp<2; gp++){
      uint32 Bh[4][4];
      #pragma unroll
      for (int gg=0; gg<4; gg++){
        int g = gp*4+gg;
        uint32 off = ((uint32)((c16 + cB) ^ rxB[g])) << 4;
        ldsm4(Bh[gg], rbB[g] + off);
      }
      #pragma unroll
      for (int mi=0;mi<2;mi++){
        #pragma unroll
        for (int nn=0;nn<8;nn++){
          int ni = gp*8+nn;
          uint32 b0 = Bh[nn>>1][(nn&1)*2], b1 = Bh[nn>>1][(nn&1)*2+1];
          mma_f16(acc[mi][ni], Ah[mi], b0, b1);
          mma_f16(acc[mi][ni], Al[mi], b0, b1);
        }
      }
    }
  }
}

__device__ __forceinline__ void store_cs(char* smem, int lane, int wm, int wn,
                                         float (&acc)[2][16][4]){
  float* Cs = (float*)smem;
  #pragma unroll
  for (int mi=0;mi<2;mi++){
    int r = wm*32 + mi*16 + (lane>>2);
    #pragma unroll
    for (int ni=0;ni<16;ni++){
      int c = wn*128 + ni*8 + (lane&3)*2;
      *(float2*)(Cs + r*CSTR + c)     = make_float2(acc[mi][ni][0], acc[mi][ni][1]);
      *(float2*)(Cs + (r+8)*CSTR + c) = make_float2(acc[mi][ni][2], acc[mi][ni][3]);
    }
  }
}

#define ZERO_ACC(acc) { \
  _Pragma("unroll") for (int _a=0;_a<2;_a++) \
    _Pragma("unroll") for (int _b=0;_b<16;_b++) \
      _Pragma("unroll") for (int _c=0;_c<4;_c++) (acc)[_a][_b][_c]=0.f; }

// ---------------- CSR build -----------------------------------------------------
__global__ void k_zero(){
  int i = blockIdx.x*256+threadIdx.x;
  if (i<N_) g_cnt[i]=0;
}
__global__ void k_count(const int* __restrict__ ei){
  int e = blockIdx.x*256+threadIdx.x;
  if (e<E_) atomicAdd(&g_cnt[ei[E_+e]], 1);
}
__global__ void k_scan(){
  __shared__ int sh[1024];
  int t = threadIdx.x;
  int base = t*10;
  int loc[10]; int run=0;
  #pragma unroll
  for (int i=0;i<10;i++){ int idx=base+i; int v=(idx<N_)? g_cnt[idx]:0; loc[i]=run; run+=v; }
  sh[t]=run; __syncthreads();
  for (int off=1; off<1024; off<<=1){
    int v = (t>=off)? sh[t-off] : 0;
    __syncthreads();
    sh[t] += v;
    __syncthreads();
  }
  int pre = (t>0)? sh[t-1] : 0;
  #pragma unroll
  for (int i=0;i<10;i++){ int idx=base+i; if (idx<N_){ int p=pre+loc[i]; g_rowptr[idx]=p; g_cur[idx]=p; } }
  if (t==1023) g_rowptr[N_] = sh[1023];
}
__global__ void k_scatter(const int* __restrict__ ei){
  int e = blockIdx.x*256+threadIdx.x;
  if (e<E_){
    int d = ei[E_+e];
    int p = atomicAdd(&g_cur[d], 1);
    g_perm[p] = e;
  }
}

// ---------------- weight transpose + fp16 -----------------------------------
__global__ void k_prep_w(const float* __restrict__ W, int K, int N, uint32 off){
  __shared__ float tile[32][33];
  int k0 = blockIdx.x*32, n0 = blockIdx.y*32;
  int tx = threadIdx.x, ty = threadIdx.y;   // 32 x 8
  #pragma unroll
  for (int i=0;i<4;i++)
    tile[ty+i*8][tx] = W[(size_t)(k0+ty+i*8)*N + n0 + tx];
  __syncthreads();
  #pragma unroll
  for (int i=0;i<4;i++){
    int n = n0 + ty + i*8, k = k0 + tx;
    g_wt[(size_t)off + (size_t)n*K + k] = __float2half_rn(tile[tx][ty+i*8]);
  }
}

// ---------------- QKV GEMMs (blockIdx.y picks set) ------------------------------
__global__ void __launch_bounds__(256,1) k_mm_qkv(
    const float* __restrict__ x,
    const float* __restrict__ bq, const float* __restrict__ bk,
    const float* __restrict__ bv){
  extern __shared__ char smem[];
  uint32 sb = smem_to_u32(smem);
  int t = threadIdx.x, lane = t&31, wid = t>>5;
  int wm = wid>>1, wn = wid&1;
  int r0 = blockIdx.x*128;
  uint32 wbase; const float* bias; float* C;
  if (blockIdx.y==0){ wbase=OFF_Q; bias=bq; C=g_Q; }
  else if (blockIdx.y==1){ wbase=OFF_K; bias=bk; C=g_K; }
  else { wbase=OFF_V; bias=bv; C=g_V; }
  float* s_bias = (float*)(smem + SM_PAR);
  s_bias[t] = bias[t];

  float acc[2][16][4];
  ZERO_ACC(acc);

  stage_a(smem, SM_A0, x, 256, N_, r0, 0, t);
  stage_b_async(sb + SM_B0, wbase, 256, 0, t);
  CPA_COMMIT();
  #pragma unroll
  for (int ck=0; ck<4; ck++){
    if (ck<3){
      uint32 ao = (ck&1)? SM_A0 : SM_A1;
      uint32 bo = (ck&1)? SM_B0 : SM_B1;
      stage_a(smem, ao, x, 256, N_, r0, (ck+1)*64, t);
      stage_b_async(sb + bo, wbase, 256, (ck+1)*64, t);
      CPA_COMMIT();
      CPA_WAIT(1);
    } else {
      CPA_WAIT(0);
    }
    __syncthreads();
    compute_chunk(sb, (ck&1)? SM_A1:SM_A0, (ck&1)? SM_B1:SM_B0, lane, wm, wn, acc);
    __syncthreads();
  }
  store_cs(smem, lane, wm, wn, acc);
  __syncthreads();

  float* Cs = (float*)smem;
  #pragma unroll
  for (int p=0;p<16;p++){
    int r = p*8 + wid;
    int row = r0 + r;
    if (row < N_){
      float4 v0 = *(float4*)(Cs + r*CSTR + lane*8);
      float4 v1 = *(float4*)(Cs + r*CSTR + lane*8 + 4);
      v0.x += s_bias[lane*8+0]; v0.y += s_bias[lane*8+1];
      v0.z += s_bias[lane*8+2]; v0.w += s_bias[lane*8+3];
      v1.x += s_bias[lane*8+4]; v1.y += s_bias[lane*8+5];
      v1.z += s_bias[lane*8+6]; v1.w += s_bias[lane*8+7];
      *(float4*)(C + (size_t)row*256 + lane*8)     = v0;
      *(float4*)(C + (size_t)row*256 + lane*8 + 4) = v1;
    }
  }
}

// ---------------- edge: pe-MLP GEMM + LN + scores -------------------------------
__global__ void __launch_bounds__(256,1) k_mm_edge(
    const float* __restrict__ pos, const int* __restrict__ ei,
    const float* __restrict__ Wp1, const float* __restrict__ bp1,
    const float* __restrict__ bp2, const float* __restrict__ gp,
    const float* __restrict__ bpn){
  extern __shared__ char smem[];
  uint32 sb = smem_to_u32(smem);
  int t = threadIdx.x, lane = t&31, wid = t>>5;
  int wm = wid>>1, wn = wid&1;
  int e0 = blockIdx.x*128;

  float* s_w1 = (float*)(smem + SM_PAR);  // 768
  float* s_b1 = s_w1 + 768;               // 256
  float* s_p2 = s_b1 + 256;               // 256
  float* s_gp = s_p2 + 256;               // 256
  float* s_bn = s_gp + 256;               // 256
  float* s_dp = s_bn + 256;               // 128*3
  int*   s_nd = (int*)(s_dp + 384);       // 256

  s_w1[t]     = Wp1[t];
  s_w1[256+t] = Wp1[256+t];
  s_w1[512+t] = Wp1[512+t];
  s_b1[t] = bp1[t]; s_p2[t] = bp2[t]; s_gp[t] = gp[t]; s_bn[t] = bpn[t];
  if (t < 128){
    int e = e0 + t;
    int sn = ei[e], dn = ei[E_+e];
    s_nd[t] = sn; s_nd[128+t] = dn;
    s_dp[t*3+0] = pos[dn*3+0]-pos[sn*3+0];
    s_dp[t*3+1] = pos[dn*3+1]-pos[sn*3+1];
    s_dp[t*3+2] = pos[dn*3+2]-pos[sn*3+2];
  }
  __syncthreads();

  int rr = t>>1;
  int h32 = (t&1)*32;
  float dx = s_dp[rr*3+0], dy = s_dp[rr*3+1], dz = s_dp[rr*3+2];

  float acc[2][16][4];
  ZERO_ACC(acc);

  // A-tile generator: h = relu(dp @ Wp1 + bp1), split fp16 hi/lo
  auto gen_a = [&](uint32 aoff, int kk){
    #pragma unroll
    for (int g=0; g<4; g++){
      HU H, L;
      #pragma unroll
      for (int j=0; j<8; j++){
        int c = kk + h32 + g*8 + j;
        float v = fmaf(dz, s_w1[512+c], fmaf(dy, s_w1[256+c], fmaf(dx, s_w1[c], s_b1[c])));
        v = fmaxf(v, 0.f);
        H.h[j] = __float2half_rn(v);
        L.h[j] = __float2half_rn(v - __half2float(H.h[j]));
      }
      uint32 dst = swz(rr, (h32>>3) + g);
      *(uint4*)(smem + aoff + dst)            = H.u;
      *(uint4*)(smem + aoff + A_LO_OFF + dst) = L.u;
    }
  };

  gen_a(SM_A0, 0);
  stage_b_async(sb + SM_B0, OFF_P2, 256, 0, t);
  CPA_COMMIT();
  #pragma unroll
  for (int ck=0; ck<4; ck++){
    if (ck<3){
      gen_a((ck&1)? SM_A0 : SM_A1, (ck+1)*64);
      stage_b_async(sb + ((ck&1)? SM_B0 : SM_B1), OFF_P2, 256, (ck+1)*64, t);
      CPA_COMMIT();
      CPA_WAIT(1);
    } else {
      CPA_WAIT(0);
    }
    __syncthreads();
    compute_chunk(sb, (ck&1)? SM_A1:SM_A0, (ck&1)? SM_B1:SM_B0, lane, wm, wn, acc);
    __syncthreads();
  }
  store_cs(smem, lane, wm, wn, acc);
  __syncthreads();

  float* Cs = (float*)smem;
  const float SC = 0.17677669529663688f;  // 1/sqrt(32)
  #pragma unroll
  for (int p=0;p<16;p++){
    int r = p*8 + wid;
    int e = e0 + r;
    float vals[8];
    float s1=0.f, s2=0.f;
    #pragma unroll
    for (int j=0;j<8;j++){
      vals[j] = Cs[r*CSTR + lane*8 + j] + s_p2[lane*8+j];
      s1 += vals[j]; s2 = fmaf(vals[j], vals[j], s2);
    }
    #pragma unroll
    for (int o=16;o>0;o>>=1){
      s1 += __shfl_xor_sync(0xffffffffu, s1, o);
      s2 += __shfl_xor_sync(0xffffffffu, s2, o);
    }
    float m = s1*(1.f/256.f);
    float rstd = rsqrtf(fmaxf(s2*(1.f/256.f) - m*m, 0.f) + 1e-5f);
    int sn = s_nd[r], dn = s_nd[128+r];
    const float* Qp = g_Q + (size_t)dn*256 + lane*8;
    const float* Kp = g_K + (size_t)sn*256 + lane*8;
    float4 q0 = *(const float4*)(Qp), q1 = *(const float4*)(Qp+4);
    float4 k0 = *(const float4*)(Kp), k1 = *(const float4*)(Kp+4);
    float qa[8] = {q0.x,q0.y,q0.z,q0.w,q1.x,q1.y,q1.z,q1.w};
    float ka[8] = {k0.x,k0.y,k0.z,k0.w,k1.x,k1.y,k1.z,k1.w};
    float partial = 0.f;
    #pragma unroll
    for (int j=0;j<8;j++){
      float pe = (vals[j]-m)*rstd*s_gp[lane*8+j] + s_bn[lane*8+j];
      partial = fmaf(qa[j], ka[j] + pe, partial);
    }
    partial += __shfl_xor_sync(0xffffffffu, partial, 1);
    partial += __shfl_xor_sync(0xffffffffu, partial, 2);
    if ((lane&3)==0)
      g_score[(size_t)e*8 + (lane>>2)] = partial*SC;
  }
}

// ---------------- segment softmax + weighted aggregation ------------------------
__global__ void __launch_bounds__(256) k_aggr(const int* __restrict__ ei){
  int n = blockIdx.x;
  int beg = g_rowptr[n], end = g_rowptr[n+1];
  int t = threadIdx.x, lane = t&31, w = t>>5;
  __shared__ float s_mx[8], s_rs[8];
  __shared__ float s_at[128*8];
  __shared__ int   s_sc[128];

  {
    int h = w;
    float mx = -3.0e38f;
    for (int i=beg+lane; i<end; i+=32)
      mx = fmaxf(mx, g_score[(size_t)g_perm[i]*8+h]);
    #pragma unroll
    for (int o=16;o>0;o>>=1) mx = fmaxf(mx, __shfl_xor_sync(0xffffffffu, mx, o));
    float s=0.f;
    for (int i=beg+lane; i<end; i+=32)
      s += __expf(g_score[(size_t)g_perm[i]*8+h]-mx);
    #pragma unroll
    for (int o=16;o>0;o>>=1) s += __shfl_xor_sync(0xffffffffu, s, o);
    if (lane==0){ s_mx[h]=mx; s_rs[h]=1.f/(s+1e-16f); }
  }
  __syncthreads();

  float acc=0.f;
  int h = t>>5;
  for (int c0=beg; c0<end; c0+=128){
    int cn = min(128, end-c0);
    for (int j=t; j<cn*8; j+=256){
      int i=j>>3, hh=j&7;
      int e = g_perm[c0+i];
      s_at[i*8+hh] = __expf(g_score[(size_t)e*8+hh]-s_mx[hh])*s_rs[hh];
      if (hh==0) s_sc[i] = ei[e];
    }
    __syncthreads();
    for (int i=0;i<cn;i++)
      acc = fmaf(s_at[i*8+h], g_V[(size_t)s_sc[i]*256 + t], acc);
    __syncthreads();
  }
  g_aggr[(size_t)n*256+t]=acc;
}

// ---------------- GEMM + LN (Wo and FFN2) ---------------------------------------
__global__ void __launch_bounds__(256,1) k_mm_ln(int mode,
    const float* __restrict__ bias, const float* __restrict__ resx,
    const float* __restrict__ gam, const float* __restrict__ bet,
    float* __restrict__ outp){
  extern __shared__ char smem[];
  uint32 sb = smem_to_u32(smem);
  int t = threadIdx.x, lane = t&31, wid = t>>5;
  int wm = wid>>1, wn = wid&1;
  int r0 = blockIdx.x*128;
  const float* A; const float* res; float* C; int K; uint32 wbase;
  if (mode==0){ A=g_aggr; res=resx; C=g_x1; K=256;  wbase=OFF_O; }
  else        { A=g_ffn;  res=g_x1; C=outp; K=1024; wbase=OFF_F2; }

  float* s_bias = (float*)(smem + SM_PAR);
  float* s_g    = s_bias + 256;
  float* s_b    = s_g + 256;
  s_bias[t] = bias[t]; s_g[t] = gam[t]; s_b[t] = bet[t];

  float acc[2][16][4];
  ZERO_ACC(acc);

  int nchunks = K/64;
  stage_a(smem, SM_A0, A, K, N_, r0, 0, t);
  stage_b_async(sb + SM_B0, wbase, K, 0, t);
  CPA_COMMIT();
  for (int ck=0; ck<nchunks; ck++){
    if (ck+1 < nchunks){
      uint32 ao = (ck&1)? SM_A0 : SM_A1;
      uint32 bo = (ck&1)? SM_B0 : SM_B1;
      stage_a(smem, ao, A, K, N_, r0, (ck+1)*64, t);
      stage_b_async(sb + bo, wbase, K, (ck+1)*64, t);
      CPA_COMMIT();
      CPA_WAIT(1);
    } else {
      CPA_WAIT(0);
    }
    __syncthreads();
    compute_chunk(sb, (ck&1)? SM_A1:SM_A0, (ck&1)? SM_B1:SM_B0, lane, wm, wn, acc);
    __syncthreads();
  }
  store_cs(smem, lane, wm, wn, acc);
  __syncthreads();

  float* Cs = (float*)smem;
  #pragma unroll
  for (int p=0;p<16;p++){
    int r = p*8 + wid;
    int row = r0 + r;
    if (row < N_){
      float4 r0v = *(const float4*)(res + (size_t)row*256 + lane*8);
      float4 r1v = *(const float4*)(res + (size_t)row*256 + lane*8 + 4);
      float vals[8];
      vals[0] = Cs[r*CSTR+lane*8+0] + s_bias[lane*8+0] + r0v.x;
      vals[1] = Cs[r*CSTR+lane*8+1] + s_bias[lane*8+1] + r0v.y;
      vals[2] = Cs[r*CSTR+lane*8+2] + s_bias[lane*8+2] + r0v.z;
      vals[3] = Cs[r*CSTR+lane*8+3] + s_bias[lane*8+3] + r0v.w;
      vals[4] = Cs[r*CSTR+lane*8+4] + s_bias[lane*8+4] + r1v.x;
      vals[5] = Cs[r*CSTR+lane*8+5] + s_bias[lane*8+5] + r1v.y;
      vals[6] = Cs[r*CSTR+lane*8+6] + s_bias[lane*8+6] + r1v.z;
      vals[7] = Cs[r*CSTR+lane*8+7] + s_bias[lane*8+7] + r1v.w;
      float s1=0.f, s2=0.f;
      #pragma unroll
      for (int j=0;j<8;j++){ s1 += vals[j]; s2 = fmaf(vals[j], vals[j], s2); }
      #pragma unroll
      for (int o=16;o>0;o>>=1){
        s1 += __shfl_xor_sync(0xffffffffu, s1, o);
        s2 += __shfl_xor_sync(0xffffffffu, s2, o);
      }
      float m = s1*(1.f/256.f);
      float rstd = rsqrtf(fmaxf(s2*(1.f/256.f) - m*m, 0.f) + 1e-5f);
      float4 o0, o1;
      o0.x = (vals[0]-m)*rstd*s_g[lane*8+0] + s_b[lane*8+0];
      o0.y = (vals[1]-m)*rstd*s_g[lane*8+1] + s_b[lane*8+1];
      o0.z = (vals[2]-m)*rstd*s_g[lane*8+2] + s_b[lane*8+2];
      o0.w = (vals[3]-m)*rstd*s_g[lane*8+3] + s_b[lane*8+3];
      o1.x = (vals[4]-m)*rstd*s_g[lane*8+4] + s_b[lane*8+4];
      o1.y = (vals[5]-m)*rstd*s_g[lane*8+5] + s_b[lane*8+5];
      o1.z = (vals[6]-m)*rstd*s_g[lane*8+6] + s_b[lane*8+6];
      o1.w = (vals[7]-m)*rstd*s_g[lane*8+7] + s_b[lane*8+7];
      *(float4*)(C + (size_t)row*256 + lane*8)     = o0;
      *(float4*)(C + (size_t)row*256 + lane*8 + 4) = o1;
    }
  }
}

// ---------------- FFN1 (relu), N=1024 via col tiles ------------------------------
__global__ void __launch_bounds__(256,1) k_mm_ffn1(const float* __restrict__ bf1){
  extern __shared__ char smem[];
  uint32 sb = smem_to_u32(smem);
  int t = threadIdx.x, lane = t&31, wid = t>>5;
  int wm = wid>>1, wn = wid&1;
  int r0 = blockIdx.x*128;
  int colOff = blockIdx.y*256;
  uint32 wbase = OFF_F1 + (uint32)colOff*256;

  float* s_bias = (float*)(smem + SM_PAR);
  s_bias[t] = bf1[colOff + t];

  float acc[2][16][4];
  ZERO_ACC(acc);

  stage_a(smem, SM_A0, g_x1, 256, N_, r0, 0, t);
  stage_b_async(sb + SM_B0, wbase, 256, 0, t);
  CPA_COMMIT();
  #pragma unroll
  for (int ck=0; ck<4; ck++){
    if (ck<3){
      uint32 ao = (ck&1)? SM_A0 : SM_A1;
      uint32 bo = (ck&1)? SM_B0 : SM_B1;
      stage_a(smem, ao, g_x1, 256, N_, r0, (ck+1)*64, t);
      stage_b_async(sb + bo, wbase, 256, (ck+1)*64, t);
      CPA_COMMIT();
      CPA_WAIT(1);
    } else {
      CPA_WAIT(0);
    }
    __syncthreads();
    compute_chunk(sb, (ck&1)? SM_A1:SM_A0, (ck&1)? SM_B1:SM_B0, lane, wm, wn, acc);
    __syncthreads();
  }
  store_cs(smem, lane, wm, wn, acc);
  __syncthreads();

  float* Cs = (float*)smem;
  #pragma unroll
  for (int p=0;p<16;p++){
    int r = p*8 + wid;
    int row = r0 + r;
    if (row < N_){
      float4 v0, v1;
      v0.x = fmaxf(Cs[r*CSTR+lane*8+0] + s_bias[lane*8+0], 0.f);
      v0.y = fmaxf(Cs[r*CSTR+lane*8+1] + s_bias[lane*8+1], 0.f);
      v0.z = fmaxf(Cs[r*CSTR+lane*8+2] + s_bias[lane*8+2], 0.f);
      v0.w = fmaxf(Cs[r*CSTR+lane*8+3] + s_bias[lane*8+3], 0.f);
      v1.x = fmaxf(Cs[r*CSTR+lane*8+4] + s_bias[lane*8+4], 0.f);
      v1.y = fmaxf(Cs[r*CSTR+lane*8+5] + s_bias[lane*8+5], 0.f);
      v1.z = fmaxf(Cs[r*CSTR+lane*8+6] + s_bias[lane*8+6], 0.f);
      v1.w = fmaxf(Cs[r*CSTR+lane*8+7] + s_bias[lane*8+7], 0.f);
      *(float4*)(g_ffn + (size_t)row*1024 + colOff + lane*8)     = v0;
      *(float4*)(g_ffn + (size_t)row*1024 + colOff + lane*8 + 4) = v1;
    }
  }
}

// ---------------- launch ---------------------------------------------------------
extern "C" void kernel_launch(void* const* d_in, const int* in_sizes, int n_in,
                              void* d_out, int out_size){
  const float* x    = (const float*)d_in[0];
  const float* pos  = (const float*)d_in[1];
  const int*   ei   = (const int*)  d_in[2];
  const float* Wq   = (const float*)d_in[3];
  const float* bq   = (const float*)d_in[4];
  const float* Wk   = (const float*)d_in[5];
  const float* bk   = (const float*)d_in[6];
  const float* Wv   = (const float*)d_in[7];
  const float* bv   = (const float*)d_in[8];
  const float* Wp1  = (const float*)d_in[9];
  const float* bp1  = (const float*)d_in[10];
  const float* Wp2  = (const float*)d_in[11];
  const float* bp2  = (const float*)d_in[12];
  const float* gp   = (const float*)d_in[13];
  const float* bp   = (const float*)d_in[14];
  const float* Wo   = (const float*)d_in[15];
  const float* bo   = (const float*)d_in[16];
  const float* g1   = (const float*)d_in[17];
  const float* b1n  = (const float*)d_in[18];
  const float* Wf1  = (const float*)d_in[19];
  const float* bf1  = (const float*)d_in[20];
  const float* Wf2  = (const float*)d_in[21];
  const float* bf2  = (const float*)d_in[22];
  const float* g2   = (const float*)d_in[23];
  const float* b2n  = (const float*)d_in[24];
  float* out = (float*)d_out;

  cudaFuncSetAttribute(k_mm_qkv,  cudaFuncAttributeMaxDynamicSharedMemorySize, SMEM_DYN);
  cudaFuncSetAttribute(k_mm_edge, cudaFuncAttributeMaxDynamicSharedMemorySize, SMEM_DYN);
  cudaFuncSetAttribute(k_mm_ln,   cudaFuncAttributeMaxDynamicSharedMemorySize, SMEM_DYN);
  cudaFuncSetAttribute(k_mm_ffn1, cudaFuncAttributeMaxDynamicSharedMemorySize, SMEM_DYN);

  const int MT = (N_ + 127) / 128;   // 79
  const int ET = E_ / 128;           // 1250

  // CSR build
  k_zero   <<<(N_+255)/256, 256>>>();
  k_count  <<<(E_+255)/256, 256>>>(ei);
  k_scan   <<<1, 1024>>>();
  k_scatter<<<(E_+255)/256, 256>>>(ei);

  // weight transpose + fp16
  k_prep_w<<<dim3(8,8),  dim3(32,8)>>>(Wq,  256, 256,  OFF_Q);
  k_prep_w<<<dim3(8,8),  dim3(32,8)>>>(Wk,  256, 256,  OFF_K);
  k_prep_w<<<dim3(8,8),  dim3(32,8)>>>(Wv,  256, 256,  OFF_V);
  k_prep_w<<<dim3(8,8),  dim3(32,8)>>>(Wp2, 256, 256,  OFF_P2);
  k_prep_w<<<dim3(8,8),  dim3(32,8)>>>(Wo,  256, 256,  OFF_O);
  k_prep_w<<<dim3(8,32), dim3(32,8)>>>(Wf1, 256, 1024, OFF_F1);
  k_prep_w<<<dim3(32,8), dim3(32,8)>>>(Wf2, 1024, 256, OFF_F2);

  // Q/K/V
  k_mm_qkv<<<dim3(MT,3), 256, SMEM_DYN>>>(x, bq, bk, bv);

  // edge: pe-MLP GEMM + LN + scores
  k_mm_edge<<<ET, 256, SMEM_DYN>>>(pos, ei, Wp1, bp1, bp2, gp, bp);

  // segment softmax + aggregation
  k_aggr<<<N_, 256>>>(ei);

  // x1 = LN(aggr@Wo + bo + x)
  k_mm_ln<<<MT, 256, SMEM_DYN>>>(0, bo, x, g1, b1n, nullptr);

  // ffn = relu(x1@Wf1 + bf1)
  k_mm_ffn1<<<dim3(MT,4), 256, SMEM_DYN>>>(bf1);

  // out = LN(ffn@Wf2 + bf2 + x1)
  k_mm_ln<<<MT, 256, SMEM_DYN>>>(1, bf2, nullptr, g2, b2n, out);

  (void)in_sizes; (void)n_in; (void)out_size;
}

// round 7
// speedup vs baseline: 3.3301x; 1.3192x over previous
#include <cuda_runtime.h>
#include <cuda_fp16.h>
#include <math.h>

#define N_ 10000
#define NPAD 10112
#define E_ 160000

typedef unsigned int uint32;

// ---------------- device scratch ---------------------------------------------
__device__ __align__(16) float g_Q[N_*256];
__device__ __align__(16) float g_K[N_*256];
__device__ __align__(16) float g_V[N_*256];
__device__ __align__(16) float g_score[E_*8];
__device__ __align__(16) float g_aggr[N_*256];
__device__ __align__(16) float g_x1[N_*256];
__device__ __align__(16) __half g_ffn[NPAD*1024];
__device__ int   g_cnt[N_];
__device__ int   g_rowptr[N_+1];
__device__ int   g_cur[N_];
__device__ int   g_perm[E_];

// transposed weights, [N][K] fp16 (K contiguous)
#define OFF_Q  0u
#define OFF_K  65536u
#define OFF_V  131072u
#define OFF_P2 196608u
#define OFF_O  262144u
#define OFF_F1 327680u      /* [1024][256] */
#define OFF_F2 589824u      /* [256][1024] */
#define WT_TOTAL 851968u
__device__ __align__(16) __half g_wt[WT_TOTAL];

// ---------------- smem layout ---------------------------------------------------
// A bufs: 128 rows x 64 k fp16 = 16K each
// B bufs: 256 rows x 64 k fp16 = 32K each
// C staging (epilogue, reuses bufs): 128 x 264 fp32 = 135168 B
#define SM_A0   0
#define SM_A1   16384
#define SM_B0   32768
#define SM_B1   65536
#define SM_PAR  135424
#define SMEM_DYN 145664
#define CSTR    264

__device__ __forceinline__ uint32 smem_to_u32(const void* p){
  uint32 a;
  asm("{ .reg .u64 t; cvta.to.shared.u64 t, %1; cvt.u32.u64 %0, t; }" : "=r"(a) : "l"(p));
  return a;
}
__device__ __forceinline__ uint32 swz(int row, int c16){
  return (uint32)(row*128 + (((c16) ^ (row & 7)) << 4));
}
__device__ __forceinline__ void ldsm4(uint32* r, uint32 addr){
  asm volatile("ldmatrix.sync.aligned.m8n8.x4.shared.b16 {%0,%1,%2,%3}, [%4];"
    : "=r"(r[0]),"=r"(r[1]),"=r"(r[2]),"=r"(r[3]) : "r"(addr));
}
__device__ __forceinline__ void mma_f16(float* c, const uint32* a, uint32 b0, uint32 b1){
  asm volatile("mma.sync.aligned.m16n8k16.row.col.f32.f16.f16.f32 "
    "{%0,%1,%2,%3}, {%4,%5,%6,%7}, {%8,%9}, {%0,%1,%2,%3};"
    : "+f"(c[0]),"+f"(c[1]),"+f"(c[2]),"+f"(c[3])
    : "r"(a[0]),"r"(a[1]),"r"(a[2]),"r"(a[3]), "r"(b0),"r"(b1));
}
__device__ __forceinline__ void cpa16(uint32 dst, const void* src){
  asm volatile("cp.async.cg.shared.global [%0], [%1], 16;" :: "r"(dst), "l"(src));
}
#define CPA_COMMIT() asm volatile("cp.async.commit_group;" ::: "memory")
#define CPA_WAIT(n)  asm volatile("cp.async.wait_group %0;" :: "n"(n) : "memory")

union HU { __half h[8]; uint4 u; };

// ---------------- staging -------------------------------------------------------
// B tile via cp.async: 256 rows (N) x 64 (K) fp16
__device__ __forceinline__ void stage_b_async(uint32 dstbase, uint32 baseOff, int Kst,
                                              int kk, int t){
  #pragma unroll
  for (int s=0; s<8; s++){
    int slot = t + s*256;
    int n = slot >> 3, g = slot & 7;
    size_t src = (size_t)baseOff + (size_t)n*Kst + kk + g*8;
    cpa16(dstbase + swz(n, g), (const void*)(g_wt + src));
  }
}

// A tile (fp16 source) via cp.async: 128 rows x 64 k
__device__ __forceinline__ void stage_h_async_128(uint32 dstbase, const __half* src0,
                                                  int Kst, int kk, int t){
  #pragma unroll
  for (int s=0; s<4; s++){
    int slot = t + s*256;
    int r = slot >> 3, g = slot & 7;
    cpa16(dstbase + swz(r, g), (const void*)(src0 + (size_t)r*Kst + kk + g*8));
  }
}

// A tile from fp32 gmem: 128 rows x 64 k, round to fp16, zero-pad past M
__device__ __forceinline__ void stage_a(char* smem, uint32 aoff,
                                        const float* __restrict__ A,
                                        int lda, int M, int r0, int kk, int t){
  int r = t >> 1;             // 0..127
  int h32 = (t & 1) * 32;     // col half
  int row = r0 + r;
  bool ok = row < M;
  const float* src = A + (size_t)row*lda + kk + h32;
  #pragma unroll
  for (int g=0; g<4; g++){
    float v[8];
    if (ok){
      float4 a = *(const float4*)(src + g*8);
      float4 b = *(const float4*)(src + g*8 + 4);
      v[0]=a.x; v[1]=a.y; v[2]=a.z; v[3]=a.w; v[4]=b.x; v[5]=b.y; v[6]=b.z; v[7]=b.w;
    } else {
      #pragma unroll
      for (int j=0;j<8;j++) v[j]=0.f;
    }
    HU H;
    #pragma unroll
    for (int j=0;j<8;j++) H.h[j] = __float2half_rn(v[j]);
    *(uint4*)(smem + aoff + swz(r, (h32>>3) + g)) = H.u;
  }
}

// ---------------- warp MMA mainloop: warp tile 32 x 128 -------------------------
__device__ __forceinline__ void compute_chunk(uint32 sb, uint32 aoff, uint32 boff,
                                              int lane, int wm, int wn,
                                              float (&acc)[2][16][4]){
  uint32 rbA[2]; int rxA[2];
  #pragma unroll
  for (int mi=0;mi<2;mi++){
    int row = wm*32 + mi*16 + (lane&15);
    rbA[mi] = sb + aoff + row*128;
    rxA[mi] = row & 7;
  }
  int hi4 = lane>>4;
  uint32 rbB[8]; int rxB[8];
  #pragma unroll
  for (int g=0; g<8; g++){
    int n = wn*128 + g*16 + ((lane>>4)<<3) + (lane&7);
    rbB[g] = sb + boff + n*128;
    rxB[g] = n & 7;
  }
  int cB = (lane>>3)&1;
  #pragma unroll
  for (int ks=0; ks<4; ks++){
    int c16 = ks*2;
    uint32 Ah[2][4];
    #pragma unroll
    for (int mi=0;mi<2;mi++){
      uint32 off = ((uint32)((c16 + hi4) ^ rxA[mi])) << 4;
      ldsm4(Ah[mi], rbA[mi] + off);
    }
    #pragma unroll
    for (int gp=0; gp<2; gp++){
      uint32 Bh[4][4];
      #pragma unroll
      for (int gg=0; gg<4; gg++){
        int g = gp*4+gg;
        uint32 off = ((uint32)((c16 + cB) ^ rxB[g])) << 4;
        ldsm4(Bh[gg], rbB[g] + off);
      }
      #pragma unroll
      for (int mi=0;mi<2;mi++){
        #pragma unroll
        for (int nn=0;nn<8;nn++){
          int ni = gp*8+nn;
          mma_f16(acc[mi][ni], Ah[mi], Bh[nn>>1][(nn&1)*2], Bh[nn>>1][(nn&1)*2+1]);
        }
      }
    }
  }
}

__device__ __forceinline__ void store_cs(char* smem, int lane, int wm, int wn,
                                         float (&acc)[2][16][4]){
  float* Cs = (float*)smem;
  #pragma unroll
  for (int mi=0;mi<2;mi++){
    int r = wm*32 + mi*16 + (lane>>2);
    #pragma unroll
    for (int ni=0;ni<16;ni++){
      int c = wn*128 + ni*8 + (lane&3)*2;
      *(float2*)(Cs + r*CSTR + c)     = make_float2(acc[mi][ni][0], acc[mi][ni][1]);
      *(float2*)(Cs + (r+8)*CSTR + c) = make_float2(acc[mi][ni][2], acc[mi][ni][3]);
    }
  }
}

#define ZERO_ACC(acc) { \
  _Pragma("unroll") for (int _a=0;_a<2;_a++) \
    _Pragma("unroll") for (int _b=0;_b<16;_b++) \
      _Pragma("unroll") for (int _c=0;_c<4;_c++) (acc)[_a][_b][_c]=0.f; }

// ---------------- CSR build -----------------------------------------------------
__global__ void k_zero(){
  int i = blockIdx.x*256+threadIdx.x;
  if (i<N_) g_cnt[i]=0;
}
__global__ void k_count(const int* __restrict__ ei){
  int e = blockIdx.x*256+threadIdx.x;
  if (e<E_) atomicAdd(&g_cnt[ei[E_+e]], 1);
}
__global__ void k_scan(){
  __shared__ int sh[1024];
  int t = threadIdx.x;
  int base = t*10;
  int loc[10]; int run=0;
  #pragma unroll
  for (int i=0;i<10;i++){ int idx=base+i; int v=(idx<N_)? g_cnt[idx]:0; loc[i]=run; run+=v; }
  sh[t]=run; __syncthreads();
  for (int off=1; off<1024; off<<=1){
    int v = (t>=off)? sh[t-off] : 0;
    __syncthreads();
    sh[t] += v;
    __syncthreads();
  }
  int pre = (t>0)? sh[t-1] : 0;
  #pragma unroll
  for (int i=0;i<10;i++){ int idx=base+i; if (idx<N_){ int p=pre+loc[i]; g_rowptr[idx]=p; g_cur[idx]=p; } }
  if (t==1023) g_rowptr[N_] = sh[1023];
}
__global__ void k_scatter(const int* __restrict__ ei){
  int e = blockIdx.x*256+threadIdx.x;
  if (e<E_){
    int d = ei[E_+e];
    int p = atomicAdd(&g_cur[d], 1);
    g_perm[p] = e;
  }
}

// ---------------- weight transpose + fp16 -----------------------------------
__global__ void k_prep_w(const float* __restrict__ W, int K, int N, uint32 off){
  __shared__ float tile[32][33];
  int k0 = blockIdx.x*32, n0 = blockIdx.y*32;
  int tx = threadIdx.x, ty = threadIdx.y;   // 32 x 8
  #pragma unroll
  for (int i=0;i<4;i++)
    tile[ty+i*8][tx] = W[(size_t)(k0+ty+i*8)*N + n0 + tx];
  __syncthreads();
  #pragma unroll
  for (int i=0;i<4;i++){
    int n = n0 + ty + i*8, k = k0 + tx;
    g_wt[(size_t)off + (size_t)n*K + k] = __float2half_rn(tile[tx][ty+i*8]);
  }
}

// ---------------- QKV GEMMs (blockIdx.y picks set) ------------------------------
__global__ void __launch_bounds__(256,1) k_mm_qkv(
    const float* __restrict__ x,
    const float* __restrict__ bq, const float* __restrict__ bk,
    const float* __restrict__ bv){
  extern __shared__ char smem[];
  uint32 sb = smem_to_u32(smem);
  int t = threadIdx.x, lane = t&31, wid = t>>5;
  int wm = wid>>1, wn = wid&1;
  int r0 = blockIdx.x*128;
  uint32 wbase; const float* bias; float* C;
  if (blockIdx.y==0){ wbase=OFF_Q; bias=bq; C=g_Q; }
  else if (blockIdx.y==1){ wbase=OFF_K; bias=bk; C=g_K; }
  else { wbase=OFF_V; bias=bv; C=g_V; }
  float* s_bias = (float*)(smem + SM_PAR);
  s_bias[t] = bias[t];

  float acc[2][16][4];
  ZERO_ACC(acc);

  stage_a(smem, SM_A0, x, 256, N_, r0, 0, t);
  stage_b_async(sb + SM_B0, wbase, 256, 0, t);
  CPA_COMMIT();
  #pragma unroll
  for (int ck=0; ck<4; ck++){
    if (ck<3){
      uint32 ao = (ck&1)? SM_A0 : SM_A1;
      uint32 bo = (ck&1)? SM_B0 : SM_B1;
      stage_a(smem, ao, x, 256, N_, r0, (ck+1)*64, t);
      stage_b_async(sb + bo, wbase, 256, (ck+1)*64, t);
      CPA_COMMIT();
      CPA_WAIT(1);
    } else {
      CPA_WAIT(0);
    }
    __syncthreads();
    compute_chunk(sb, (ck&1)? SM_A1:SM_A0, (ck&1)? SM_B1:SM_B0, lane, wm, wn, acc);
    __syncthreads();
  }
  store_cs(smem, lane, wm, wn, acc);
  __syncthreads();

  float* Cs = (float*)smem;
  #pragma unroll
  for (int p=0;p<16;p++){
    int r = p*8 + wid;
    int row = r0 + r;
    if (row < N_){
      float4 v0 = *(float4*)(Cs + r*CSTR + lane*8);
      float4 v1 = *(float4*)(Cs + r*CSTR + lane*8 + 4);
      v0.x += s_bias[lane*8+0]; v0.y += s_bias[lane*8+1];
      v0.z += s_bias[lane*8+2]; v0.w += s_bias[lane*8+3];
      v1.x += s_bias[lane*8+4]; v1.y += s_bias[lane*8+5];
      v1.z += s_bias[lane*8+6]; v1.w += s_bias[lane*8+7];
      *(float4*)(C + (size_t)row*256 + lane*8)     = v0;
      *(float4*)(C + (size_t)row*256 + lane*8 + 4) = v1;
    }
  }
}

// ---------------- edge: pe-MLP GEMM + LN + scores -------------------------------
__global__ void __launch_bounds__(256,1) k_mm_edge(
    const float* __restrict__ pos, const int* __restrict__ ei,
    const float* __restrict__ Wp1, const float* __restrict__ bp1,
    const float* __restrict__ bp2, const float* __restrict__ gp,
    const float* __restrict__ bpn){
  extern __shared__ char smem[];
  uint32 sb = smem_to_u32(smem);
  int t = threadIdx.x, lane = t&31, wid = t>>5;
  int wm = wid>>1, wn = wid&1;
  int e0 = blockIdx.x*128;

  float* s_w1 = (float*)(smem + SM_PAR);  // 768
  float* s_b1 = s_w1 + 768;               // 256
  float* s_p2 = s_b1 + 256;               // 256
  float* s_gp = s_p2 + 256;               // 256
  float* s_bn = s_gp + 256;               // 256
  float* s_dp = s_bn + 256;               // 128*3
  int*   s_nd = (int*)(s_dp + 384);       // 256

  s_w1[t]     = Wp1[t];
  s_w1[256+t] = Wp1[256+t];
  s_w1[512+t] = Wp1[512+t];
  s_b1[t] = bp1[t]; s_p2[t] = bp2[t]; s_gp[t] = gp[t]; s_bn[t] = bpn[t];
  if (t < 128){
    int e = e0 + t;
    int sn = ei[e], dn = ei[E_+e];
    s_nd[t] = sn; s_nd[128+t] = dn;
    s_dp[t*3+0] = pos[dn*3+0]-pos[sn*3+0];
    s_dp[t*3+1] = pos[dn*3+1]-pos[sn*3+1];
    s_dp[t*3+2] = pos[dn*3+2]-pos[sn*3+2];
  }
  __syncthreads();

  int rr = t>>1;
  int h32 = (t&1)*32;
  float dx = s_dp[rr*3+0], dy = s_dp[rr*3+1], dz = s_dp[rr*3+2];

  float acc[2][16][4];
  ZERO_ACC(acc);

  // A-tile generator: h = relu(dp @ Wp1 + bp1) -> fp16
  auto gen_a = [&](uint32 aoff, int kk){
    #pragma unroll
    for (int g=0; g<4; g++){
      HU H;
      #pragma unroll
      for (int j=0; j<8; j++){
        int c = kk + h32 + g*8 + j;
        float v = fmaf(dz, s_w1[512+c], fmaf(dy, s_w1[256+c], fmaf(dx, s_w1[c], s_b1[c])));
        H.h[j] = __float2half_rn(fmaxf(v, 0.f));
      }
      *(uint4*)(smem + aoff + swz(rr, (h32>>3) + g)) = H.u;
    }
  };

  gen_a(SM_A0, 0);
  stage_b_async(sb + SM_B0, OFF_P2, 256, 0, t);
  CPA_COMMIT();
  #pragma unroll
  for (int ck=0; ck<4; ck++){
    if (ck<3){
      gen_a((ck&1)? SM_A0 : SM_A1, (ck+1)*64);
      stage_b_async(sb + ((ck&1)? SM_B0 : SM_B1), OFF_P2, 256, (ck+1)*64, t);
      CPA_COMMIT();
      CPA_WAIT(1);
    } else {
      CPA_WAIT(0);
    }
    __syncthreads();
    compute_chunk(sb, (ck&1)? SM_A1:SM_A0, (ck&1)? SM_B1:SM_B0, lane, wm, wn, acc);
    __syncthreads();
  }
  store_cs(smem, lane, wm, wn, acc);
  __syncthreads();

  float* Cs = (float*)smem;
  const float SC = 0.17677669529663688f;  // 1/sqrt(32)
  #pragma unroll
  for (int p=0;p<16;p++){
    int r = p*8 + wid;
    int e = e0 + r;
    float vals[8];
    float s1=0.f, s2=0.f;
    #pragma unroll
    for (int j=0;j<8;j++){
      vals[j] = Cs[r*CSTR + lane*8 + j] + s_p2[lane*8+j];
      s1 += vals[j]; s2 = fmaf(vals[j], vals[j], s2);
    }
    #pragma unroll
    for (int o=16;o>0;o>>=1){
      s1 += __shfl_xor_sync(0xffffffffu, s1, o);
      s2 += __shfl_xor_sync(0xffffffffu, s2, o);
    }
    float m = s1*(1.f/256.f);
    float rstd = rsqrtf(fmaxf(s2*(1.f/256.f) - m*m, 0.f) + 1e-5f);
    int sn = s_nd[r], dn = s_nd[128+r];
    const float* Qp = g_Q + (size_t)dn*256 + lane*8;
    const float* Kp = g_K + (size_t)sn*256 + lane*8;
    float4 q0 = *(const float4*)(Qp), q1 = *(const float4*)(Qp+4);
    float4 k0 = *(const float4*)(Kp), k1 = *(const float4*)(Kp+4);
    float qa[8] = {q0.x,q0.y,q0.z,q0.w,q1.x,q1.y,q1.z,q1.w};
    float ka[8] = {k0.x,k0.y,k0.z,k0.w,k1.x,k1.y,k1.z,k1.w};
    float partial = 0.f;
    #pragma unroll
    for (int j=0;j<8;j++){
      float pe = (vals[j]-m)*rstd*s_gp[lane*8+j] + s_bn[lane*8+j];
      partial = fmaf(qa[j], ka[j] + pe, partial);
    }
    partial += __shfl_xor_sync(0xffffffffu, partial, 1);
    partial += __shfl_xor_sync(0xffffffffu, partial, 2);
    if ((lane&3)==0)
      g_score[(size_t)e*8 + (lane>>2)] = partial*SC;
  }
}

// ---------------- segment softmax + weighted aggregation ------------------------
__global__ void __launch_bounds__(256) k_aggr(const int* __restrict__ ei){
  int n = blockIdx.x;
  int beg = g_rowptr[n], end = g_rowptr[n+1];
  int t = threadIdx.x, lane = t&31, w = t>>5;
  __shared__ float s_mx[8], s_rs[8];
  __shared__ float s_at[128*8];
  __shared__ int   s_sc[128];

  {
    int h = w;
    float mx = -3.0e38f;
    for (int i=beg+lane; i<end; i+=32)
      mx = fmaxf(mx, g_score[(size_t)g_perm[i]*8+h]);
    #pragma unroll
    for (int o=16;o>0;o>>=1) mx = fmaxf(mx, __shfl_xor_sync(0xffffffffu, mx, o));
    float s=0.f;
    for (int i=beg+lane; i<end; i+=32)
      s += __expf(g_score[(size_t)g_perm[i]*8+h]-mx);
    #pragma unroll
    for (int o=16;o>0;o>>=1) s += __shfl_xor_sync(0xffffffffu, s, o);
    if (lane==0){ s_mx[h]=mx; s_rs[h]=1.f/(s+1e-16f); }
  }
  __syncthreads();

  float acc=0.f;
  int h = t>>5;
  for (int c0=beg; c0<end; c0+=128){
    int cn = min(128, end-c0);
    for (int j=t; j<cn*8; j+=256){
      int i=j>>3, hh=j&7;
      int e = g_perm[c0+i];
      s_at[i*8+hh] = __expf(g_score[(size_t)e*8+hh]-s_mx[hh])*s_rs[hh];
      if (hh==0) s_sc[i] = ei[e];
    }
    __syncthreads();
    for (int i=0;i<cn;i++)
      acc = fmaf(s_at[i*8+h], g_V[(size_t)s_sc[i]*256 + t], acc);
    __syncthreads();
  }
  g_aggr[(size_t)n*256+t]=acc;
}

// ---------------- GEMM + LN (Wo and FFN2) ---------------------------------------
__global__ void __launch_bounds__(256,1) k_mm_ln(int mode,
    const float* __restrict__ bias, const float* __restrict__ resx,
    const float* __restrict__ gam, const float* __restrict__ bet,
    float* __restrict__ outp){
  extern __shared__ char smem[];
  uint32 sb = smem_to_u32(smem);
  int t = threadIdx.x, lane = t&31, wid = t>>5;
  int wm = wid>>1, wn = wid&1;
  int r0 = blockIdx.x*128;
  const float* res; float* C; int K; uint32 wbase;
  if (mode==0){ res=resx; C=g_x1; K=256;  wbase=OFF_O; }
  else        { res=g_x1; C=outp; K=1024; wbase=OFF_F2; }
  const __half* Ah16 = g_ffn + (size_t)r0*1024;

  float* s_bias = (float*)(smem + SM_PAR);
  float* s_g    = s_bias + 256;
  float* s_b    = s_g + 256;
  s_bias[t] = bias[t]; s_g[t] = gam[t]; s_b[t] = bet[t];

  float acc[2][16][4];
  ZERO_ACC(acc);

  int nchunks = K/64;
  if (mode==0) stage_a(smem, SM_A0, g_aggr, K, N_, r0, 0, t);
  else         stage_h_async_128(sb + SM_A0, Ah16, 1024, 0, t);
  stage_b_async(sb + SM_B0, wbase, K, 0, t);
  CPA_COMMIT();
  for (int ck=0; ck<nchunks; ck++){
    if (ck+1 < nchunks){
      uint32 ao = (ck&1)? SM_A0 : SM_A1;
      uint32 bo = (ck&1)? SM_B0 : SM_B1;
      if (mode==0) stage_a(smem, ao, g_aggr, K, N_, r0, (ck+1)*64, t);
      else         stage_h_async_128(sb + ao, Ah16, 1024, (ck+1)*64, t);
      stage_b_async(sb + bo, wbase, K, (ck+1)*64, t);
      CPA_COMMIT();
      CPA_WAIT(1);
    } else {
      CPA_WAIT(0);
    }
    __syncthreads();
    compute_chunk(sb, (ck&1)? SM_A1:SM_A0, (ck&1)? SM_B1:SM_B0, lane, wm, wn, acc);
    __syncthreads();
  }
  store_cs(smem, lane, wm, wn, acc);
  __syncthreads();

  float* Cs = (float*)smem;
  #pragma unroll
  for (int p=0;p<16;p++){
    int r = p*8 + wid;
    int row = r0 + r;
    if (row < N_){
      float4 r0v = *(const float4*)(res + (size_t)row*256 + lane*8);
      float4 r1v = *(const float4*)(res + (size_t)row*256 + lane*8 + 4);
      float vals[8];
      vals[0] = Cs[r*CSTR+lane*8+0] + s_bias[lane*8+0] + r0v.x;
      vals[1] = Cs[r*CSTR+lane*8+1] + s_bias[lane*8+1] + r0v.y;
      vals[2] = Cs[r*CSTR+lane*8+2] + s_bias[lane*8+2] + r0v.z;
      vals[3] = Cs[r*CSTR+lane*8+3] + s_bias[lane*8+3] + r0v.w;
      vals[4] = Cs[r*CSTR+lane*8+4] + s_bias[lane*8+4] + r1v.x;
      vals[5] = Cs[r*CSTR+lane*8+5] + s_bias[lane*8+5] + r1v.y;
      vals[6] = Cs[r*CSTR+lane*8+6] + s_bias[lane*8+6] + r1v.z;
      vals[7] = Cs[r*CSTR+lane*8+7] + s_bias[lane*8+7] + r1v.w;
      float s1=0.f, s2=0.f;
      #pragma unroll
      for (int j=0;j<8;j++){ s1 += vals[j]; s2 = fmaf(vals[j], vals[j], s2); }
      #pragma unroll
      for (int o=16;o>0;o>>=1){
        s1 += __shfl_xor_sync(0xffffffffu, s1, o);
        s2 += __shfl_xor_sync(0xffffffffu, s2, o);
      }
      float m = s1*(1.f/256.f);
      float rstd = rsqrtf(fmaxf(s2*(1.f/256.f) - m*m, 0.f) + 1e-5f);
      float4 o0, o1;
      o0.x = (vals[0]-m)*rstd*s_g[lane*8+0] + s_b[lane*8+0];
      o0.y = (vals[1]-m)*rstd*s_g[lane*8+1] + s_b[lane*8+1];
      o0.z = (vals[2]-m)*rstd*s_g[lane*8+2] + s_b[lane*8+2];
      o0.w = (vals[3]-m)*rstd*s_g[lane*8+3] + s_b[lane*8+3];
      o1.x = (vals[4]-m)*rstd*s_g[lane*8+4] + s_b[lane*8+4];
      o1.y = (vals[5]-m)*rstd*s_g[lane*8+5] + s_b[lane*8+5];
      o1.z = (vals[6]-m)*rstd*s_g[lane*8+6] + s_b[lane*8+6];
      o1.w = (vals[7]-m)*rstd*s_g[lane*8+7] + s_b[lane*8+7];
      *(float4*)(C + (size_t)row*256 + lane*8)     = o0;
      *(float4*)(C + (size_t)row*256 + lane*8 + 4) = o1;
    }
  }
}

// ---------------- FFN1 (relu), N=1024 via col tiles; fp16 output ----------------
__global__ void __launch_bounds__(256,1) k_mm_ffn1(const float* __restrict__ bf1){
  extern __shared__ char smem[];
  uint32 sb = smem_to_u32(smem);
  int t = threadIdx.x, lane = t&31, wid = t>>5;
  int wm = wid>>1, wn = wid&1;
  int r0 = blockIdx.x*128;
  int colOff = blockIdx.y*256;
  uint32 wbase = OFF_F1 + (uint32)colOff*256;

  float* s_bias = (float*)(smem + SM_PAR);
  s_bias[t] = bf1[colOff + t];

  float acc[2][16][4];
  ZERO_ACC(acc);

  stage_a(smem, SM_A0, g_x1, 256, N_, r0, 0, t);
  stage_b_async(sb + SM_B0, wbase, 256, 0, t);
  CPA_COMMIT();
  #pragma unroll
  for (int ck=0; ck<4; ck++){
    if (ck<3){
      uint32 ao = (ck&1)? SM_A0 : SM_A1;
      uint32 bo = (ck&1)? SM_B0 : SM_B1;
      stage_a(smem, ao, g_x1, 256, N_, r0, (ck+1)*64, t);
      stage_b_async(sb + bo, wbase, 256, (ck+1)*64, t);
      CPA_COMMIT();
      CPA_WAIT(1);
    } else {
      CPA_WAIT(0);
    }
    __syncthreads();
    compute_chunk(sb, (ck&1)? SM_A1:SM_A0, (ck&1)? SM_B1:SM_B0, lane, wm, wn, acc);
    __syncthreads();
  }
  store_cs(smem, lane, wm, wn, acc);
  __syncthreads();

  float* Cs = (float*)smem;
  #pragma unroll
  for (int p=0;p<16;p++){
    int r = p*8 + wid;
    int row = r0 + r;
    if (row < N_){
      HU P;
      #pragma unroll
      for (int j=0;j<8;j++)
        P.h[j] = __float2half_rn(fmaxf(Cs[r*CSTR+lane*8+j] + s_bias[lane*8+j], 0.f));
      *(uint4*)(g_ffn + (size_t)row*1024 + colOff + lane*8) = P.u;
    }
  }
}

// ---------------- launch ---------------------------------------------------------
extern "C" void kernel_launch(void* const* d_in, const int* in_sizes, int n_in,
                              void* d_out, int out_size){
  const float* x    = (const float*)d_in[0];
  const float* pos  = (const float*)d_in[1];
  const int*   ei   = (const int*)  d_in[2];
  const float* Wq   = (const float*)d_in[3];
  const float* bq   = (const float*)d_in[4];
  const float* Wk   = (const float*)d_in[5];
  const float* bk   = (const float*)d_in[6];
  const float* Wv   = (const float*)d_in[7];
  const float* bv   = (const float*)d_in[8];
  const float* Wp1  = (const float*)d_in[9];
  const float* bp1  = (const float*)d_in[10];
  const float* Wp2  = (const float*)d_in[11];
  const float* bp2  = (const float*)d_in[12];
  const float* gp   = (const float*)d_in[13];
  const float* bp   = (const float*)d_in[14];
  const float* Wo   = (const float*)d_in[15];
  const float* bo   = (const float*)d_in[16];
  const float* g1   = (const float*)d_in[17];
  const float* b1n  = (const float*)d_in[18];
  const float* Wf1  = (const float*)d_in[19];
  const float* bf1  = (const float*)d_in[20];
  const float* Wf2  = (const float*)d_in[21];
  const float* bf2  = (const float*)d_in[22];
  const float* g2   = (const float*)d_in[23];
  const float* b2n  = (const float*)d_in[24];
  float* out = (float*)d_out;

  cudaFuncSetAttribute(k_mm_qkv,  cudaFuncAttributeMaxDynamicSharedMemorySize, SMEM_DYN);
  cudaFuncSetAttribute(k_mm_edge, cudaFuncAttributeMaxDynamicSharedMemorySize, SMEM_DYN);
  cudaFuncSetAttribute(k_mm_ln,   cudaFuncAttributeMaxDynamicSharedMemorySize, SMEM_DYN);
  cudaFuncSetAttribute(k_mm_ffn1, cudaFuncAttributeMaxDynamicSharedMemorySize, SMEM_DYN);

  const int MT = (N_ + 127) / 128;   // 79
  const int ET = E_ / 128;           // 1250

  // CSR build
  k_zero   <<<(N_+255)/256, 256>>>();
  k_count  <<<(E_+255)/256, 256>>>(ei);
  k_scan   <<<1, 1024>>>();
  k_scatter<<<(E_+255)/256, 256>>>(ei);

  // weight transpose + fp16
  k_prep_w<<<dim3(8,8),  dim3(32,8)>>>(Wq,  256, 256,  OFF_Q);
  k_prep_w<<<dim3(8,8),  dim3(32,8)>>>(Wk,  256, 256,  OFF_K);
  k_prep_w<<<dim3(8,8),  dim3(32,8)>>>(Wv,  256, 256,  OFF_V);
  k_prep_w<<<dim3(8,8),  dim3(32,8)>>>(Wp2, 256, 256,  OFF_P2);
  k_prep_w<<<dim3(8,8),  dim3(32,8)>>>(Wo,  256, 256,  OFF_O);
  k_prep_w<<<dim3(8,32), dim3(32,8)>>>(Wf1, 256, 1024, OFF_F1);
  k_prep_w<<<dim3(32,8), dim3(32,8)>>>(Wf2, 1024, 256, OFF_F2);

  // Q/K/V
  k_mm_qkv<<<dim3(MT,3), 256, SMEM_DYN>>>(x, bq, bk, bv);

  // edge: pe-MLP GEMM + LN + scores
  k_mm_edge<<<ET, 256, SMEM_DYN>>>(pos, ei, Wp1, bp1, bp2, gp, bp);

  // segment softmax + aggregation
  k_aggr<<<N_, 256>>>(ei);

  // x1 = LN(aggr@Wo + bo + x)
  k_mm_ln<<<MT, 256, SMEM_DYN>>>(0, bo, x, g1, b1n, nullptr);

  // ffn = relu(x1@Wf1 + bf1)  [fp16 out]
  k_mm_ffn1<<<dim3(MT,4), 256, SMEM_DYN>>>(bf1);

  // out = LN(ffn@Wf2 + bf2 + x1)
  k_mm_ln<<<MT, 256, SMEM_DYN>>>(1, bf2, nullptr, g2, b2n, out);

  (void)in_sizes; (void)n_in; (void)out_size;
}

// round 8
// speedup vs baseline: 3.7011x; 1.1114x over previous
#include <cuda_runtime.h>
#include <cuda_fp16.h>
#include <math.h>

#define N_ 10000
#define NPAD 10112
#define E_ 160000

typedef unsigned int uint32;

// ---------------- device scratch ---------------------------------------------
__device__ __align__(16) float g_Q[N_*256];
__device__ __align__(16) float g_K[N_*256];
__device__ __align__(16) float g_V[N_*256];
__device__ __align__(16) float g_score[E_*8];
__device__ __align__(16) float g_x1[N_*256];
__device__ __align__(16) __half g_xh[NPAD*256];
__device__ __align__(16) __half g_aggrh[NPAD*256];
__device__ __align__(16) __half g_x1h[NPAD*256];
__device__ __align__(16) __half g_ffn[NPAD*1024];
__device__ int   g_cnt[N_];
__device__ int   g_rowptr[N_+1];
__device__ int   g_cur[N_];
__device__ int   g_perm[E_];

// transposed weights, [N][K] fp16 (K contiguous)
#define OFF_Q  0u
#define OFF_K  65536u
#define OFF_V  131072u
#define OFF_P2 196608u
#define OFF_O  262144u
#define OFF_F1 327680u      /* [1024][256] */
#define OFF_F2 589824u      /* [256][1024] */
#define WT_TOTAL 851968u
__device__ __align__(16) __half g_wt[WT_TOTAL];

// ---------------- smem layout ---------------------------------------------------
#define SM_A0   0
#define SM_A1   16384
#define SM_B0   32768
#define SM_B1   65536
#define SM_PAR  135424
#define SMEM_DYN 145664
#define CSTR    264

__device__ __forceinline__ uint32 smem_to_u32(const void* p){
  uint32 a;
  asm("{ .reg .u64 t; cvta.to.shared.u64 t, %1; cvt.u32.u64 %0, t; }" : "=r"(a) : "l"(p));
  return a;
}
__device__ __forceinline__ uint32 swz(int row, int c16){
  return (uint32)(row*128 + (((c16) ^ (row & 7)) << 4));
}
__device__ __forceinline__ void ldsm4(uint32* r, uint32 addr){
  asm volatile("ldmatrix.sync.aligned.m8n8.x4.shared.b16 {%0,%1,%2,%3}, [%4];"
    : "=r"(r[0]),"=r"(r[1]),"=r"(r[2]),"=r"(r[3]) : "r"(addr));
}
__device__ __forceinline__ void mma_f16(float* c, const uint32* a, uint32 b0, uint32 b1){
  asm volatile("mma.sync.aligned.m16n8k16.row.col.f32.f16.f16.f32 "
    "{%0,%1,%2,%3}, {%4,%5,%6,%7}, {%8,%9}, {%0,%1,%2,%3};"
    : "+f"(c[0]),"+f"(c[1]),"+f"(c[2]),"+f"(c[3])
    : "r"(a[0]),"r"(a[1]),"r"(a[2]),"r"(a[3]), "r"(b0),"r"(b1));
}
__device__ __forceinline__ void cpa16(uint32 dst, const void* src){
  asm volatile("cp.async.cg.shared.global [%0], [%1], 16;" :: "r"(dst), "l"(src));
}
#define CPA_COMMIT() asm volatile("cp.async.commit_group;" ::: "memory")
#define CPA_WAIT(n)  asm volatile("cp.async.wait_group %0;" :: "n"(n) : "memory")

union HU { __half h[8]; uint4 u; };

// ---------------- staging -------------------------------------------------------
// B tile via cp.async: 256 rows (N) x 64 (K) fp16
__device__ __forceinline__ void stage_b_async(uint32 dstbase, uint32 baseOff, int Kst,
                                              int kk, int t){
  #pragma unroll
  for (int s=0; s<8; s++){
    int slot = t + s*256;
    int n = slot >> 3, g = slot & 7;
    size_t src = (size_t)baseOff + (size_t)n*Kst + kk + g*8;
    cpa16(dstbase + swz(n, g), (const void*)(g_wt + src));
  }
}

// A tile (fp16 source) via cp.async: 128 rows x 64 k
__device__ __forceinline__ void stage_h_async_128(uint32 dstbase, const __half* src0,
                                                  int Kst, int kk, int t){
  #pragma unroll
  for (int s=0; s<4; s++){
    int slot = t + s*256;
    int r = slot >> 3, g = slot & 7;
    cpa16(dstbase + swz(r, g), (const void*)(src0 + (size_t)r*Kst + kk + g*8));
  }
}

// ---------------- warp MMA mainloop: warp tile 32 x 128 -------------------------
__device__ __forceinline__ void compute_chunk(uint32 sb, uint32 aoff, uint32 boff,
                                              int lane, int wm, int wn,
                                              float (&acc)[2][16][4]){
  uint32 rbA[2]; int rxA[2];
  #pragma unroll
  for (int mi=0;mi<2;mi++){
    int row = wm*32 + mi*16 + (lane&15);
    rbA[mi] = sb + aoff + row*128;
    rxA[mi] = row & 7;
  }
  int hi4 = lane>>4;
  uint32 rbB[8]; int rxB[8];
  #pragma unroll
  for (int g=0; g<8; g++){
    int n = wn*128 + g*16 + ((lane>>4)<<3) + (lane&7);
    rbB[g] = sb + boff + n*128;
    rxB[g] = n & 7;
  }
  int cB = (lane>>3)&1;
  #pragma unroll
  for (int ks=0; ks<4; ks++){
    int c16 = ks*2;
    uint32 Ah[2][4];
    #pragma unroll
    for (int mi=0;mi<2;mi++){
      uint32 off = ((uint32)((c16 + hi4) ^ rxA[mi])) << 4;
      ldsm4(Ah[mi], rbA[mi] + off);
    }
    #pragma unroll
    for (int gp=0; gp<2; gp++){
      uint32 Bh[4][4];
      #pragma unroll
      for (int gg=0; gg<4; gg++){
        int g = gp*4+gg;
        uint32 off = ((uint32)((c16 + cB) ^ rxB[g])) << 4;
        ldsm4(Bh[gg], rbB[g] + off);
      }
      #pragma unroll
      for (int mi=0;mi<2;mi++){
        #pragma unroll
        for (int nn=0;nn<8;nn++){
          int ni = gp*8+nn;
          mma_f16(acc[mi][ni], Ah[mi], Bh[nn>>1][(nn&1)*2], Bh[nn>>1][(nn&1)*2+1]);
        }
      }
    }
  }
}

__device__ __forceinline__ void store_cs(char* smem, int lane, int wm, int wn,
                                         float (&acc)[2][16][4]){
  float* Cs = (float*)smem;
  #pragma unroll
  for (int mi=0;mi<2;mi++){
    int r = wm*32 + mi*16 + (lane>>2);
    #pragma unroll
    for (int ni=0;ni<16;ni++){
      int c = wn*128 + ni*8 + (lane&3)*2;
      *(float2*)(Cs + r*CSTR + c)     = make_float2(acc[mi][ni][0], acc[mi][ni][1]);
      *(float2*)(Cs + (r+8)*CSTR + c) = make_float2(acc[mi][ni][2], acc[mi][ni][3]);
    }
  }
}

#define ZERO_ACC(acc) { \
  _Pragma("unroll") for (int _a=0;_a<2;_a++) \
    _Pragma("unroll") for (int _b=0;_b<16;_b++) \
      _Pragma("unroll") for (int _c=0;_c<4;_c++) (acc)[_a][_b][_c]=0.f; }

// ---------------- CSR build -----------------------------------------------------
__global__ void k_count(const int* __restrict__ ei){
  int e = blockIdx.x*256+threadIdx.x;
  if (e<E_) atomicAdd(&g_cnt[ei[E_+e]], 1);
}
__global__ void k_scan(){
  __shared__ int sh[1024];
  int t = threadIdx.x;
  int base = t*10;
  int loc[10]; int run=0;
  #pragma unroll
  for (int i=0;i<10;i++){ int idx=base+i; int v=(idx<N_)? g_cnt[idx]:0; loc[i]=run; run+=v; }
  sh[t]=run; __syncthreads();
  for (int off=1; off<1024; off<<=1){
    int v = (t>=off)? sh[t-off] : 0;
    __syncthreads();
    sh[t] += v;
    __syncthreads();
  }
  int pre = (t>0)? sh[t-1] : 0;
  #pragma unroll
  for (int i=0;i<10;i++){ int idx=base+i; if (idx<N_){ int p=pre+loc[i]; g_rowptr[idx]=p; g_cur[idx]=p; } }
  if (t==1023) g_rowptr[N_] = sh[1023];
}
// scatter + re-zero g_cnt for the next replay (deterministic: each run leaves
// g_cnt zeroed; initial state is zero from module load)
__global__ void k_scatter(const int* __restrict__ ei){
  int e = blockIdx.x*256+threadIdx.x;
  if (e<E_){
    int d = ei[E_+e];
    int p = atomicAdd(&g_cur[d], 1);
    g_perm[p] = e;
  }
  if (e<N_) g_cnt[e]=0;
}

// ---------------- fused prep: 7 weight transposes + x fp16 conversion ----------
// flat block ranges: [0,320) Q/K/V/P2/O (64 each), [320,576) F1, [576,832) F2,
// [832,2082) x conversion
__global__ void k_prep_all(
    const float* __restrict__ Wq, const float* __restrict__ Wk,
    const float* __restrict__ Wv, const float* __restrict__ Wp2,
    const float* __restrict__ Wo, const float* __restrict__ Wf1,
    const float* __restrict__ Wf2, const float* __restrict__ x){
  __shared__ float tile[32][33];
  int bid = blockIdx.x;
  int tx = threadIdx.x, ty = threadIdx.y;   // 32 x 8
  if (bid >= 832){
    // x -> fp16
    int t = ty*32 + tx;
    size_t base = (size_t)(bid-832)*2048 + (size_t)t*8;
    float4 a = *(const float4*)(x + base);
    float4 b = *(const float4*)(x + base + 4);
    HU H;
    H.h[0]=__float2half_rn(a.x); H.h[1]=__float2half_rn(a.y);
    H.h[2]=__float2half_rn(a.z); H.h[3]=__float2half_rn(a.w);
    H.h[4]=__float2half_rn(b.x); H.h[5]=__float2half_rn(b.y);
    H.h[6]=__float2half_rn(b.z); H.h[7]=__float2half_rn(b.w);
    *(uint4*)(g_xh + base) = H.u;
    return;
  }
  const float* W; int K, N; uint32 off; int local;
  if (bid < 320){
    local = bid & 63;
    int w = bid >> 6;
    W = (w==0)?Wq:(w==1)?Wk:(w==2)?Wv:(w==3)?Wp2:Wo;
    K = 256; N = 256; off = (uint32)w*65536u;
  } else if (bid < 576){ local = bid-320; W = Wf1; K = 256;  N = 1024; off = OFF_F1; }
  else                 { local = bid-576; W = Wf2; K = 1024; N = 256;  off = OFF_F2; }
  int nkb = K/32;
  int k0 = (local % nkb)*32, n0 = (local / nkb)*32;
  #pragma unroll
  for (int i=0;i<4;i++)
    tile[ty+i*8][tx] = W[(size_t)(k0+ty+i*8)*N + n0 + tx];
  __syncthreads();
  #pragma unroll
  for (int i=0;i<4;i++){
    int n = n0 + ty + i*8, k = k0 + tx;
    g_wt[(size_t)off + (size_t)n*K + k] = __float2half_rn(tile[tx][ty+i*8]);
  }
}

// ---------------- QKV GEMMs (blockIdx.y picks set) ------------------------------
__global__ void __launch_bounds__(256,1) k_mm_qkv(
    const float* __restrict__ bq, const float* __restrict__ bk,
    const float* __restrict__ bv){
  extern __shared__ char smem[];
  uint32 sb = smem_to_u32(smem);
  int t = threadIdx.x, lane = t&31, wid = t>>5;
  int wm = wid>>1, wn = wid&1;
  int r0 = blockIdx.x*128;
  uint32 wbase; const float* bias; float* C;
  if (blockIdx.y==0){ wbase=OFF_Q; bias=bq; C=g_Q; }
  else if (blockIdx.y==1){ wbase=OFF_K; bias=bk; C=g_K; }
  else { wbase=OFF_V; bias=bv; C=g_V; }
  const __half* Asrc = g_xh + (size_t)r0*256;
  float* s_bias = (float*)(smem + SM_PAR);
  s_bias[t] = bias[t];

  float acc[2][16][4];
  ZERO_ACC(acc);

  stage_h_async_128(sb + SM_A0, Asrc, 256, 0, t);
  stage_b_async(sb + SM_B0, wbase, 256, 0, t);
  CPA_COMMIT();
  #pragma unroll
  for (int ck=0; ck<4; ck++){
    if (ck<3){
      uint32 ao = (ck&1)? SM_A0 : SM_A1;
      uint32 bo = (ck&1)? SM_B0 : SM_B1;
      stage_h_async_128(sb + ao, Asrc, 256, (ck+1)*64, t);
      stage_b_async(sb + bo, wbase, 256, (ck+1)*64, t);
      CPA_COMMIT();
      CPA_WAIT(1);
    } else {
      CPA_WAIT(0);
    }
    __syncthreads();
    compute_chunk(sb, (ck&1)? SM_A1:SM_A0, (ck&1)? SM_B1:SM_B0, lane, wm, wn, acc);
    __syncthreads();
  }
  store_cs(smem, lane, wm, wn, acc);
  __syncthreads();

  float* Cs = (float*)smem;
  #pragma unroll
  for (int p=0;p<16;p++){
    int r = p*8 + wid;
    int row = r0 + r;
    if (row < N_){
      float4 v0 = *(float4*)(Cs + r*CSTR + lane*8);
      float4 v1 = *(float4*)(Cs + r*CSTR + lane*8 + 4);
      v0.x += s_bias[lane*8+0]; v0.y += s_bias[lane*8+1];
      v0.z += s_bias[lane*8+2]; v0.w += s_bias[lane*8+3];
      v1.x += s_bias[lane*8+4]; v1.y += s_bias[lane*8+5];
      v1.z += s_bias[lane*8+6]; v1.w += s_bias[lane*8+7];
      *(float4*)(C + (size_t)row*256 + lane*8)     = v0;
      *(float4*)(C + (size_t)row*256 + lane*8 + 4) = v1;
    }
  }
}

// ---------------- edge: pe-MLP GEMM + LN + scores -------------------------------
__global__ void __launch_bounds__(256,1) k_mm_edge(
    const float* __restrict__ pos, const int* __restrict__ ei,
    const float* __restrict__ Wp1, const float* __restrict__ bp1,
    const float* __restrict__ bp2, const float* __restrict__ gp,
    const float* __restrict__ bpn){
  extern __shared__ char smem[];
  uint32 sb = smem_to_u32(smem);
  int t = threadIdx.x, lane = t&31, wid = t>>5;
  int wm = wid>>1, wn = wid&1;
  int e0 = blockIdx.x*128;

  float* s_w1 = (float*)(smem + SM_PAR);  // 768
  float* s_b1 = s_w1 + 768;               // 256
  float* s_p2 = s_b1 + 256;               // 256
  float* s_gp = s_p2 + 256;               // 256
  float* s_bn = s_gp + 256;               // 256
  float* s_dp = s_bn + 256;               // 128*3
  int*   s_nd = (int*)(s_dp + 384);       // 256

  s_w1[t]     = Wp1[t];
  s_w1[256+t] = Wp1[256+t];
  s_w1[512+t] = Wp1[512+t];
  s_b1[t] = bp1[t]; s_p2[t] = bp2[t]; s_gp[t] = gp[t]; s_bn[t] = bpn[t];
  if (t < 128){
    int e = e0 + t;
    int sn = ei[e], dn = ei[E_+e];
    s_nd[t] = sn; s_nd[128+t] = dn;
    s_dp[t*3+0] = pos[dn*3+0]-pos[sn*3+0];
    s_dp[t*3+1] = pos[dn*3+1]-pos[sn*3+1];
    s_dp[t*3+2] = pos[dn*3+2]-pos[sn*3+2];
  }
  __syncthreads();

  int rr = t>>1;
  int h32 = (t&1)*32;
  float dx = s_dp[rr*3+0], dy = s_dp[rr*3+1], dz = s_dp[rr*3+2];

  float acc[2][16][4];
  ZERO_ACC(acc);

  // A-tile generator: h = relu(dp @ Wp1 + bp1) -> fp16
  auto gen_a = [&](uint32 aoff, int kk){
    #pragma unroll
    for (int g=0; g<4; g++){
      HU H;
      #pragma unroll
      for (int j=0; j<8; j++){
        int c = kk + h32 + g*8 + j;
        float v = fmaf(dz, s_w1[512+c], fmaf(dy, s_w1[256+c], fmaf(dx, s_w1[c], s_b1[c])));
        H.h[j] = __float2half_rn(fmaxf(v, 0.f));
      }
      *(uint4*)(smem + aoff + swz(rr, (h32>>3) + g)) = H.u;
    }
  };

  gen_a(SM_A0, 0);
  stage_b_async(sb + SM_B0, OFF_P2, 256, 0, t);
  CPA_COMMIT();
  #pragma unroll
  for (int ck=0; ck<4; ck++){
    if (ck<3){
      gen_a((ck&1)? SM_A0 : SM_A1, (ck+1)*64);
      stage_b_async(sb + ((ck&1)? SM_B0 : SM_B1), OFF_P2, 256, (ck+1)*64, t);
      CPA_COMMIT();
      CPA_WAIT(1);
    } else {
      CPA_WAIT(0);
    }
    __syncthreads();
    compute_chunk(sb, (ck&1)? SM_A1:SM_A0, (ck&1)? SM_B1:SM_B0, lane, wm, wn, acc);
    __syncthreads();
  }
  store_cs(smem, lane, wm, wn, acc);
  __syncthreads();

  float* Cs = (float*)smem;
  const float SC = 0.17677669529663688f;  // 1/sqrt(32)
  #pragma unroll
  for (int p=0;p<16;p++){
    int r = p*8 + wid;
    int e = e0 + r;
    float vals[8];
    float s1=0.f, s2=0.f;
    #pragma unroll
    for (int j=0;j<8;j++){
      vals[j] = Cs[r*CSTR + lane*8 + j] + s_p2[lane*8+j];
      s1 += vals[j]; s2 = fmaf(vals[j], vals[j], s2);
    }
    #pragma unroll
    for (int o=16;o>0;o>>=1){
      s1 += __shfl_xor_sync(0xffffffffu, s1, o);
      s2 += __shfl_xor_sync(0xffffffffu, s2, o);
    }
    float m = s1*(1.f/256.f);
    float rstd = rsqrtf(fmaxf(s2*(1.f/256.f) - m*m, 0.f) + 1e-5f);
    int sn = s_nd[r], dn = s_nd[128+r];
    const float* Qp = g_Q + (size_t)dn*256 + lane*8;
    const float* Kp = g_K + (size_t)sn*256 + lane*8;
    float4 q0 = *(const float4*)(Qp), q1 = *(const float4*)(Qp+4);
    float4 k0 = *(const float4*)(Kp), k1 = *(const float4*)(Kp+4);
    float qa[8] = {q0.x,q0.y,q0.z,q0.w,q1.x,q1.y,q1.z,q1.w};
    float ka[8] = {k0.x,k0.y,k0.z,k0.w,k1.x,k1.y,k1.z,k1.w};
    float partial = 0.f;
    #pragma unroll
    for (int j=0;j<8;j++){
      float pe = (vals[j]-m)*rstd*s_gp[lane*8+j] + s_bn[lane*8+j];
      partial = fmaf(qa[j], ka[j] + pe, partial);
    }
    partial += __shfl_xor_sync(0xffffffffu, partial, 1);
    partial += __shfl_xor_sync(0xffffffffu, partial, 2);
    if ((lane&3)==0)
      g_score[(size_t)e*8 + (lane>>2)] = partial*SC;
  }
}

// ---------------- segment softmax + weighted aggregation ------------------------
__global__ void __launch_bounds__(256) k_aggr(const int* __restrict__ ei){
  int n = blockIdx.x;
  int beg = g_rowptr[n], end = g_rowptr[n+1];
  int t = threadIdx.x, lane = t&31, w = t>>5;
  __shared__ float s_mx[8], s_rs[8];
  __shared__ float s_at[128*8];
  __shared__ int   s_sc[128];

  {
    int h = w;
    float mx = -3.0e38f;
    for (int i=beg+lane; i<end; i+=32)
      mx = fmaxf(mx, g_score[(size_t)g_perm[i]*8+h]);
    #pragma unroll
    for (int o=16;o>0;o>>=1) mx = fmaxf(mx, __shfl_xor_sync(0xffffffffu, mx, o));
    float s=0.f;
    for (int i=beg+lane; i<end; i+=32)
      s += __expf(g_score[(size_t)g_perm[i]*8+h]-mx);
    #pragma unroll
    for (int o=16;o>0;o>>=1) s += __shfl_xor_sync(0xffffffffu, s, o);
    if (lane==0){ s_mx[h]=mx; s_rs[h]=1.f/(s+1e-16f); }
  }
  __syncthreads();

  float acc=0.f;
  int h = t>>5;
  for (int c0=beg; c0<end; c0+=128){
    int cn = min(128, end-c0);
    for (int j=t; j<cn*8; j+=256){
      int i=j>>3, hh=j&7;
      int e = g_perm[c0+i];
      s_at[i*8+hh] = __expf(g_score[(size_t)e*8+hh]-s_mx[hh])*s_rs[hh];
      if (hh==0) s_sc[i] = ei[e];
    }
    __syncthreads();
    for (int i=0;i<cn;i++)
      acc = fmaf(s_at[i*8+h], g_V[(size_t)s_sc[i]*256 + t], acc);
    __syncthreads();
  }
  g_aggrh[(size_t)n*256+t] = __float2half_rn(acc);
}

// ---------------- GEMM + LN (Wo and FFN2) ---------------------------------------
__global__ void __launch_bounds__(256,1) k_mm_ln(int mode,
    const float* __restrict__ bias, const float* __restrict__ resx,
    const float* __restrict__ gam, const float* __restrict__ bet,
    float* __restrict__ outp){
  extern __shared__ char smem[];
  uint32 sb = smem_to_u32(smem);
  int t = threadIdx.x, lane = t&31, wid = t>>5;
  int wm = wid>>1, wn = wid&1;
  int r0 = blockIdx.x*128;
  const float* res; float* C; int K; uint32 wbase;
  const __half* Asrc; int Kst;
  if (mode==0){
    res=resx; C=g_x1; K=256; wbase=OFF_O;
    Asrc = g_aggrh + (size_t)r0*256; Kst=256;
  } else {
    res=g_x1; C=outp; K=1024; wbase=OFF_F2;
    Asrc = g_ffn + (size_t)r0*1024; Kst=1024;
  }

  float* s_bias = (float*)(smem + SM_PAR);
  float* s_g    = s_bias + 256;
  float* s_b    = s_g + 256;
  s_bias[t] = bias[t]; s_g[t] = gam[t]; s_b[t] = bet[t];

  float acc[2][16][4];
  ZERO_ACC(acc);

  int nchunks = K/64;
  stage_h_async_128(sb + SM_A0, Asrc, Kst, 0, t);
  stage_b_async(sb + SM_B0, wbase, K, 0, t);
  CPA_COMMIT();
  for (int ck=0; ck<nchunks; ck++){
    if (ck+1 < nchunks){
      uint32 ao = (ck&1)? SM_A0 : SM_A1;
      uint32 bo = (ck&1)? SM_B0 : SM_B1;
      stage_h_async_128(sb + ao, Asrc, Kst, (ck+1)*64, t);
      stage_b_async(sb + bo, wbase, K, (ck+1)*64, t);
      CPA_COMMIT();
      CPA_WAIT(1);
    } else {
      CPA_WAIT(0);
    }
    __syncthreads();
    compute_chunk(sb, (ck&1)? SM_A1:SM_A0, (ck&1)? SM_B1:SM_B0, lane, wm, wn, acc);
    __syncthreads();
  }
  store_cs(smem, lane, wm, wn, acc);
  __syncthreads();

  float* Cs = (float*)smem;
  #pragma unroll
  for (int p=0;p<16;p++){
    int r = p*8 + wid;
    int row = r0 + r;
    if (row < N_){
      float4 r0v = *(const float4*)(res + (size_t)row*256 + lane*8);
      float4 r1v = *(const float4*)(res + (size_t)row*256 + lane*8 + 4);
      float vals[8];
      vals[0] = Cs[r*CSTR+lane*8+0] + s_bias[lane*8+0] + r0v.x;
      vals[1] = Cs[r*CSTR+lane*8+1] + s_bias[lane*8+1] + r0v.y;
      vals[2] = Cs[r*CSTR+lane*8+2] + s_bias[lane*8+2] + r0v.z;
      vals[3] = Cs[r*CSTR+lane*8+3] + s_bias[lane*8+3] + r0v.w;
      vals[4] = Cs[r*CSTR+lane*8+4] + s_bias[lane*8+4] + r1v.x;
      vals[5] = Cs[r*CSTR+lane*8+5] + s_bias[lane*8+5] + r1v.y;
      vals[6] = Cs[r*CSTR+lane*8+6] + s_bias[lane*8+6] + r1v.z;
      vals[7] = Cs[r*CSTR+lane*8+7] + s_bias[lane*8+7] + r1v.w;
      float s1=0.f, s2=0.f;
      #pragma unroll
      for (int j=0;j<8;j++){ s1 += vals[j]; s2 = fmaf(vals[j], vals[j], s2); }
      #pragma unroll
      for (int o=16;o>0;o>>=1){
        s1 += __shfl_xor_sync(0xffffffffu, s1, o);
        s2 += __shfl_xor_sync(0xffffffffu, s2, o);
      }
      float m = s1*(1.f/256.f);
      float rstd = rsqrtf(fmaxf(s2*(1.f/256.f) - m*m, 0.f) + 1e-5f);
      float4 o0, o1;
      o0.x = (vals[0]-m)*rstd*s_g[lane*8+0] + s_b[lane*8+0];
      o0.y = (vals[1]-m)*rstd*s_g[lane*8+1] + s_b[lane*8+1];
      o0.z = (vals[2]-m)*rstd*s_g[lane*8+2] + s_b[lane*8+2];
      o0.w = (vals[3]-m)*rstd*s_g[lane*8+3] + s_b[lane*8+3];
      o1.x = (vals[4]-m)*rstd*s_g[lane*8+4] + s_b[lane*8+4];
      o1.y = (vals[5]-m)*rstd*s_g[lane*8+5] + s_b[lane*8+5];
      o1.z = (vals[6]-m)*rstd*s_g[lane*8+6] + s_b[lane*8+6];
      o1.w = (vals[7]-m)*rstd*s_g[lane*8+7] + s_b[lane*8+7];
      *(float4*)(C + (size_t)row*256 + lane*8)     = o0;
      *(float4*)(C + (size_t)row*256 + lane*8 + 4) = o1;
      if (mode==0){
        HU P;
        P.h[0]=__float2half_rn(o0.x); P.h[1]=__float2half_rn(o0.y);
        P.h[2]=__float2half_rn(o0.z); P.h[3]=__float2half_rn(o0.w);
        P.h[4]=__float2half_rn(o1.x); P.h[5]=__float2half_rn(o1.y);
        P.h[6]=__float2half_rn(o1.z); P.h[7]=__float2half_rn(o1.w);
        *(uint4*)(g_x1h + (size_t)row*256 + lane*8) = P.u;
      }
    }
  }
}

// ---------------- FFN1 (relu), N=1024 via col tiles; fp16 output ----------------
__global__ void __launch_bounds__(256,1) k_mm_ffn1(const float* __restrict__ bf1){
  extern __shared__ char smem[];
  uint32 sb = smem_to_u32(smem);
  int t = threadIdx.x, lane = t&31, wid = t>>5;
  int wm = wid>>1, wn = wid&1;
  int r0 = blockIdx.x*128;
  int colOff = blockIdx.y*256;
  uint32 wbase = OFF_F1 + (uint32)colOff*256;
  const __half* Asrc = g_x1h + (size_t)r0*256;

  float* s_bias = (float*)(smem + SM_PAR);
  s_bias[t] = bf1[colOff + t];

  float acc[2][16][4];
  ZERO_ACC(acc);

  stage_h_async_128(sb + SM_A0, Asrc, 256, 0, t);
  stage_b_async(sb + SM_B0, wbase, 256, 0, t);
  CPA_COMMIT();
  #pragma unroll
  for (int ck=0; ck<4; ck++){
    if (ck<3){
      uint32 ao = (ck&1)? SM_A0 : SM_A1;
      uint32 bo = (ck&1)? SM_B0 : SM_B1;
      stage_h_async_128(sb + ao, Asrc, 256, (ck+1)*64, t);
      stage_b_async(sb + bo, wbase, 256, (ck+1)*64, t);
      CPA_COMMIT();
      CPA_WAIT(1);
    } else {
      CPA_WAIT(0);
    }
    __syncthreads();
    compute_chunk(sb, (ck&1)? SM_A1:SM_A0, (ck&1)? SM_B1:SM_B0, lane, wm, wn, acc);
    __syncthreads();
  }
  store_cs(smem, lane, wm, wn, acc);
  __syncthreads();

  float* Cs = (float*)smem;
  #pragma unroll
  for (int p=0;p<16;p++){
    int r = p*8 + wid;
    int row = r0 + r;
    if (row < N_){
      HU P;
      #pragma unroll
      for (int j=0;j<8;j++)
        P.h[j] = __float2half_rn(fmaxf(Cs[r*CSTR+lane*8+j] + s_bias[lane*8+j], 0.f));
      *(uint4*)(g_ffn + (size_t)row*1024 + colOff + lane*8) = P.u;
    }
  }
}

// ---------------- launch ---------------------------------------------------------
extern "C" void kernel_launch(void* const* d_in, const int* in_sizes, int n_in,
                              void* d_out, int out_size){
  const float* x    = (const float*)d_in[0];
  const float* pos  = (const float*)d_in[1];
  const int*   ei   = (const int*)  d_in[2];
  const float* Wq   = (const float*)d_in[3];
  const float* bq   = (const float*)d_in[4];
  const float* Wk   = (const float*)d_in[5];
  const float* bk   = (const float*)d_in[6];
  const float* Wv   = (const float*)d_in[7];
  const float* bv   = (const float*)d_in[8];
  const float* Wp1  = (const float*)d_in[9];
  const float* bp1  = (const float*)d_in[10];
  const float* Wp2  = (const float*)d_in[11];
  const float* bp2  = (const float*)d_in[12];
  const float* gp   = (const float*)d_in[13];
  const float* bp   = (const float*)d_in[14];
  const float* Wo   = (const float*)d_in[15];
  const float* bo   = (const float*)d_in[16];
  const float* g1   = (const float*)d_in[17];
  const float* b1n  = (const float*)d_in[18];
  const float* Wf1  = (const float*)d_in[19];
  const float* bf1  = (const float*)d_in[20];
  const float* Wf2  = (const float*)d_in[21];
  const float* bf2  = (const float*)d_in[22];
  const float* g2   = (const float*)d_in[23];
  const float* b2n  = (const float*)d_in[24];
  float* out = (float*)d_out;

  cudaFuncSetAttribute(k_mm_qkv,  cudaFuncAttributeMaxDynamicSharedMemorySize, SMEM_DYN);
  cudaFuncSetAttribute(k_mm_edge, cudaFuncAttributeMaxDynamicSharedMemorySize, SMEM_DYN);
  cudaFuncSetAttribute(k_mm_ln,   cudaFuncAttributeMaxDynamicSharedMemorySize, SMEM_DYN);
  cudaFuncSetAttribute(k_mm_ffn1, cudaFuncAttributeMaxDynamicSharedMemorySize, SMEM_DYN);

  const int MT = (N_ + 127) / 128;   // 79
  const int ET = E_ / 128;           // 1250

  // CSR build (g_cnt is zeroed by the tail of k_scatter each run)
  k_count  <<<(E_+255)/256, 256>>>(ei);
  k_scan   <<<1, 1024>>>();
  k_scatter<<<(E_+255)/256, 256>>>(ei);

  // fused prep: 7 weight transposes + x->fp16
  k_prep_all<<<2082, dim3(32,8)>>>(Wq, Wk, Wv, Wp2, Wo, Wf1, Wf2, x);

  // Q/K/V
  k_mm_qkv<<<dim3(MT,3), 256, SMEM_DYN>>>(bq, bk, bv);

  // edge: pe-MLP GEMM + LN + scores
  k_mm_edge<<<ET, 256, SMEM_DYN>>>(pos, ei, Wp1, bp1, bp2, gp, bp);

  // segment softmax + aggregation  [fp16 out]
  k_aggr<<<N_, 256>>>(ei);

  // x1 = LN(aggr@Wo + bo + x)  [+ fp16 copy]
  k_mm_ln<<<MT, 256, SMEM_DYN>>>(0, bo, x, g1, b1n, nullptr);

  // ffn = relu(x1@Wf1 + bf1)  [fp16 out]
  k_mm_ffn1<<<dim3(MT,4), 256, SMEM_DYN>>>(bf1);

  // out = LN(ffn@Wf2 + bf2 + x1)
  k_mm_ln<<<MT, 256, SMEM_DYN>>>(1, bf2, nullptr, g2, b2n, out);

  (void)in_sizes; (void)n_in; (void)out_size;
}

// round 9
// speedup vs baseline: 3.8707x; 1.0458x over previous
#include <cuda_runtime.h>
#include <cuda_fp16.h>

#define N_ 10000
#define NPAD 10112
#define E_ 160000

typedef unsigned int uint32;

// ---------------- device scratch ---------------------------------------------
__device__ __align__(16) float g_Q[N_*256];
__device__ __align__(16) float g_K[N_*256];
__device__ __align__(16) float g_V[N_*256];
__device__ __align__(16) float g_score[E_*8];
__device__ __align__(16) float g_x1[N_*256];
__device__ __align__(16) __half g_xh[NPAD*256];
__device__ __align__(16) __half g_aggrh[NPAD*256];
__device__ __align__(16) __half g_x1h[NPAD*256];
__device__ __align__(16) __half g_ffn[NPAD*1024];
__device__ int   g_cnt[N_];
__device__ int   g_rowptr[N_+1];
__device__ int   g_cur[N_];
__device__ int   g_perm[E_];

// transposed weights, [N][K] fp16 (K contiguous)
#define OFF_Q  0u
#define OFF_K  65536u
#define OFF_V  131072u
#define OFF_P2 196608u
#define OFF_O  262144u
#define OFF_F1 327680u      /* [1024][256] */
#define OFF_F2 589824u      /* [256][1024] */
#define WT_TOTAL 851968u
__device__ __align__(16) __half g_wt[WT_TOTAL];

// ---------------- smem layouts ---------------------------------------------------
// QKV/FFN1 (M=128,N=128): A0 0 (16K), A1 16K, B0 32K (16K), B1 48K, PAR 64K
#define Q_A0 0
#define Q_A1 16384
#define Q_B0 32768
#define Q_B1 49152
#define Q_PAR 65536
#define Q_DYN 67584
// LN/EDGE (M=64,N=256): A0 0 (8K), A1 8K, B0 16K (32K), B1 48K, PAR 80K
#define L_A0 0
#define L_A1 8192
#define L_B0 16384
#define L_B1 49152
#define L_PAR 81920
#define L_DYN 94208

__device__ __forceinline__ uint32 smem_to_u32(const void* p){
  uint32 a;
  asm("{ .reg .u64 t; cvta.to.shared.u64 t, %1; cvt.u32.u64 %0, t; }" : "=r"(a) : "l"(p));
  return a;
}
__device__ __forceinline__ uint32 swz(int row, int c16){
  return (uint32)(row*128 + (((c16) ^ (row & 7)) << 4));
}
__device__ __forceinline__ void ldsm4(uint32* r, uint32 addr){
  asm volatile("ldmatrix.sync.aligned.m8n8.x4.shared.b16 {%0,%1,%2,%3}, [%4];"
    : "=r"(r[0]),"=r"(r[1]),"=r"(r[2]),"=r"(r[3]) : "r"(addr));
}
__device__ __forceinline__ void mma_f16(float* c, const uint32* a, uint32 b0, uint32 b1){
  asm volatile("mma.sync.aligned.m16n8k16.row.col.f32.f16.f16.f32 "
    "{%0,%1,%2,%3}, {%4,%5,%6,%7}, {%8,%9}, {%0,%1,%2,%3};"
    : "+f"(c[0]),"+f"(c[1]),"+f"(c[2]),"+f"(c[3])
    : "r"(a[0]),"r"(a[1]),"r"(a[2]),"r"(a[3]), "r"(b0),"r"(b1));
}
__device__ __forceinline__ void cpa16(uint32 dst, const void* src){
  asm volatile("cp.async.cg.shared.global [%0], [%1], 16;" :: "r"(dst), "l"(src));
}
#define CPA_COMMIT() asm volatile("cp.async.commit_group;" ::: "memory")
#define CPA_WAIT(n)  asm volatile("cp.async.wait_group %0;" :: "n"(n) : "memory")

union HU { __half h[8]; uint4 u; };

// ---------------- staging: generic fp16 tile via cp.async ------------------------
template<int ROWS>
__device__ __forceinline__ void stage_tile(uint32 dstbase, const __half* src0,
                                           int Kst, int kk, int t){
  #pragma unroll
  for (int s=0; s<(ROWS>>5); s++){
    int slot = t + s*256;
    int r = slot >> 3, g = slot & 7;
    cpa16(dstbase + swz(r, g), (const void*)(src0 + (size_t)r*Kst + kk + g*8));
  }
}

// ---------------- warp MMA mainloop: warp tile 32 x 64 --------------------------
__device__ __forceinline__ void compute_chunk(uint32 sb, uint32 aoff, uint32 boff,
                                              int lane, int wm, int wn,
                                              float (&acc)[2][8][4]){
  uint32 rbA[2]; int rxA[2];
  #pragma unroll
  for (int mi=0;mi<2;mi++){
    int row = wm*32 + mi*16 + (lane&15);
    rbA[mi] = sb + aoff + row*128;
    rxA[mi] = row & 7;
  }
  int hi4 = lane>>4;
  uint32 rbB[4]; int rxB[4];
  #pragma unroll
  for (int g=0; g<4; g++){
    int n = wn*64 + g*16 + ((lane>>4)<<3) + (lane&7);
    rbB[g] = sb + boff + n*128;
    rxB[g] = n & 7;
  }
  int cB = (lane>>3)&1;
  #pragma unroll
  for (int ks=0; ks<4; ks++){
    int c16 = ks*2;
    uint32 Ah[2][4];
    #pragma unroll
    for (int mi=0;mi<2;mi++){
      uint32 off = ((uint32)((c16 + hi4) ^ rxA[mi])) << 4;
      ldsm4(Ah[mi], rbA[mi] + off);
    }
    uint32 Bh[4][4];
    #pragma unroll
    for (int g=0; g<4; g++){
      uint32 off = ((uint32)((c16 + cB) ^ rxB[g])) << 4;
      ldsm4(Bh[g], rbB[g] + off);
    }
    #pragma unroll
    for (int mi=0;mi<2;mi++){
      #pragma unroll
      for (int nn=0;nn<8;nn++)
        mma_f16(acc[mi][nn], Ah[mi], Bh[nn>>1][(nn&1)*2], Bh[nn>>1][(nn&1)*2+1]);
    }
  }
}

#define ZERO_ACC(acc) { \
  _Pragma("unroll") for (int _a=0;_a<2;_a++) \
    _Pragma("unroll") for (int _b=0;_b<8;_b++) \
      _Pragma("unroll") for (int _c=0;_c<4;_c++) (acc)[_a][_b][_c]=0.f; }

// ---------------- CSR build -----------------------------------------------------
__global__ void k_count(const int* __restrict__ ei){
  int e = blockIdx.x*256+threadIdx.x;
  if (e<E_) atomicAdd(&g_cnt[ei[E_+e]], 1);
}
__global__ void k_scan(){
  __shared__ int sh[1024];
  int t = threadIdx.x;
  int base = t*10;
  int loc[10]; int run=0;
  #pragma unroll
  for (int i=0;i<10;i++){ int idx=base+i; int v=(idx<N_)? g_cnt[idx]:0; loc[i]=run; run+=v; }
  sh[t]=run; __syncthreads();
  for (int off=1; off<1024; off<<=1){
    int v = (t>=off)? sh[t-off] : 0;
    __syncthreads();
    sh[t] += v;
    __syncthreads();
  }
  int pre = (t>0)? sh[t-1] : 0;
  #pragma unroll
  for (int i=0;i<10;i++){ int idx=base+i; if (idx<N_){ int p=pre+loc[i]; g_rowptr[idx]=p; g_cur[idx]=p; } }
  if (t==1023) g_rowptr[N_] = sh[1023];
}
__global__ void k_scatter(const int* __restrict__ ei){
  int e = blockIdx.x*256+threadIdx.x;
  if (e<E_){
    int d = ei[E_+e];
    int p = atomicAdd(&g_cur[d], 1);
    g_perm[p] = e;
  }
  if (e<N_) g_cnt[e]=0;
}

// ---------------- fused prep: 7 weight transposes + x fp16 conversion ----------
__global__ void k_prep_all(
    const float* __restrict__ Wq, const float* __restrict__ Wk,
    const float* __restrict__ Wv, const float* __restrict__ Wp2,
    const float* __restrict__ Wo, const float* __restrict__ Wf1,
    const float* __restrict__ Wf2, const float* __restrict__ x){
  __shared__ float tile[32][33];
  int bid = blockIdx.x;
  int tx = threadIdx.x, ty = threadIdx.y;   // 32 x 8
  if (bid >= 832){
    int t = ty*32 + tx;
    size_t base = (size_t)(bid-832)*2048 + (size_t)t*8;
    float4 a = *(const float4*)(x + base);
    float4 b = *(const float4*)(x + base + 4);
    HU H;
    H.h[0]=__float2half_rn(a.x); H.h[1]=__float2half_rn(a.y);
    H.h[2]=__float2half_rn(a.z); H.h[3]=__float2half_rn(a.w);
    H.h[4]=__float2half_rn(b.x); H.h[5]=__float2half_rn(b.y);
    H.h[6]=__float2half_rn(b.z); H.h[7]=__float2half_rn(b.w);
    *(uint4*)(g_xh + base) = H.u;
    return;
  }
  const float* W; int K, N; uint32 off; int local;
  if (bid < 320){
    local = bid & 63;
    int w = bid >> 6;
    W = (w==0)?Wq:(w==1)?Wk:(w==2)?Wv:(w==3)?Wp2:Wo;
    K = 256; N = 256; off = (uint32)w*65536u;
  } else if (bid < 576){ local = bid-320; W = Wf1; K = 256;  N = 1024; off = OFF_F1; }
  else                 { local = bid-576; W = Wf2; K = 1024; N = 256;  off = OFF_F2; }
  int nkb = K/32;
  int k0 = (local % nkb)*32, n0 = (local / nkb)*32;
  #pragma unroll
  for (int i=0;i<4;i++)
    tile[ty+i*8][tx] = W[(size_t)(k0+ty+i*8)*N + n0 + tx];
  __syncthreads();
  #pragma unroll
  for (int i=0;i<4;i++){
    int n = n0 + ty + i*8, k = k0 + tx;
    g_wt[(size_t)off + (size_t)n*K + k] = __float2half_rn(tile[tx][ty+i*8]);
  }
}

// ---------------- QKV GEMMs: M=128, N=128 tile; blockIdx.y = gemm*2 + nhalf ----
__global__ void __launch_bounds__(256,2) k_mm_qkv(
    const float* __restrict__ bq, const float* __restrict__ bk,
    const float* __restrict__ bv){
  extern __shared__ char smem[];
  uint32 sb = smem_to_u32(smem);
  int t = threadIdx.x, lane = t&31, wid = t>>5;
  int wm = wid>>1, wn = wid&1;
  int r0 = blockIdx.x*128;
  int gemm = blockIdx.y >> 1, nh = blockIdx.y & 1;
  const __half* Bsrc = g_wt + (size_t)gemm*65536 + (size_t)nh*128*256;
  const float* bias = (gemm==0)?bq:((gemm==1)?bk:bv);
  float* C = (gemm==0)?g_Q:((gemm==1)?g_K:g_V);
  const __half* Asrc = g_xh + (size_t)r0*256;
  float* s_bias = (float*)(smem + Q_PAR);
  if (t < 128) s_bias[t] = bias[nh*128 + t];

  float acc[2][8][4];
  ZERO_ACC(acc);

  stage_tile<128>(sb + Q_A0, Asrc, 256, 0, t);
  stage_tile<128>(sb + Q_B0, Bsrc, 256, 0, t);
  CPA_COMMIT();
  #pragma unroll
  for (int ck=0; ck<4; ck++){
    if (ck<3){
      stage_tile<128>(sb + ((ck&1)? Q_A0:Q_A1), Asrc, 256, (ck+1)*64, t);
      stage_tile<128>(sb + ((ck&1)? Q_B0:Q_B1), Bsrc, 256, (ck+1)*64, t);
      CPA_COMMIT(); CPA_WAIT(1);
    } else { CPA_WAIT(0); }
    __syncthreads();
    compute_chunk(sb, (ck&1)?Q_A1:Q_A0, (ck&1)?Q_B1:Q_B0, lane, wm, wn, acc);
    __syncthreads();
  }

  #pragma unroll
  for (int mi=0;mi<2;mi++){
    int rA = wm*32 + mi*16 + (lane>>2);
    #pragma unroll
    for (int half=0; half<2; half++){
      int row = r0 + rA + half*8;
      if (row >= N_) continue;
      #pragma unroll
      for (int ni=0;ni<8;ni++){
        int lc = wn*64 + ni*8 + (lane&3)*2;
        float2 o;
        o.x = acc[mi][ni][half*2+0] + s_bias[lc];
        o.y = acc[mi][ni][half*2+1] + s_bias[lc+1];
        *(float2*)(C + (size_t)row*256 + nh*128 + lc) = o;
      }
    }
  }
}

// ---------------- FFN1: M=128, N=128 tile; fp16 out ----------------------------
__global__ void __launch_bounds__(256,2) k_mm_ffn1(const float* __restrict__ bf1){
  extern __shared__ char smem[];
  uint32 sb = smem_to_u32(smem);
  int t = threadIdx.x, lane = t&31, wid = t>>5;
  int wm = wid>>1, wn = wid&1;
  int r0 = blockIdx.x*128;
  int colOff = blockIdx.y*128;
  const __half* Bsrc = g_wt + OFF_F1 + (size_t)colOff*256;
  const __half* Asrc = g_x1h + (size_t)r0*256;
  float* s_bias = (float*)(smem + Q_PAR);
  if (t < 128) s_bias[t] = bf1[colOff + t];

  float acc[2][8][4];
  ZERO_ACC(acc);

  stage_tile<128>(sb + Q_A0, Asrc, 256, 0, t);
  stage_tile<128>(sb + Q_B0, Bsrc, 256, 0, t);
  CPA_COMMIT();
  #pragma unroll
  for (int ck=0; ck<4; ck++){
    if (ck<3){
      stage_tile<128>(sb + ((ck&1)? Q_A0:Q_A1), Asrc, 256, (ck+1)*64, t);
      stage_tile<128>(sb + ((ck&1)? Q_B0:Q_B1), Bsrc, 256, (ck+1)*64, t);
      CPA_COMMIT(); CPA_WAIT(1);
    } else { CPA_WAIT(0); }
    __syncthreads();
    compute_chunk(sb, (ck&1)?Q_A1:Q_A0, (ck&1)?Q_B1:Q_B0, lane, wm, wn, acc);
    __syncthreads();
  }

  #pragma unroll
  for (int mi=0;mi<2;mi++){
    int rA = wm*32 + mi*16 + (lane>>2);
    #pragma unroll
    for (int half=0; half<2; half++){
      int row = r0 + rA + half*8;
      if (row >= N_) continue;
      #pragma unroll
      for (int ni=0;ni<8;ni++){
        int lc = wn*64 + ni*8 + (lane&3)*2;
        float v0 = fmaxf(acc[mi][ni][half*2+0] + s_bias[lc],   0.f);
        float v1 = fmaxf(acc[mi][ni][half*2+1] + s_bias[lc+1], 0.f);
        *(__half2*)(g_ffn + (size_t)row*1024 + colOff + lc) = __floats2half2_rn(v0, v1);
      }
    }
  }
}

// ---------------- edge: M=64, N=256; pe-MLP GEMM + LN + scores ------------------
__global__ void __launch_bounds__(256,2) k_mm_edge(
    const float* __restrict__ pos, const int* __restrict__ ei,
    const float* __restrict__ Wp1, const float* __restrict__ bp1,
    const float* __restrict__ bp2, const float* __restrict__ gp,
    const float* __restrict__ bpn){
  extern __shared__ char smem[];
  uint32 sb = smem_to_u32(smem);
  int t = threadIdx.x, lane = t&31, wid = t>>5;
  int wm = wid>>2, wn = wid&3;
  int e0 = blockIdx.x*64;

  float* s_w1   = (float*)(smem + L_PAR);   // 768
  float* s_b1   = s_w1 + 768;               // 256
  float* s_p2   = s_b1 + 256;               // 256
  float* s_gp   = s_p2 + 256;               // 256
  float* s_bn   = s_gp + 256;               // 256
  float* s_dp   = s_bn + 256;               // 192
  float* s_part = s_dp + 192;               // 512
  int*   s_nd   = (int*)(s_part + 512);     // 128

  s_w1[t]     = Wp1[t];
  s_w1[256+t] = Wp1[256+t];
  s_w1[512+t] = Wp1[512+t];
  s_b1[t] = bp1[t]; s_p2[t] = bp2[t]; s_gp[t] = gp[t]; s_bn[t] = bpn[t];
  if (t < 64){
    int e = e0 + t;
    int sn = ei[e], dn = ei[E_+e];
    s_nd[t] = sn; s_nd[64+t] = dn;
    s_dp[t*3+0] = pos[dn*3+0]-pos[sn*3+0];
    s_dp[t*3+1] = pos[dn*3+1]-pos[sn*3+1];
    s_dp[t*3+2] = pos[dn*3+2]-pos[sn*3+2];
  }
  __syncthreads();

  int rr = t>>2, q4 = t&3;
  float dx = s_dp[rr*3+0], dy = s_dp[rr*3+1], dz = s_dp[rr*3+2];

  float acc[2][8][4];
  ZERO_ACC(acc);

  // generate A tile (64 rows x 64 k): h = relu(dp @ Wp1 + bp1) -> fp16
  auto gen_a = [&](uint32 aoff, int kk){
    #pragma unroll
    for (int half=0; half<2; half++){
      HU H;
      #pragma unroll
      for (int j=0; j<8; j++){
        int c = kk + q4*16 + half*8 + j;
        float v = fmaf(dz, s_w1[512+c], fmaf(dy, s_w1[256+c], fmaf(dx, s_w1[c], s_b1[c])));
        H.h[j] = __float2half_rn(fmaxf(v, 0.f));
      }
      *(uint4*)(smem + aoff + swz(rr, q4*2 + half)) = H.u;
    }
  };

  gen_a(L_A0, 0);
  stage_tile<256>(sb + L_B0, g_wt + OFF_P2, 256, 0, t);
  CPA_COMMIT();
  #pragma unroll
  for (int ck=0; ck<4; ck++){
    if (ck<3){
      gen_a((ck&1)? L_A0:L_A1, (ck+1)*64);
      stage_tile<256>(sb + ((ck&1)? L_B0:L_B1), g_wt + OFF_P2, 256, (ck+1)*64, t);
      CPA_COMMIT(); CPA_WAIT(1);
    } else { CPA_WAIT(0); }
    __syncthreads();
    compute_chunk(sb, (ck&1)?L_A1:L_A0, (ck&1)?L_B1:L_B0, lane, wm, wn, acc);
    __syncthreads();
  }

  // pass 1: vals = acc + bp2; per-row partial LN stats
  #pragma unroll
  for (int mi=0;mi<2;mi++){
    int rA = wm*32 + mi*16 + (lane>>2);
    #pragma unroll
    for (int half=0; half<2; half++){
      int rl = rA + half*8;
      float s1=0.f, s2=0.f;
      #pragma unroll
      for (int ni=0;ni<8;ni++){
        int col = wn*64 + ni*8 + (lane&3)*2;
        float v0 = acc[mi][ni][half*2+0] + s_p2[col];
        float v1 = acc[mi][ni][half*2+1] + s_p2[col+1];
        acc[mi][ni][half*2+0] = v0;
        acc[mi][ni][half*2+1] = v1;
        s1 += v0 + v1;
        s2 = fmaf(v0, v0, fmaf(v1, v1, s2));
      }
      s1 += __shfl_xor_sync(0xffffffffu, s1, 1);
      s1 += __shfl_xor_sync(0xffffffffu, s1, 2);
      s2 += __shfl_xor_sync(0xffffffffu, s2, 1);
      s2 += __shfl_xor_sync(0xffffffffu, s2, 2);
      if ((lane&3)==0){ s_part[(rl*4+wn)*2] = s1; s_part[(rl*4+wn)*2+1] = s2; }
    }
  }
  __syncthreads();

  // pass 2: LN + per-head scores
  const float SC = 0.17677669529663688f;  // 1/sqrt(32)
  #pragma unroll
  for (int mi=0;mi<2;mi++){
    int rA = wm*32 + mi*16 + (lane>>2);
    #pragma unroll
    for (int half=0; half<2; half++){
      int rl = rA + half*8;
      int e = e0 + rl;
      float s1 = s_part[(rl*4+0)*2] + s_part[(rl*4+1)*2]
               + s_part[(rl*4+2)*2] + s_part[(rl*4+3)*2];
      float s2 = s_part[(rl*4+0)*2+1] + s_part[(rl*4+1)*2+1]
               + s_part[(rl*4+2)*2+1] + s_part[(rl*4+3)*2+1];
      float m = s1*(1.f/256.f);
      float rstd = rsqrtf(fmaxf(s2*(1.f/256.f) - m*m, 0.f) + 1e-5f);
      int sn = s_nd[rl], dn = s_nd[64+rl];
      const float* Qp = g_Q + (size_t)dn*256;
      const float* Kp = g_K + (size_t)sn*256;
      #pragma unroll
      for (int h=0; h<2; h++){
        float partial = 0.f;
        #pragma unroll
        for (int nio=0; nio<4; nio++){
          int ni = h*4 + nio;
          int col = wn*64 + ni*8 + (lane&3)*2;
          float2 qv = *(const float2*)(Qp + col);
          float2 kv = *(const float2*)(Kp + col);
          float pe0 = (acc[mi][ni][half*2+0]-m)*rstd*s_gp[col]   + s_bn[col];
          float pe1 = (acc[mi][ni][half*2+1]-m)*rstd*s_gp[col+1] + s_bn[col+1];
          partial = fmaf(qv.x, kv.x + pe0, partial);
          partial = fmaf(qv.y, kv.y + pe1, partial);
        }
        partial += __shfl_xor_sync(0xffffffffu, partial, 1);
        partial += __shfl_xor_sync(0xffffffffu, partial, 2);
        if ((lane&3)==0)
          g_score[(size_t)e*8 + wn*2 + h] = partial*SC;
      }
    }
  }
}

// ---------------- segment softmax + weighted aggregation ------------------------
__global__ void __launch_bounds__(256) k_aggr(const int* __restrict__ ei){
  int n = blockIdx.x;
  int beg = g_rowptr[n], end = g_rowptr[n+1];
  int t = threadIdx.x, lane = t&31, w = t>>5;
  __shared__ float s_mx[8], s_rs[8];
  __shared__ float s_at[128*8];
  __shared__ int   s_sc[128];

  {
    int h = w;
    float mx = -3.0e38f;
    for (int i=beg+lane; i<end; i+=32)
      mx = fmaxf(mx, g_score[(size_t)g_perm[i]*8+h]);
    #pragma unroll
    for (int o=16;o>0;o>>=1) mx = fmaxf(mx, __shfl_xor_sync(0xffffffffu, mx, o));
    float s=0.f;
    for (int i=beg+lane; i<end; i+=32)
      s += __expf(g_score[(size_t)g_perm[i]*8+h]-mx);
    #pragma unroll
    for (int o=16;o>0;o>>=1) s += __shfl_xor_sync(0xffffffffu, s, o);
    if (lane==0){ s_mx[h]=mx; s_rs[h]=1.f/(s+1e-16f); }
  }
  __syncthreads();

  float acc=0.f;
  int h = t>>5;
  for (int c0=beg; c0<end; c0+=128){
    int cn = min(128, end-c0);
    for (int j=t; j<cn*8; j+=256){
      int i=j>>3, hh=j&7;
      int e = g_perm[c0+i];
      s_at[i*8+hh] = __expf(g_score[(size_t)e*8+hh]-s_mx[hh])*s_rs[hh];
      if (hh==0) s_sc[i] = ei[e];
    }
    __syncthreads();
    for (int i=0;i<cn;i++)
      acc = fmaf(s_at[i*8+h], g_V[(size_t)s_sc[i]*256 + t], acc);
    __syncthreads();
  }
  g_aggrh[(size_t)n*256+t] = __float2half_rn(acc);
}

// ---------------- GEMM + LN (Wo / FFN2): M=64, N=256 ---------------------------
__global__ void __launch_bounds__(256,2) k_mm_ln(int mode,
    const float* __restrict__ bias, const float* __restrict__ resx,
    const float* __restrict__ gam, const float* __restrict__ bet,
    float* __restrict__ outp){
  extern __shared__ char smem[];
  uint32 sb = smem_to_u32(smem);
  int t = threadIdx.x, lane = t&31, wid = t>>5;
  int wm = wid>>2, wn = wid&3;
  int r0 = blockIdx.x*64;
  const float* res; float* C; int K; const __half* Bsrc; const __half* Asrc; int Kst;
  if (mode==0){
    res=resx; C=g_x1; K=256; Bsrc=g_wt+OFF_O;
    Asrc = g_aggrh + (size_t)r0*256; Kst=256;
  } else {
    res=g_x1; C=outp; K=1024; Bsrc=g_wt+OFF_F2;
    Asrc = g_ffn + (size_t)r0*1024; Kst=1024;
  }

  float* s_bias = (float*)(smem + L_PAR);
  float* s_g    = s_bias + 256;
  float* s_b    = s_g + 256;
  float* s_part = s_b + 256;                // 512
  s_bias[t] = bias[t]; s_g[t] = gam[t]; s_b[t] = bet[t];

  float acc[2][8][4];
  ZERO_ACC(acc);

  int nchunks = K/64;
  stage_tile<64>(sb + L_A0, Asrc, Kst, 0, t);
  stage_tile<256>(sb + L_B0, Bsrc, K, 0, t);
  CPA_COMMIT();
  for (int ck=0; ck<nchunks; ck++){
    if (ck+1 < nchunks){
      stage_tile<64>(sb + ((ck&1)? L_A0:L_A1), Asrc, Kst, (ck+1)*64, t);
      stage_tile<256>(sb + ((ck&1)? L_B0:L_B1), Bsrc, K, (ck+1)*64, t);
      CPA_COMMIT(); CPA_WAIT(1);
    } else { CPA_WAIT(0); }
    __syncthreads();
    compute_chunk(sb, (ck&1)?L_A1:L_A0, (ck&1)?L_B1:L_B0, lane, wm, wn, acc);
    __syncthreads();
  }

  // pass 1: vals = acc + bias + residual; partial LN stats
  #pragma unroll
  for (int mi=0;mi<2;mi++){
    int rA = wm*32 + mi*16 + (lane>>2);
    #pragma unroll
    for (int half=0; half<2; half++){
      int rl = rA + half*8;
      int row = r0 + rl;
      bool ok = row < N_;
      float s1=0.f, s2=0.f;
      #pragma unroll
      for (int ni=0;ni<8;ni++){
        int col = wn*64 + ni*8 + (lane&3)*2;
        float2 rv = ok ? *(const float2*)(res + (size_t)row*256 + col)
                       : make_float2(0.f, 0.f);
        float v0 = acc[mi][ni][half*2+0] + s_bias[col]   + rv.x;
        float v1 = acc[mi][ni][half*2+1] + s_bias[col+1] + rv.y;
        acc[mi][ni][half*2+0] = v0;
        acc[mi][ni][half*2+1] = v1;
        s1 += v0 + v1;
        s2 = fmaf(v0, v0, fmaf(v1, v1, s2));
      }
      s1 += __shfl_xor_sync(0xffffffffu, s1, 1);
      s1 += __shfl_xor_sync(0xffffffffu, s1, 2);
      s2 += __shfl_xor_sync(0xffffffffu, s2, 1);
      s2 += __shfl_xor_sync(0xffffffffu, s2, 2);
      if ((lane&3)==0){ s_part[(rl*4+wn)*2] = s1; s_part[(rl*4+wn)*2+1] = s2; }
    }
  }
  __syncthreads();

  // pass 2: normalize + store
  #pragma unroll
  for (int mi=0;mi<2;mi++){
    int rA = wm*32 + mi*16 + (lane>>2);
    #pragma unroll
    for (int half=0; half<2; half++){
      int rl = rA + half*8;
      int row = r0 + rl;
      if (row >= N_) continue;
      float s1 = s_part[(rl*4+0)*2] + s_part[(rl*4+1)*2]
               + s_part[(rl*4+2)*2] + s_part[(rl*4+3)*2];
      float s2 = s_part[(rl*4+0)*2+1] + s_part[(rl*4+1)*2+1]
               + s_part[(rl*4+2)*2+1] + s_part[(rl*4+3)*2+1];
      float m = s1*(1.f/256.f);
      float rstd = rsqrtf(fmaxf(s2*(1.f/256.f) - m*m, 0.f) + 1e-5f);
      #pragma unroll
      for (int ni=0;ni<8;ni++){
        int col = wn*64 + ni*8 + (lane&3)*2;
        float o0 = (acc[mi][ni][half*2+0]-m)*rstd*s_g[col]   + s_b[col];
        float o1 = (acc[mi][ni][half*2+1]-m)*rstd*s_g[col+1] + s_b[col+1];
        *(float2*)(C + (size_t)row*256 + col) = make_float2(o0, o1);
        if (mode==0)
          *(__half2*)(g_x1h + (size_t)row*256 + col) = __floats2half2_rn(o0, o1);
      }
    }
  }
}

// ---------------- launch ---------------------------------------------------------
extern "C" void kernel_launch(void* const* d_in, const int* in_sizes, int n_in,
                              void* d_out, int out_size){
  const float* x    = (const float*)d_in[0];
  const float* pos  = (const float*)d_in[1];
  const int*   ei   = (const int*)  d_in[2];
  const float* Wq   = (const float*)d_in[3];
  const float* bq   = (const float*)d_in[4];
  const float* Wk   = (const float*)d_in[5];
  const float* bk   = (const float*)d_in[6];
  const float* Wv   = (const float*)d_in[7];
  const float* bv   = (const float*)d_in[8];
  const float* Wp1  = (const float*)d_in[9];
  const float* bp1  = (const float*)d_in[10];
  const float* Wp2  = (const float*)d_in[11];
  const float* bp2  = (const float*)d_in[12];
  const float* gp   = (const float*)d_in[13];
  const float* bp   = (const float*)d_in[14];
  const float* Wo   = (const float*)d_in[15];
  const float* bo   = (const float*)d_in[16];
  const float* g1   = (const float*)d_in[17];
  const float* b1n  = (const float*)d_in[18];
  const float* Wf1  = (const float*)d_in[19];
  const float* bf1  = (const float*)d_in[20];
  const float* Wf2  = (const float*)d_in[21];
  const float* bf2  = (const float*)d_in[22];
  const float* g2   = (const float*)d_in[23];
  const float* b2n  = (const float*)d_in[24];
  float* out = (float*)d_out;

  cudaFuncSetAttribute(k_mm_qkv,  cudaFuncAttributeMaxDynamicSharedMemorySize, Q_DYN);
  cudaFuncSetAttribute(k_mm_ffn1, cudaFuncAttributeMaxDynamicSharedMemorySize, Q_DYN);
  cudaFuncSetAttribute(k_mm_edge, cudaFuncAttributeMaxDynamicSharedMemorySize, L_DYN);
  cudaFuncSetAttribute(k_mm_ln,   cudaFuncAttributeMaxDynamicSharedMemorySize, L_DYN);

  const int MT128 = (N_ + 127) / 128;  // 79
  const int MT64  = (N_ + 63) / 64;    // 157
  const int ET    = E_ / 64;           // 2500

  // CSR build (g_cnt re-zeroed by k_scatter tail each run)
  k_count  <<<(E_+255)/256, 256>>>(ei);
  k_scan   <<<1, 1024>>>();
  k_scatter<<<(E_+255)/256, 256>>>(ei);

  // fused prep: 7 weight transposes + x->fp16
  k_prep_all<<<2082, dim3(32,8)>>>(Wq, Wk, Wv, Wp2, Wo, Wf1, Wf2, x);

  // Q/K/V  (3 gemms x 2 n-halves)
  k_mm_qkv<<<dim3(MT128,6), 256, Q_DYN>>>(bq, bk, bv);

  // edge: pe-MLP GEMM + LN + scores
  k_mm_edge<<<ET, 256, L_DYN>>>(pos, ei, Wp1, bp1, bp2, gp, bp);

  // segment softmax + aggregation [fp16 out]
  k_aggr<<<N_, 256>>>(ei);

  // x1 = LN(aggr@Wo + bo + x)  [+ fp16 mirror]
  k_mm_ln<<<MT64, 256, L_DYN>>>(0, bo, x, g1, b1n, nullptr);

  // ffn = relu(x1@Wf1 + bf1)  [fp16 out]  (8 col tiles)
  k_mm_ffn1<<<dim3(MT128,8), 256, Q_DYN>>>(bf1);

  // out = LN(ffn@Wf2 + bf2 + x1)
  k_mm_ln<<<MT64, 256, L_DYN>>>(1, bf2, nullptr, g2, b2n, out);

  (void)in_sizes; (void)n_in; (void)out_size;
}

// round 10
// speedup vs baseline: 3.9414x; 1.0183x over previous
#include <cuda_runtime.h>
#include <cuda_fp16.h>

#define N_ 10000
#define NPAD 10112
#define E_ 160000

typedef unsigned int uint32;

// ---------------- device scratch ---------------------------------------------
__device__ __align__(16) __half g_Qh[N_*256];
__device__ __align__(16) __half g_Kh[N_*256];
__device__ __align__(16) __half g_Vh[N_*256];
__device__ __align__(16) float g_score[E_*8];
__device__ __align__(16) float g_x1[N_*256];
__device__ __align__(16) __half g_xh[NPAD*256];
__device__ __align__(16) __half g_aggrh[NPAD*256];
__device__ __align__(16) __half g_x1h[NPAD*256];
__device__ __align__(16) __half g_ffn[NPAD*1024];
__device__ int   g_cnt[N_];
__device__ int   g_rowptr[N_+1];
__device__ int   g_cur[N_];
__device__ int   g_pos[E_];    // edge -> CSR slot
__device__ int   g_srcs[E_];   // CSR slot -> src node

// transposed weights, [N][K] fp16 (K contiguous)
#define OFF_Q  0u
#define OFF_K  65536u
#define OFF_V  131072u
#define OFF_P2 196608u
#define OFF_O  262144u
#define OFF_F1 327680u      /* [1024][256] */
#define OFF_F2 589824u      /* [256][1024] */
#define WT_TOTAL 851968u
__device__ __align__(16) __half g_wt[WT_TOTAL];

// ---------------- smem layouts ---------------------------------------------------
#define Q_A0 0
#define Q_A1 16384
#define Q_B0 32768
#define Q_B1 49152
#define Q_PAR 65536
#define Q_DYN 67584
#define L_A0 0
#define L_A1 8192
#define L_B0 16384
#define L_B1 49152
#define L_PAR 81920
#define L_DYN 94208

__device__ __forceinline__ uint32 smem_to_u32(const void* p){
  uint32 a;
  asm("{ .reg .u64 t; cvta.to.shared.u64 t, %1; cvt.u32.u64 %0, t; }" : "=r"(a) : "l"(p));
  return a;
}
__device__ __forceinline__ uint32 swz(int row, int c16){
  return (uint32)(row*128 + (((c16) ^ (row & 7)) << 4));
}
__device__ __forceinline__ void ldsm4(uint32* r, uint32 addr){
  asm volatile("ldmatrix.sync.aligned.m8n8.x4.shared.b16 {%0,%1,%2,%3}, [%4];"
    : "=r"(r[0]),"=r"(r[1]),"=r"(r[2]),"=r"(r[3]) : "r"(addr));
}
__device__ __forceinline__ void mma_f16(float* c, const uint32* a, uint32 b0, uint32 b1){
  asm volatile("mma.sync.aligned.m16n8k16.row.col.f32.f16.f16.f32 "
    "{%0,%1,%2,%3}, {%4,%5,%6,%7}, {%8,%9}, {%0,%1,%2,%3};"
    : "+f"(c[0]),"+f"(c[1]),"+f"(c[2]),"+f"(c[3])
    : "r"(a[0]),"r"(a[1]),"r"(a[2]),"r"(a[3]), "r"(b0),"r"(b1));
}
__device__ __forceinline__ void cpa16(uint32 dst, const void* src){
  asm volatile("cp.async.cg.shared.global [%0], [%1], 16;" :: "r"(dst), "l"(src));
}
#define CPA_COMMIT() asm volatile("cp.async.commit_group;" ::: "memory")
#define CPA_WAIT(n)  asm volatile("cp.async.wait_group %0;" :: "n"(n) : "memory")

union HU { __half h[8]; uint4 u; };

// ---------------- staging: generic fp16 tile via cp.async ------------------------
template<int ROWS>
__device__ __forceinline__ void stage_tile(uint32 dstbase, const __half* src0,
                                           int Kst, int kk, int t){
  #pragma unroll
  for (int s=0; s<(ROWS>>5); s++){
    int slot = t + s*256;
    int r = slot >> 3, g = slot & 7;
    cpa16(dstbase + swz(r, g), (const void*)(src0 + (size_t)r*Kst + kk + g*8));
  }
}

// ---------------- warp MMA mainloop: warp tile 32 x 64 --------------------------
__device__ __forceinline__ void compute_chunk(uint32 sb, uint32 aoff, uint32 boff,
                                              int lane, int wm, int wn,
                                              float (&acc)[2][8][4]){
  uint32 rbA[2]; int rxA[2];
  #pragma unroll
  for (int mi=0;mi<2;mi++){
    int row = wm*32 + mi*16 + (lane&15);
    rbA[mi] = sb + aoff + row*128;
    rxA[mi] = row & 7;
  }
  int hi4 = lane>>4;
  uint32 rbB[4]; int rxB[4];
  #pragma unroll
  for (int g=0; g<4; g++){
    int n = wn*64 + g*16 + ((lane>>4)<<3) + (lane&7);
    rbB[g] = sb + boff + n*128;
    rxB[g] = n & 7;
  }
  int cB = (lane>>3)&1;
  #pragma unroll
  for (int ks=0; ks<4; ks++){
    int c16 = ks*2;
    uint32 Ah[2][4];
    #pragma unroll
    for (int mi=0;mi<2;mi++){
      uint32 off = ((uint32)((c16 + hi4) ^ rxA[mi])) << 4;
      ldsm4(Ah[mi], rbA[mi] + off);
    }
    uint32 Bh[4][4];
    #pragma unroll
    for (int g=0; g<4; g++){
      uint32 off = ((uint32)((c16 + cB) ^ rxB[g])) << 4;
      ldsm4(Bh[g], rbB[g] + off);
    }
    #pragma unroll
    for (int mi=0;mi<2;mi++){
      #pragma unroll
      for (int nn=0;nn<8;nn++)
        mma_f16(acc[mi][nn], Ah[mi], Bh[nn>>1][(nn&1)*2], Bh[nn>>1][(nn&1)*2+1]);
    }
  }
}

#define ZERO_ACC(acc) { \
  _Pragma("unroll") for (int _a=0;_a<2;_a++) \
    _Pragma("unroll") for (int _b=0;_b<8;_b++) \
      _Pragma("unroll") for (int _c=0;_c<4;_c++) (acc)[_a][_b][_c]=0.f; }

// ---------------- CSR build -----------------------------------------------------
__global__ void k_count(const int* __restrict__ ei){
  int e = blockIdx.x*256+threadIdx.x;
  if (e<E_) atomicAdd(&g_cnt[ei[E_+e]], 1);
}
__global__ void k_scan(){
  __shared__ int sh[1024];
  int t = threadIdx.x;
  int base = t*10;
  int loc[10]; int run=0;
  #pragma unroll
  for (int i=0;i<10;i++){ int idx=base+i; int v=(idx<N_)? g_cnt[idx]:0; loc[i]=run; run+=v; }
  sh[t]=run; __syncthreads();
  for (int off=1; off<1024; off<<=1){
    int v = (t>=off)? sh[t-off] : 0;
    __syncthreads();
    sh[t] += v;
    __syncthreads();
  }
  int pre = (t>0)? sh[t-1] : 0;
  #pragma unroll
  for (int i=0;i<10;i++){ int idx=base+i; if (idx<N_){ int p=pre+loc[i]; g_rowptr[idx]=p; g_cur[idx]=p; } }
  if (t==1023) g_rowptr[N_] = sh[1023];
}
__global__ void k_scatter(const int* __restrict__ ei){
  int e = blockIdx.x*256+threadIdx.x;
  if (e<E_){
    int d = ei[E_+e];
    int p = atomicAdd(&g_cur[d], 1);
    g_pos[e] = p;
    g_srcs[p] = ei[e];
  }
  if (e<N_) g_cnt[e]=0;
}

// ---------------- fused prep: 7 weight transposes + x fp16 conversion ----------
__global__ void k_prep_all(
    const float* __restrict__ Wq, const float* __restrict__ Wk,
    const float* __restrict__ Wv, const float* __restrict__ Wp2,
    const float* __restrict__ Wo, const float* __restrict__ Wf1,
    const float* __restrict__ Wf2, const float* __restrict__ x){
  __shared__ float tile[32][33];
  int bid = blockIdx.x;
  int tx = threadIdx.x, ty = threadIdx.y;   // 32 x 8
  if (bid >= 832){
    int t = ty*32 + tx;
    size_t base = (size_t)(bid-832)*2048 + (size_t)t*8;
    float4 a = *(const float4*)(x + base);
    float4 b = *(const float4*)(x + base + 4);
    HU H;
    H.h[0]=__float2half_rn(a.x); H.h[1]=__float2half_rn(a.y);
    H.h[2]=__float2half_rn(a.z); H.h[3]=__float2half_rn(a.w);
    H.h[4]=__float2half_rn(b.x); H.h[5]=__float2half_rn(b.y);
    H.h[6]=__float2half_rn(b.z); H.h[7]=__float2half_rn(b.w);
    *(uint4*)(g_xh + base) = H.u;
    return;
  }
  const float* W; int K, N; uint32 off; int local;
  if (bid < 320){
    local = bid & 63;
    int w = bid >> 6;
    W = (w==0)?Wq:(w==1)?Wk:(w==2)?Wv:(w==3)?Wp2:Wo;
    K = 256; N = 256; off = (uint32)w*65536u;
  } else if (bid < 576){ local = bid-320; W = Wf1; K = 256;  N = 1024; off = OFF_F1; }
  else                 { local = bid-576; W = Wf2; K = 1024; N = 256;  off = OFF_F2; }
  int nkb = K/32;
  int k0 = (local % nkb)*32, n0 = (local / nkb)*32;
  #pragma unroll
  for (int i=0;i<4;i++)
    tile[ty+i*8][tx] = W[(size_t)(k0+ty+i*8)*N + n0 + tx];
  __syncthreads();
  #pragma unroll
  for (int i=0;i<4;i++){
    int n = n0 + ty + i*8, k = k0 + tx;
    g_wt[(size_t)off + (size_t)n*K + k] = __float2half_rn(tile[tx][ty+i*8]);
  }
}

// ---------------- QKV GEMMs: M=128, N=128 tile; fp16 out ------------------------
__global__ void __launch_bounds__(256,2) k_mm_qkv(
    const float* __restrict__ bq, const float* __restrict__ bk,
    const float* __restrict__ bv){
  extern __shared__ char smem[];
  uint32 sb = smem_to_u32(smem);
  int t = threadIdx.x, lane = t&31, wid = t>>5;
  int wm = wid>>1, wn = wid&1;
  int r0 = blockIdx.x*128;
  int gemm = blockIdx.y >> 1, nh = blockIdx.y & 1;
  const __half* Bsrc = g_wt + (size_t)gemm*65536 + (size_t)nh*128*256;
  const float* bias = (gemm==0)?bq:((gemm==1)?bk:bv);
  __half* C = (gemm==0)?g_Qh:((gemm==1)?g_Kh:g_Vh);
  const __half* Asrc = g_xh + (size_t)r0*256;
  float* s_bias = (float*)(smem + Q_PAR);
  if (t < 128) s_bias[t] = bias[nh*128 + t];

  float acc[2][8][4];
  ZERO_ACC(acc);

  stage_tile<128>(sb + Q_A0, Asrc, 256, 0, t);
  stage_tile<128>(sb + Q_B0, Bsrc, 256, 0, t);
  CPA_COMMIT();
  #pragma unroll
  for (int ck=0; ck<4; ck++){
    if (ck<3){
      stage_tile<128>(sb + ((ck&1)? Q_A0:Q_A1), Asrc, 256, (ck+1)*64, t);
      stage_tile<128>(sb + ((ck&1)? Q_B0:Q_B1), Bsrc, 256, (ck+1)*64, t);
      CPA_COMMIT(); CPA_WAIT(1);
    } else { CPA_WAIT(0); }
    __syncthreads();
    compute_chunk(sb, (ck&1)?Q_A1:Q_A0, (ck&1)?Q_B1:Q_B0, lane, wm, wn, acc);
    __syncthreads();
  }

  #pragma unroll
  for (int mi=0;mi<2;mi++){
    int rA = wm*32 + mi*16 + (lane>>2);
    #pragma unroll
    for (int half=0; half<2; half++){
      int row = r0 + rA + half*8;
      if (row >= N_) continue;
      #pragma unroll
      for (int ni=0;ni<8;ni++){
        int lc = wn*64 + ni*8 + (lane&3)*2;
        float v0 = acc[mi][ni][half*2+0] + s_bias[lc];
        float v1 = acc[mi][ni][half*2+1] + s_bias[lc+1];
        *(__half2*)(C + (size_t)row*256 + nh*128 + lc) = __floats2half2_rn(v0, v1);
      }
    }
  }
}

// ---------------- FFN1: M=128, N=128 tile; fp16 out ----------------------------
__global__ void __launch_bounds__(256,2) k_mm_ffn1(const float* __restrict__ bf1){
  extern __shared__ char smem[];
  uint32 sb = smem_to_u32(smem);
  int t = threadIdx.x, lane = t&31, wid = t>>5;
  int wm = wid>>1, wn = wid&1;
  int r0 = blockIdx.x*128;
  int colOff = blockIdx.y*128;
  const __half* Bsrc = g_wt + OFF_F1 + (size_t)colOff*256;
  const __half* Asrc = g_x1h + (size_t)r0*256;
  float* s_bias = (float*)(smem + Q_PAR);
  if (t < 128) s_bias[t] = bf1[colOff + t];

  float acc[2][8][4];
  ZERO_ACC(acc);

  stage_tile<128>(sb + Q_A0, Asrc, 256, 0, t);
  stage_tile<128>(sb + Q_B0, Bsrc, 256, 0, t);
  CPA_COMMIT();
  #pragma unroll
  for (int ck=0; ck<4; ck++){
    if (ck<3){
      stage_tile<128>(sb + ((ck&1)? Q_A0:Q_A1), Asrc, 256, (ck+1)*64, t);
      stage_tile<128>(sb + ((ck&1)? Q_B0:Q_B1), Bsrc, 256, (ck+1)*64, t);
      CPA_COMMIT(); CPA_WAIT(1);
    } else { CPA_WAIT(0); }
    __syncthreads();
    compute_chunk(sb, (ck&1)?Q_A1:Q_A0, (ck&1)?Q_B1:Q_B0, lane, wm, wn, acc);
    __syncthreads();
  }

  #pragma unroll
  for (int mi=0;mi<2;mi++){
    int rA = wm*32 + mi*16 + (lane>>2);
    #pragma unroll
    for (int half=0; half<2; half++){
      int row = r0 + rA + half*8;
      if (row >= N_) continue;
      #pragma unroll
      for (int ni=0;ni<8;ni++){
        int lc = wn*64 + ni*8 + (lane&3)*2;
        float v0 = fmaxf(acc[mi][ni][half*2+0] + s_bias[lc],   0.f);
        float v1 = fmaxf(acc[mi][ni][half*2+1] + s_bias[lc+1], 0.f);
        *(__half2*)(g_ffn + (size_t)row*1024 + colOff + lc) = __floats2half2_rn(v0, v1);
      }
    }
  }
}

// ---------------- edge: M=64, N=256; pe-MLP GEMM + LN + scores ------------------
__global__ void __launch_bounds__(256,2) k_mm_edge(
    const float* __restrict__ pos, const int* __restrict__ ei,
    const float* __restrict__ Wp1, const float* __restrict__ bp1,
    const float* __restrict__ bp2, const float* __restrict__ gp,
    const float* __restrict__ bpn){
  extern __shared__ char smem[];
  uint32 sb = smem_to_u32(smem);
  int t = threadIdx.x, lane = t&31, wid = t>>5;
  int wm = wid>>2, wn = wid&3;
  int e0 = blockIdx.x*64;

  float* s_w1   = (float*)(smem + L_PAR);   // 768
  float* s_b1   = s_w1 + 768;               // 256
  float* s_p2   = s_b1 + 256;               // 256
  float* s_gp   = s_p2 + 256;               // 256
  float* s_bn   = s_gp + 256;               // 256
  float* s_dp   = s_bn + 256;               // 192
  float* s_part = s_dp + 192;               // 512
  int*   s_nd   = (int*)(s_part + 512);     // 192 ints (src, dst, pos)

  s_w1[t]     = Wp1[t];
  s_w1[256+t] = Wp1[256+t];
  s_w1[512+t] = Wp1[512+t];
  s_b1[t] = bp1[t]; s_p2[t] = bp2[t]; s_gp[t] = gp[t]; s_bn[t] = bpn[t];
  if (t < 64){
    int e = e0 + t;
    int sn = ei[e], dn = ei[E_+e];
    s_nd[t] = sn; s_nd[64+t] = dn; s_nd[128+t] = g_pos[e];
    s_dp[t*3+0] = pos[dn*3+0]-pos[sn*3+0];
    s_dp[t*3+1] = pos[dn*3+1]-pos[sn*3+1];
    s_dp[t*3+2] = pos[dn*3+2]-pos[sn*3+2];
  }
  __syncthreads();

  int rr = t>>2, q4 = t&3;
  float dx = s_dp[rr*3+0], dy = s_dp[rr*3+1], dz = s_dp[rr*3+2];

  float acc[2][8][4];
  ZERO_ACC(acc);

  auto gen_a = [&](uint32 aoff, int kk){
    #pragma unroll
    for (int half=0; half<2; half++){
      HU H;
      #pragma unroll
      for (int j=0; j<8; j++){
        int c = kk + q4*16 + half*8 + j;
        float v = fmaf(dz, s_w1[512+c], fmaf(dy, s_w1[256+c], fmaf(dx, s_w1[c], s_b1[c])));
        H.h[j] = __float2half_rn(fmaxf(v, 0.f));
      }
      *(uint4*)(smem + aoff + swz(rr, q4*2 + half)) = H.u;
    }
  };

  gen_a(L_A0, 0);
  stage_tile<256>(sb + L_B0, g_wt + OFF_P2, 256, 0, t);
  CPA_COMMIT();
  #pragma unroll
  for (int ck=0; ck<4; ck++){
    if (ck<3){
      gen_a((ck&1)? L_A0:L_A1, (ck+1)*64);
      stage_tile<256>(sb + ((ck&1)? L_B0:L_B1), g_wt + OFF_P2, 256, (ck+1)*64, t);
      CPA_COMMIT(); CPA_WAIT(1);
    } else { CPA_WAIT(0); }
    __syncthreads();
    compute_chunk(sb, (ck&1)?L_A1:L_A0, (ck&1)?L_B1:L_B0, lane, wm, wn, acc);
    __syncthreads();
  }

  // pass 1: vals = acc + bp2; per-row partial LN stats
  #pragma unroll
  for (int mi=0;mi<2;mi++){
    int rA = wm*32 + mi*16 + (lane>>2);
    #pragma unroll
    for (int half=0; half<2; half++){
      int rl = rA + half*8;
      float s1=0.f, s2=0.f;
      #pragma unroll
      for (int ni=0;ni<8;ni++){
        int col = wn*64 + ni*8 + (lane&3)*2;
        float v0 = acc[mi][ni][half*2+0] + s_p2[col];
        float v1 = acc[mi][ni][half*2+1] + s_p2[col+1];
        acc[mi][ni][half*2+0] = v0;
        acc[mi][ni][half*2+1] = v1;
        s1 += v0 + v1;
        s2 = fmaf(v0, v0, fmaf(v1, v1, s2));
      }
      s1 += __shfl_xor_sync(0xffffffffu, s1, 1);
      s1 += __shfl_xor_sync(0xffffffffu, s1, 2);
      s2 += __shfl_xor_sync(0xffffffffu, s2, 1);
      s2 += __shfl_xor_sync(0xffffffffu, s2, 2);
      if ((lane&3)==0){ s_part[(rl*4+wn)*2] = s1; s_part[(rl*4+wn)*2+1] = s2; }
    }
  }
  __syncthreads();

  // pass 2: LN + per-head scores (fp16 Q/K gathers)
  const float SC = 0.17677669529663688f;  // 1/sqrt(32)
  #pragma unroll
  for (int mi=0;mi<2;mi++){
    int rA = wm*32 + mi*16 + (lane>>2);
    #pragma unroll
    for (int half=0; half<2; half++){
      int rl = rA + half*8;
      float s1 = s_part[(rl*4+0)*2] + s_part[(rl*4+1)*2]
               + s_part[(rl*4+2)*2] + s_part[(rl*4+3)*2];
      float s2 = s_part[(rl*4+0)*2+1] + s_part[(rl*4+1)*2+1]
               + s_part[(rl*4+2)*2+1] + s_part[(rl*4+3)*2+1];
      float m = s1*(1.f/256.f);
      float rstd = rsqrtf(fmaxf(s2*(1.f/256.f) - m*m, 0.f) + 1e-5f);
      int sn = s_nd[rl], dn = s_nd[64+rl], pp = s_nd[128+rl];
      const __half* Qp = g_Qh + (size_t)dn*256;
      const __half* Kp = g_Kh + (size_t)sn*256;
      #pragma unroll
      for (int h=0; h<2; h++){
        float partial = 0.f;
        #pragma unroll
        for (int nio=0; nio<4; nio++){
          int ni = h*4 + nio;
          int col = wn*64 + ni*8 + (lane&3)*2;
          float2 qv = __half22float2(*(const __half2*)(Qp + col));
          float2 kv = __half22float2(*(const __half2*)(Kp + col));
          float pe0 = (acc[mi][ni][half*2+0]-m)*rstd*s_gp[col]   + s_bn[col];
          float pe1 = (acc[mi][ni][half*2+1]-m)*rstd*s_gp[col+1] + s_bn[col+1];
          partial = fmaf(qv.x, kv.x + pe0, partial);
          partial = fmaf(qv.y, kv.y + pe1, partial);
        }
        partial += __shfl_xor_sync(0xffffffffu, partial, 1);
        partial += __shfl_xor_sync(0xffffffffu, partial, 2);
        if ((lane&3)==0)
          g_score[(size_t)pp*8 + wn*2 + h] = partial*SC;
      }
    }
  }
}

// ---------------- segment softmax + weighted aggregation ------------------------
__global__ void __launch_bounds__(256) k_aggr(){
  int n = blockIdx.x;
  int beg = g_rowptr[n], end = g_rowptr[n+1];
  int t = threadIdx.x, lane = t&31, w = t>>5;
  __shared__ float s_mx[8], s_rs[8];
  __shared__ float s_at[128*8];
  __shared__ int   s_sc[128];

  {
    int h = w;
    float mx = -3.0e38f;
    for (int i=beg+lane; i<end; i+=32)
      mx = fmaxf(mx, g_score[(size_t)i*8+h]);
    #pragma unroll
    for (int o=16;o>0;o>>=1) mx = fmaxf(mx, __shfl_xor_sync(0xffffffffu, mx, o));
    float s=0.f;
    for (int i=beg+lane; i<end; i+=32)
      s += __expf(g_score[(size_t)i*8+h]-mx);
    #pragma unroll
    for (int o=16;o>0;o>>=1) s += __shfl_xor_sync(0xffffffffu, s, o);
    if (lane==0){ s_mx[h]=mx; s_rs[h]=1.f/(s+1e-16f); }
  }
  __syncthreads();

  float acc=0.f;
  int h = t>>5;
  for (int c0=beg; c0<end; c0+=128){
    int cn = min(128, end-c0);
    for (int j=t; j<cn*8; j+=256){
      int i=j>>3, hh=j&7;
      s_at[i*8+hh] = __expf(g_score[(size_t)(c0+i)*8+hh]-s_mx[hh])*s_rs[hh];
      if (hh==0) s_sc[i] = g_srcs[c0+i];
    }
    __syncthreads();
    for (int i=0;i<cn;i++)
      acc = fmaf(s_at[i*8+h], __half2float(g_Vh[(size_t)s_sc[i]*256 + t]), acc);
    __syncthreads();
  }
  g_aggrh[(size_t)n*256+t] = __float2half_rn(acc);
}

// ---------------- GEMM + LN (Wo / FFN2): M=64, N=256 ---------------------------
__global__ void __launch_bounds__(256,2) k_mm_ln(int mode,
    const float* __restrict__ bias, const float* __restrict__ resx,
    const float* __restrict__ gam, const float* __restrict__ bet,
    float* __restrict__ outp){
  extern __shared__ char smem[];
  uint32 sb = smem_to_u32(smem);
  int t = threadIdx.x, lane = t&31, wid = t>>5;
  int wm = wid>>2, wn = wid&3;
  int r0 = blockIdx.x*64;
  const float* res; float* C; int K; const __half* Bsrc; const __half* Asrc; int Kst;
  if (mode==0){
    res=resx; C=g_x1; K=256; Bsrc=g_wt+OFF_O;
    Asrc = g_aggrh + (size_t)r0*256; Kst=256;
  } else {
    res=g_x1; C=outp; K=1024; Bsrc=g_wt+OFF_F2;
    Asrc = g_ffn + (size_t)r0*1024; Kst=1024;
  }

  float* s_bias = (float*)(smem + L_PAR);
  float* s_g    = s_bias + 256;
  float* s_b    = s_g + 256;
  float* s_part = s_b + 256;                // 512
  s_bias[t] = bias[t]; s_g[t] = gam[t]; s_b[t] = bet[t];

  float acc[2][8][4];
  ZERO_ACC(acc);

  int nchunks = K/64;
  stage_tile<64>(sb + L_A0, Asrc, Kst, 0, t);
  stage_tile<256>(sb + L_B0, Bsrc, K, 0, t);
  CPA_COMMIT();
  for (int ck=0; ck<nchunks; ck++){
    if (ck+1 < nchunks){
      stage_tile<64>(sb + ((ck&1)? L_A0:L_A1), Asrc, Kst, (ck+1)*64, t);
      stage_tile<256>(sb + ((ck&1)? L_B0:L_B1), Bsrc, K, (ck+1)*64, t);
      CPA_COMMIT(); CPA_WAIT(1);
    } else { CPA_WAIT(0); }
    __syncthreads();
    compute_chunk(sb, (ck&1)?L_A1:L_A0, (ck&1)?L_B1:L_B0, lane, wm, wn, acc);
    __syncthreads();
  }

  #pragma unroll
  for (int mi=0;mi<2;mi++){
    int rA = wm*32 + mi*16 + (lane>>2);
    #pragma unroll
    for (int half=0; half<2; half++){
      int rl = rA + half*8;
      int row = r0 + rl;
      bool ok = row < N_;
      float s1=0.f, s2=0.f;
      #pragma unroll
      for (int ni=0;ni<8;ni++){
        int col = wn*64 + ni*8 + (lane&3)*2;
        float2 rv = ok ? *(const float2*)(res + (size_t)row*256 + col)
                       : make_float2(0.f, 0.f);
        float v0 = acc[mi][ni][half*2+0] + s_bias[col]   + rv.x;
        float v1 = acc[mi][ni][half*2+1] + s_bias[col+1] + rv.y;
        acc[mi][ni][half*2+0] = v0;
        acc[mi][ni][half*2+1] = v1;
        s1 += v0 + v1;
        s2 = fmaf(v0, v0, fmaf(v1, v1, s2));
      }
      s1 += __shfl_xor_sync(0xffffffffu, s1, 1);
      s1 += __shfl_xor_sync(0xffffffffu, s1, 2);
      s2 += __shfl_xor_sync(0xffffffffu, s2, 1);
      s2 += __shfl_xor_sync(0xffffffffu, s2, 2);
      if ((lane&3)==0){ s_part[(rl*4+wn)*2] = s1; s_part[(rl*4+wn)*2+1] = s2; }
    }
  }
  __syncthreads();

  #pragma unroll
  for (int mi=0;mi<2;mi++){
    int rA = wm*32 + mi*16 + (lane>>2);
    #pragma unroll
    for (int half=0; half<2; half++){
      int rl = rA + half*8;
      int row = r0 + rl;
      if (row >= N_) continue;
      float s1 = s_part[(rl*4+0)*2] + s_part[(rl*4+1)*2]
               + s_part[(rl*4+2)*2] + s_part[(rl*4+3)*2];
      float s2 = s_part[(rl*4+0)*2+1] + s_part[(rl*4+1)*2+1]
               + s_part[(rl*4+2)*2+1] + s_part[(rl*4+3)*2+1];
      float m = s1*(1.f/256.f);
      float rstd = rsqrtf(fmaxf(s2*(1.f/256.f) - m*m, 0.f) + 1e-5f);
      #pragma unroll
      for (int ni=0;ni<8;ni++){
        int col = wn*64 + ni*8 + (lane&3)*2;
        float o0 = (acc[mi][ni][half*2+0]-m)*rstd*s_g[col]   + s_b[col];
        float o1 = (acc[mi][ni][half*2+1]-m)*rstd*s_g[col+1] + s_b[col+1];
        *(float2*)(C + (size_t)row*256 + col) = make_float2(o0, o1);
        if (mode==0)
          *(__half2*)(g_x1h + (size_t)row*256 + col) = __floats2half2_rn(o0, o1);
      }
    }
  }
}

// ---------------- launch ---------------------------------------------------------
extern "C" void kernel_launch(void* const* d_in, const int* in_sizes, int n_in,
                              void* d_out, int out_size){
  const float* x    = (const float*)d_in[0];
  const float* pos  = (const float*)d_in[1];
  const int*   ei   = (const int*)  d_in[2];
  const float* Wq   = (const float*)d_in[3];
  const float* bq   = (const float*)d_in[4];
  const float* Wk   = (const float*)d_in[5];
  const float* bk   = (const float*)d_in[6];
  const float* Wv   = (const float*)d_in[7];
  const float* bv   = (const float*)d_in[8];
  const float* Wp1  = (const float*)d_in[9];
  const float* bp1  = (const float*)d_in[10];
  const float* Wp2  = (const float*)d_in[11];
  const float* bp2  = (const float*)d_in[12];
  const float* gp   = (const float*)d_in[13];
  const float* bp   = (const float*)d_in[14];
  const float* Wo   = (const float*)d_in[15];
  const float* bo   = (const float*)d_in[16];
  const float* g1   = (const float*)d_in[17];
  const float* b1n  = (const float*)d_in[18];
  const float* Wf1  = (const float*)d_in[19];
  const float* bf1  = (const float*)d_in[20];
  const float* Wf2  = (const float*)d_in[21];
  const float* bf2  = (const float*)d_in[22];
  const float* g2   = (const float*)d_in[23];
  const float* b2n  = (const float*)d_in[24];
  float* out = (float*)d_out;

  cudaFuncSetAttribute(k_mm_qkv,  cudaFuncAttributeMaxDynamicSharedMemorySize, Q_DYN);
  cudaFuncSetAttribute(k_mm_ffn1, cudaFuncAttributeMaxDynamicSharedMemorySize, Q_DYN);
  cudaFuncSetAttribute(k_mm_edge, cudaFuncAttributeMaxDynamicSharedMemorySize, L_DYN);
  cudaFuncSetAttribute(k_mm_ln,   cudaFuncAttributeMaxDynamicSharedMemorySize, L_DYN);

  const int MT128 = (N_ + 127) / 128;  // 79
  const int MT64  = (N_ + 63) / 64;    // 157
  const int ET    = E_ / 64;           // 2500

  // CSR build (g_cnt re-zeroed by k_scatter tail each run)
  k_count  <<<(E_+255)/256, 256>>>(ei);
  k_scan   <<<1, 1024>>>();
  k_scatter<<<(E_+255)/256, 256>>>(ei);

  // fused prep: 7 weight transposes + x->fp16
  k_prep_all<<<2082, dim3(32,8)>>>(Wq, Wk, Wv, Wp2, Wo, Wf1, Wf2, x);

  // Q/K/V  (3 gemms x 2 n-halves)  [fp16 out]
  k_mm_qkv<<<dim3(MT128,6), 256, Q_DYN>>>(bq, bk, bv);

  // edge: pe-MLP GEMM + LN + scores (CSR-ordered)
  k_mm_edge<<<ET, 256, L_DYN>>>(pos, ei, Wp1, bp1, bp2, gp, bp);

  // segment softmax + aggregation [fp16 out]
  k_aggr<<<N_, 256>>>();

  // x1 = LN(aggr@Wo + bo + x)  [+ fp16 mirror]
  k_mm_ln<<<MT64, 256, L_DYN>>>(0, bo, x, g1, b1n, nullptr);

  // ffn = relu(x1@Wf1 + bf1)  [fp16 out]
  k_mm_ffn1<<<dim3(MT128,8), 256, Q_DYN>>>(bf1);

  // out = LN(ffn@Wf2 + bf2 + x1)
  k_mm_ln<<<MT64, 256, L_DYN>>>(1, bf2, nullptr, g2, b2n, out);

  (void)in_sizes; (void)n_in; (void)out_size;
}